// round 1
// baseline (speedup 1.0000x reference)
#include <cuda_runtime.h>
#include <math.h>

#define NPTS 200000
#define MPTS 100000

// ---------------- scratch (device globals: allocation-free rule) ----------
__device__ float g_fx[NPTS * 32];            // feats_x        25.6 MB
__device__ float g_gx[NPTS * 32];            // guidance_x     25.6 MB
__device__ float g_agg[(size_t)MPTS * 512];  // agg            204.8 MB
__device__ float g_sf[MPTS * 64];            // maxpooled dense feats 25.6 MB

__device__ __forceinline__ float relu_f(float x) { return x > 0.f ? x : 0.f; }
__device__ __forceinline__ float lrelu_f(float x) { return x > 0.f ? x : 0.1f * x; }

// ======================= K1: dense transform ==============================
// feats_x = leaky_relu(dense_feats @ w1 + b1, 0.1)   [N,32]
// guidance = feats_x @ wgu + bgu                      [N,32]
// block = 256 threads = 8 points x 32 channels
__global__ void __launch_bounds__(256) k1_dense(
    const float* __restrict__ df,
    const float* __restrict__ w1, const float* __restrict__ b1,
    const float* __restrict__ wgu, const float* __restrict__ bgu) {
    __shared__ float w1s[64 * 32];
    __shared__ float wgus[32 * 32];
    __shared__ float fs[8][64];
    __shared__ float fxs[8][33];
    int t = threadIdx.x;
    for (int i = t; i < 2048; i += 256) w1s[i] = w1[i];
    for (int i = t; i < 1024; i += 256) wgus[i] = wgu[i];
    int p0 = blockIdx.x * 8;
    for (int i = t; i < 512; i += 256) fs[i >> 6][i & 63] = df[(size_t)p0 * 64 + i];
    __syncthreads();
    int p = t >> 5, c = t & 31;
    float acc = __ldg(&b1[c]);
#pragma unroll
    for (int k = 0; k < 64; k++) acc = fmaf(fs[p][k], w1s[k * 32 + c], acc);
    float v = lrelu_f(acc);
    fxs[p][c] = v;
    g_fx[(size_t)(p0 + p) * 32 + c] = v;
    __syncthreads();
    float g = __ldg(&bgu[c]);
#pragma unroll
    for (int k = 0; k < 32; k++) g = fmaf(fxs[p][k], wgus[k * 32 + c], g);
    g_gx[(size_t)(p0 + p) * 32 + c] = g;
}

// ======================= K2: per-sparse-point pipeline =====================
// warp per point; 2 lanes per neighbor (j = lane>>1, half = lane&1).
// half=0 lane owns g_feat channels 0..31 (gathered guidance),
// half=1 lane owns g_feat channels 32..63 (positional encoding).
__global__ void __launch_bounds__(256) k2_point(
    const float* __restrict__ df,
    const float* __restrict__ vi_f,
    const int* __restrict__ nei,
    const float* __restrict__ wpe, const float* __restrict__ bpe,
    const float* __restrict__ wg1, const float* __restrict__ bg1,
    const float* __restrict__ wg2, const float* __restrict__ bg2,
    const float* __restrict__ wn1, const float* __restrict__ bn1,
    const float* __restrict__ wn2, const float* __restrict__ bn2,
    const float* __restrict__ wn3, const float* __restrict__ bn3) {
    __shared__ __align__(16) float s_wpe[12 * 32];
    __shared__ __align__(16) float s_wg1[64 * 8];
    __shared__ __align__(16) float s_wg2[8 * 8];
    __shared__ __align__(16) float s_wn1[12 * 8];
    __shared__ __align__(16) float s_wn2[8 * 8];
    __shared__ __align__(16) float s_wn3[8 * 16];
    __shared__ __align__(16) float s_nf[8][16][32];  // [warp][j][c]
    __shared__ __align__(16) float s_w[8][16][16];   // [warp][j][w]
    int t = threadIdx.x;
    for (int i = t; i < 384; i += 256) s_wpe[i] = wpe[i];
    for (int i = t; i < 512; i += 256) s_wg1[i] = wg1[i];
    if (t < 64) s_wg2[t] = wg2[t];
    if (t < 96) s_wn1[t] = wn1[t];
    if (t < 64) s_wn2[t] = wn2[t];
    if (t < 128) s_wn3[t] = wn3[t];
    __syncthreads();

    const unsigned FULL = 0xffffffffu;
    int wid = t >> 5, lane = t & 31;
    int j = lane >> 1, half = lane & 1;
    int m = blockIdx.x * 8 + wid;
    int idx = nei[m * 16 + j];

    // VI features for this neighbor (12 floats, 48B-aligned)
    float vi[12];
    {
        const float4* vp = (const float4*)(vi_f + ((size_t)m * 16 + j) * 12);
        float4 a = vp[0], b = vp[1], c = vp[2];
        vi[0] = a.x; vi[1] = a.y; vi[2] = a.z; vi[3] = a.w;
        vi[4] = b.x; vi[5] = b.y; vi[6] = b.z; vi[7] = b.w;
        vi[8] = c.x; vi[9] = c.y; vi[10] = c.z; vi[11] = c.w;
    }

    // g_feat half owned by this lane
    float gf[32];
    if (half == 0) {
        const float4* gp = (const float4*)(g_gx + (size_t)idx * 32);
#pragma unroll
        for (int q = 0; q < 8; q++) {
            float4 v = gp[q];
            gf[4 * q] = v.x; gf[4 * q + 1] = v.y; gf[4 * q + 2] = v.z; gf[4 * q + 3] = v.w;
        }
    } else {
#pragma unroll
        for (int c = 0; c < 32; c++) {
            float a = __ldg(&bpe[c]);
#pragma unroll
            for (int i = 0; i < 12; i++) a = fmaf(vi[i], s_wpe[i * 32 + c], a);
            gf[c] = relu_f(a);
        }
    }

    // subtraction guidance: per-channel max over K neighbors (same-parity lanes),
    // then first guidance MLP partial over this lane's 32 channels.
    float part[8];
#pragma unroll
    for (int h = 0; h < 8; h++) part[h] = 0.f;
    int base = half * 32;
#pragma unroll
    for (int c = 0; c < 32; c++) {
        float v = gf[c];
        float mx = v;
        mx = fmaxf(mx, __shfl_xor_sync(FULL, mx, 2));
        mx = fmaxf(mx, __shfl_xor_sync(FULL, mx, 4));
        mx = fmaxf(mx, __shfl_xor_sync(FULL, mx, 8));
        mx = fmaxf(mx, __shfl_xor_sync(FULL, mx, 16));
        float d = v - mx;
        const float4* wr = (const float4*)&s_wg1[(base + c) * 8];
        float4 wa = wr[0], wb = wr[1];
        part[0] = fmaf(d, wa.x, part[0]); part[1] = fmaf(d, wa.y, part[1]);
        part[2] = fmaf(d, wa.z, part[2]); part[3] = fmaf(d, wa.w, part[3]);
        part[4] = fmaf(d, wb.x, part[4]); part[5] = fmaf(d, wb.y, part[5]);
        part[6] = fmaf(d, wb.z, part[6]); part[7] = fmaf(d, wb.w, part[7]);
    }
#pragma unroll
    for (int h = 0; h < 8; h++) part[h] += __shfl_xor_sync(FULL, part[h], 1);
    float s1[8];
#pragma unroll
    for (int h = 0; h < 8; h++) s1[h] = relu_f(part[h] + __ldg(&bg1[h]));
    float sc[8];
#pragma unroll
    for (int h2 = 0; h2 < 8; h2++) {
        float a = __ldg(&bg2[h2]);
#pragma unroll
        for (int h = 0; h < 8; h++) a = fmaf(s1[h], s_wg2[h * 8 + h2], a);
        sc[h2] = 1.f / (1.f + expf(-a));
    }

    // WeightNet 12->8->8->16 (hidden redundant per lane pair, split final 16)
    float h1[8];
#pragma unroll
    for (int o = 0; o < 8; o++) {
        float a = __ldg(&bn1[o]);
#pragma unroll
        for (int i = 0; i < 12; i++) a = fmaf(vi[i], s_wn1[i * 8 + o], a);
        h1[o] = relu_f(a);
    }
    float h2v[8];
#pragma unroll
    for (int o = 0; o < 8; o++) {
        float a = __ldg(&bn2[o]);
#pragma unroll
        for (int i = 0; i < 8; i++) a = fmaf(h1[i], s_wn2[i * 8 + o], a);
        h2v[o] = relu_f(a);
    }
#pragma unroll
    for (int oo = 0; oo < 8; oo++) {
        int o = half * 8 + oo;
        float a = __ldg(&bn3[o]);
#pragma unroll
        for (int i = 0; i < 8; i++) a = fmaf(h2v[i], s_wn3[i * 16 + o], a);
        s_w[wid][j][o] = relu_f(a);
    }

    // nf = gathered feats_x * scores[head], head = c>>2
    {
        const float4* fp = (const float4*)(g_fx + (size_t)idx * 32 + half * 16);
#pragma unroll
        for (int q = 0; q < 4; q++) {
            float4 v = fp[q];
            int c0 = half * 16 + 4 * q;
            float s = sc[c0 >> 2];
            s_nf[wid][j][c0 + 0] = v.x * s;
            s_nf[wid][j][c0 + 1] = v.y * s;
            s_nf[wid][j][c0 + 2] = v.z * s;
            s_nf[wid][j][c0 + 3] = v.w * s;
        }
    }

    // shortcut maxpool of dense feats over neighborhood (lane owns ch lane, lane+32)
    {
        float m0 = -3.0e38f, m1 = -3.0e38f;
#pragma unroll
        for (int jj = 0; jj < 16; jj++) {
            int ix = __shfl_sync(FULL, idx, jj * 2);
            m0 = fmaxf(m0, __ldg(&df[(size_t)ix * 64 + lane]));
            m1 = fmaxf(m1, __ldg(&df[(size_t)ix * 64 + 32 + lane]));
        }
        g_sf[(size_t)m * 64 + lane] = m0;
        g_sf[(size_t)m * 64 + 32 + lane] = m1;
    }

    __syncwarp();

    // agg[c][w] = sum_j nf[j][c] * w[j][w];  lane = c (32 lanes), 16 accumulators
    float acc[16];
#pragma unroll
    for (int w = 0; w < 16; w++) acc[w] = 0.f;
    int c = lane;
#pragma unroll
    for (int jj = 0; jj < 16; jj++) {
        float a = s_nf[wid][jj][c];
        const float4* wp = (const float4*)&s_w[wid][jj][0];
        float4 w0 = wp[0], w1 = wp[1], w2 = wp[2], w3 = wp[3];
        acc[0] = fmaf(a, w0.x, acc[0]);  acc[1] = fmaf(a, w0.y, acc[1]);
        acc[2] = fmaf(a, w0.z, acc[2]);  acc[3] = fmaf(a, w0.w, acc[3]);
        acc[4] = fmaf(a, w1.x, acc[4]);  acc[5] = fmaf(a, w1.y, acc[5]);
        acc[6] = fmaf(a, w1.z, acc[6]);  acc[7] = fmaf(a, w1.w, acc[7]);
        acc[8] = fmaf(a, w2.x, acc[8]);  acc[9] = fmaf(a, w2.y, acc[9]);
        acc[10] = fmaf(a, w2.z, acc[10]); acc[11] = fmaf(a, w2.w, acc[11]);
        acc[12] = fmaf(a, w3.x, acc[12]); acc[13] = fmaf(a, w3.y, acc[13]);
        acc[14] = fmaf(a, w3.z, acc[14]); acc[15] = fmaf(a, w3.w, acc[15]);
    }
    float4* op = (float4*)(g_agg + (size_t)m * 512 + c * 16);
    op[0] = make_float4(acc[0], acc[1], acc[2], acc[3]);
    op[1] = make_float4(acc[4], acc[5], acc[6], acc[7]);
    op[2] = make_float4(acc[8], acc[9], acc[10], acc[11]);
    op[3] = make_float4(acc[12], acc[13], acc[14], acc[15]);
}

// ======================= K3: output GEMM + epilogue ========================
// per block: 16 points. out64 = relu(agg[512] @ w_lin + b_lin)
//            out128 = out64 @ w_u2 + b_u2 + sf @ w_sc + b_sc -> leaky(0.1)
__global__ void __launch_bounds__(256) k3_out(
    const float* __restrict__ wlin, const float* __restrict__ blin,
    const float* __restrict__ wu2, const float* __restrict__ bu2,
    const float* __restrict__ wsc, const float* __restrict__ bsc,
    float* __restrict__ out) {
    __shared__ float s_agg[16][65];
    __shared__ __align__(16) float s_w[64 * 64];
    __shared__ float s_o[16][65];
    __shared__ float s_sf[16][65];
    int t = threadIdx.x;
    int m0 = blockIdx.x * 16;
    int p = t & 15, og = t >> 4;

    float acc[4] = {0.f, 0.f, 0.f, 0.f};
#pragma unroll 1
    for (int kt = 0; kt < 8; kt++) {
        int k0 = kt * 64;
        {   // stage 16x64 agg tile
            int i = t * 4;
            int pp = i >> 6, kk = i & 63;
            float4 v = *(const float4*)(g_agg + (size_t)(m0 + pp) * 512 + k0 + kk);
            s_agg[pp][kk] = v.x; s_agg[pp][kk + 1] = v.y;
            s_agg[pp][kk + 2] = v.z; s_agg[pp][kk + 3] = v.w;
        }
#pragma unroll
        for (int q = 0; q < 4; q++) {  // stage 64x64 w_lin tile
            int i = (t + q * 256) * 4;
            *(float4*)&s_w[i] = __ldg((const float4*)(wlin + (size_t)k0 * 64 + i));
        }
        __syncthreads();
#pragma unroll
        for (int kk = 0; kk < 64; kk++) {
            float a = s_agg[p][kk];
            float4 w = *(const float4*)&s_w[kk * 64 + og * 4];
            acc[0] = fmaf(a, w.x, acc[0]); acc[1] = fmaf(a, w.y, acc[1]);
            acc[2] = fmaf(a, w.z, acc[2]); acc[3] = fmaf(a, w.w, acc[3]);
        }
        __syncthreads();
    }
    {   // out64 -> shared
        float4 bl = __ldg((const float4*)(blin + og * 4));
        s_o[p][og * 4 + 0] = relu_f(acc[0] + bl.x);
        s_o[p][og * 4 + 1] = relu_f(acc[1] + bl.y);
        s_o[p][og * 4 + 2] = relu_f(acc[2] + bl.z);
        s_o[p][og * 4 + 3] = relu_f(acc[3] + bl.w);
    }
    {   // stage maxpooled dense feats
        int i = t * 4;
        int pp = i >> 6, kk = i & 63;
        float4 v = *(const float4*)(g_sf + (size_t)(m0 + pp) * 64 + kk);
        s_sf[pp][kk] = v.x; s_sf[pp][kk + 1] = v.y;
        s_sf[pp][kk + 2] = v.z; s_sf[pp][kk + 3] = v.w;
    }
    __syncthreads();

    int ob = og * 8;
    float r8[8];
#pragma unroll
    for (int q = 0; q < 8; q++) r8[q] = __ldg(&bu2[ob + q]) + __ldg(&bsc[ob + q]);
#pragma unroll
    for (int k = 0; k < 64; k++) {
        float x = s_o[p][k];
        float s = s_sf[p][k];
        float4 wa = __ldg((const float4*)(wu2 + (size_t)k * 128 + ob));
        float4 wb = __ldg((const float4*)(wu2 + (size_t)k * 128 + ob + 4));
        float4 sa = __ldg((const float4*)(wsc + (size_t)k * 128 + ob));
        float4 sb = __ldg((const float4*)(wsc + (size_t)k * 128 + ob + 4));
        r8[0] = fmaf(x, wa.x, r8[0]); r8[1] = fmaf(x, wa.y, r8[1]);
        r8[2] = fmaf(x, wa.z, r8[2]); r8[3] = fmaf(x, wa.w, r8[3]);
        r8[4] = fmaf(x, wb.x, r8[4]); r8[5] = fmaf(x, wb.y, r8[5]);
        r8[6] = fmaf(x, wb.z, r8[6]); r8[7] = fmaf(x, wb.w, r8[7]);
        r8[0] = fmaf(s, sa.x, r8[0]); r8[1] = fmaf(s, sa.y, r8[1]);
        r8[2] = fmaf(s, sa.z, r8[2]); r8[3] = fmaf(s, sa.w, r8[3]);
        r8[4] = fmaf(s, sb.x, r8[4]); r8[5] = fmaf(s, sb.y, r8[5]);
        r8[6] = fmaf(s, sb.z, r8[6]); r8[7] = fmaf(s, sb.w, r8[7]);
    }
    float4* op = (float4*)(out + (size_t)(m0 + p) * 128 + ob);
    op[0] = make_float4(lrelu_f(r8[0]), lrelu_f(r8[1]), lrelu_f(r8[2]), lrelu_f(r8[3]));
    op[1] = make_float4(lrelu_f(r8[4]), lrelu_f(r8[5]), lrelu_f(r8[6]), lrelu_f(r8[7]));
}

// ======================= launch ============================================
extern "C" void kernel_launch(void* const* d_in, const int* in_sizes, int n_in,
                              void* d_out, int out_size) {
    const float* df  = (const float*)d_in[1];   // dense_feats
    const float* vi  = (const float*)d_in[5];   // vi_features
    const int*   nei = (const int*)d_in[6];     // nei_inds
    const float* w1  = (const float*)d_in[7];
    const float* b1  = (const float*)d_in[8];
    const float* wgu = (const float*)d_in[9];
    const float* bgu = (const float*)d_in[10];
    const float* wpe = (const float*)d_in[11];
    const float* bpe = (const float*)d_in[12];
    const float* wg1 = (const float*)d_in[13];
    const float* bg1 = (const float*)d_in[14];
    const float* wg2 = (const float*)d_in[15];
    const float* bg2 = (const float*)d_in[16];
    const float* wn1 = (const float*)d_in[17];
    const float* bn1 = (const float*)d_in[18];
    const float* wn2 = (const float*)d_in[19];
    const float* bn2 = (const float*)d_in[20];
    const float* wn3 = (const float*)d_in[21];
    const float* bn3 = (const float*)d_in[22];
    const float* wlin = (const float*)d_in[23];
    const float* blin = (const float*)d_in[24];
    const float* wu2 = (const float*)d_in[25];
    const float* bu2 = (const float*)d_in[26];
    const float* wsc = (const float*)d_in[27];
    const float* bsc = (const float*)d_in[28];
    float* out = (float*)d_out;

    k1_dense<<<NPTS / 8, 256>>>(df, w1, b1, wgu, bgu);
    k2_point<<<MPTS / 8, 256>>>(df, vi, nei,
                                wpe, bpe, wg1, bg1, wg2, bg2,
                                wn1, bn1, wn2, bn2, wn3, bn3);
    k3_out<<<MPTS / 16, 256>>>(wlin, blin, wu2, bu2, wsc, bsc, out);
}

// round 2
// speedup vs baseline: 1.1362x; 1.1362x over previous
#include <cuda_runtime.h>
#include <math.h>

#define NPTS 200000
#define MPTS 100000

// ---------------- scratch (device globals: allocation-free rule) ----------
__device__ float g_fx[NPTS * 32];            // feats_x        25.6 MB
__device__ float g_gx[NPTS * 32];            // guidance_x     25.6 MB
__device__ float g_agg[(size_t)MPTS * 512];  // agg            204.8 MB
__device__ float g_sf[MPTS * 64];            // maxpooled dense feats 25.6 MB

__device__ __forceinline__ float relu_f(float x) { return x > 0.f ? x : 0.f; }
__device__ __forceinline__ float lrelu_f(float x) { return x > 0.f ? x : 0.1f * x; }

// ======================= K1: dense transform ==============================
// 32 points/block, thread = (point p = t>>3, channel-quad cg = t&7)
__global__ void __launch_bounds__(256) k1_dense(
    const float* __restrict__ df,
    const float* __restrict__ w1, const float* __restrict__ b1,
    const float* __restrict__ wgu, const float* __restrict__ bgu) {
    __shared__ __align__(16) float s_w1[64 * 32];
    __shared__ __align__(16) float s_wgu[32 * 32];
    __shared__ __align__(16) float s_f[32][68];
    __shared__ __align__(16) float s_fx[32][36];
    int t = threadIdx.x;
    int p0 = blockIdx.x * 32;
    for (int i = t; i < 2048; i += 256) s_w1[i] = w1[i];
    for (int i = t; i < 1024; i += 256) s_wgu[i] = wgu[i];
#pragma unroll
    for (int q = 0; q < 2; q++) {
        int id = t + q * 256;
        int pp = id >> 4, kk = (id & 15) * 4;
        float4 v = *(const float4*)(df + (size_t)(p0 + pp) * 64 + kk);
        *(float4*)&s_f[pp][kk] = v;
    }
    __syncthreads();

    int p = t >> 3, c4 = (t & 7) * 4;
    float4 bb = *(const float4*)(b1 + c4);
    float acc[4] = {bb.x, bb.y, bb.z, bb.w};
#pragma unroll
    for (int kb = 0; kb < 64; kb += 4) {
        float4 f = *(const float4*)&s_f[p][kb];
        float4 w0 = *(const float4*)&s_w1[(kb + 0) * 32 + c4];
        float4 w1v = *(const float4*)&s_w1[(kb + 1) * 32 + c4];
        float4 w2 = *(const float4*)&s_w1[(kb + 2) * 32 + c4];
        float4 w3 = *(const float4*)&s_w1[(kb + 3) * 32 + c4];
        acc[0] = fmaf(f.x, w0.x, acc[0]); acc[1] = fmaf(f.x, w0.y, acc[1]);
        acc[2] = fmaf(f.x, w0.z, acc[2]); acc[3] = fmaf(f.x, w0.w, acc[3]);
        acc[0] = fmaf(f.y, w1v.x, acc[0]); acc[1] = fmaf(f.y, w1v.y, acc[1]);
        acc[2] = fmaf(f.y, w1v.z, acc[2]); acc[3] = fmaf(f.y, w1v.w, acc[3]);
        acc[0] = fmaf(f.z, w2.x, acc[0]); acc[1] = fmaf(f.z, w2.y, acc[1]);
        acc[2] = fmaf(f.z, w2.z, acc[2]); acc[3] = fmaf(f.z, w2.w, acc[3]);
        acc[0] = fmaf(f.w, w3.x, acc[0]); acc[1] = fmaf(f.w, w3.y, acc[1]);
        acc[2] = fmaf(f.w, w3.z, acc[2]); acc[3] = fmaf(f.w, w3.w, acc[3]);
    }
    float4 fx = make_float4(lrelu_f(acc[0]), lrelu_f(acc[1]), lrelu_f(acc[2]), lrelu_f(acc[3]));
    *(float4*)(g_fx + (size_t)(p0 + p) * 32 + c4) = fx;
    *(float4*)&s_fx[p][c4] = fx;
    __syncthreads();

    float4 bg = *(const float4*)(bgu + c4);
    float g[4] = {bg.x, bg.y, bg.z, bg.w};
#pragma unroll
    for (int kb = 0; kb < 32; kb += 4) {
        float4 f = *(const float4*)&s_fx[p][kb];
        float4 w0 = *(const float4*)&s_wgu[(kb + 0) * 32 + c4];
        float4 w1v = *(const float4*)&s_wgu[(kb + 1) * 32 + c4];
        float4 w2 = *(const float4*)&s_wgu[(kb + 2) * 32 + c4];
        float4 w3 = *(const float4*)&s_wgu[(kb + 3) * 32 + c4];
        g[0] = fmaf(f.x, w0.x, g[0]); g[1] = fmaf(f.x, w0.y, g[1]);
        g[2] = fmaf(f.x, w0.z, g[2]); g[3] = fmaf(f.x, w0.w, g[3]);
        g[0] = fmaf(f.y, w1v.x, g[0]); g[1] = fmaf(f.y, w1v.y, g[1]);
        g[2] = fmaf(f.y, w1v.z, g[2]); g[3] = fmaf(f.y, w1v.w, g[3]);
        g[0] = fmaf(f.z, w2.x, g[0]); g[1] = fmaf(f.z, w2.y, g[1]);
        g[2] = fmaf(f.z, w2.z, g[2]); g[3] = fmaf(f.z, w2.w, g[3]);
        g[0] = fmaf(f.w, w3.x, g[0]); g[1] = fmaf(f.w, w3.y, g[1]);
        g[2] = fmaf(f.w, w3.z, g[2]); g[3] = fmaf(f.w, w3.w, g[3]);
    }
    *(float4*)(g_gx + (size_t)(p0 + p) * 32 + c4) = make_float4(g[0], g[1], g[2], g[3]);
}

// ======================= K2: per-sparse-point pipeline =====================
// warp per point; 2 lanes per neighbor (j = lane>>1, half = lane&1).
// Guidance uses linearity: (g - max_j g) @ W1 = g@W1 - (max_j g)@W1.
__global__ void __launch_bounds__(256) k2_point(
    const float* __restrict__ df,
    const float* __restrict__ vi_f,
    const int* __restrict__ nei,
    const float* __restrict__ wpe, const float* __restrict__ bpe,
    const float* __restrict__ wg1, const float* __restrict__ bg1,
    const float* __restrict__ wg2, const float* __restrict__ bg2,
    const float* __restrict__ wn1, const float* __restrict__ bn1,
    const float* __restrict__ wn2, const float* __restrict__ bn2,
    const float* __restrict__ wn3, const float* __restrict__ bn3) {
    __shared__ __align__(16) float s_wpet[32 * 12];  // [c][i]
    __shared__ __align__(16) float s_wg1[64 * 8];    // [c][h]
    __shared__ __align__(16) float s_wg2t[8 * 8];    // [h2][h]
    __shared__ __align__(16) float s_wn1t[8 * 12];   // [o][i]
    __shared__ __align__(16) float s_wn2t[8 * 8];    // [o][i]
    __shared__ __align__(16) float s_wn3t[16 * 8];   // [o][i]
    __shared__ float s_bpe[32], s_bg1[8], s_bg2[8], s_bn1[8], s_bn2[8], s_bn3[16];
    __shared__ __align__(16) float s_gf[8][16][64];  // [warp][j][c] g_feat
    __shared__ __align__(16) float s_nf[8][16][32];
    __shared__ __align__(16) float s_w[8][16][16];
    int t = threadIdx.x;
    for (int i = t; i < 384; i += 256) { int c = i / 12, ii = i % 12; s_wpet[i] = wpe[ii * 32 + c]; }
    for (int i = t; i < 512; i += 256) s_wg1[i] = wg1[i];
    if (t < 64) s_wg2t[t] = wg2[(t & 7) * 8 + (t >> 3)];
    if (t < 96) { int o = t / 12, ii = t % 12; s_wn1t[t] = wn1[ii * 8 + o]; }
    if (t < 64) s_wn2t[t] = wn2[(t & 7) * 8 + (t >> 3)];
    if (t < 128) { int o = t >> 3, ii = t & 7; s_wn3t[t] = wn3[ii * 16 + o]; }
    if (t < 32) s_bpe[t] = bpe[t];
    if (t < 8) { s_bg1[t] = bg1[t]; s_bg2[t] = bg2[t]; s_bn1[t] = bn1[t]; s_bn2[t] = bn2[t]; }
    if (t < 16) s_bn3[t] = bn3[t];
    __syncthreads();

    const unsigned FULL = 0xffffffffu;
    int wid = t >> 5, lane = t & 31;
    int j = lane >> 1, half = lane & 1;
    int m = blockIdx.x * 8 + wid;
    int idx = nei[m * 16 + j];

    // VI features for this neighbor
    float vi[12];
    {
        const float4* vp = (const float4*)(vi_f + ((size_t)m * 16 + j) * 12);
        float4 a = vp[0], b = vp[1], c = vp[2];
        vi[0] = a.x; vi[1] = a.y; vi[2] = a.z; vi[3] = a.w;
        vi[4] = b.x; vi[5] = b.y; vi[6] = b.z; vi[7] = b.w;
        vi[8] = c.x; vi[9] = c.y; vi[10] = c.z; vi[11] = c.w;
    }

    // g_feat half owned by this lane (half 0: gathered guidance, half 1: PE)
    float gf[32];
    if (half == 0) {
        const float4* gp = (const float4*)(g_gx + (size_t)idx * 32);
#pragma unroll
        for (int q = 0; q < 8; q++) {
            float4 v = gp[q];
            gf[4 * q] = v.x; gf[4 * q + 1] = v.y; gf[4 * q + 2] = v.z; gf[4 * q + 3] = v.w;
        }
    } else {
#pragma unroll
        for (int c = 0; c < 32; c++) {
            float a = s_bpe[c];
            const float4* wr = (const float4*)&s_wpet[c * 12];
            float4 w0 = wr[0], w1v = wr[1], w2 = wr[2];
            a = fmaf(vi[0], w0.x, a); a = fmaf(vi[1], w0.y, a);
            a = fmaf(vi[2], w0.z, a); a = fmaf(vi[3], w0.w, a);
            a = fmaf(vi[4], w1v.x, a); a = fmaf(vi[5], w1v.y, a);
            a = fmaf(vi[6], w1v.z, a); a = fmaf(vi[7], w1v.w, a);
            a = fmaf(vi[8], w2.x, a); a = fmaf(vi[9], w2.y, a);
            a = fmaf(vi[10], w2.z, a); a = fmaf(vi[11], w2.w, a);
            gf[c] = relu_f(a);
        }
    }

    // stash g_feat for channel-max; compute vW = gf @ W1 (this lane's half)
    int base = half * 32;
#pragma unroll
    for (int q = 0; q < 8; q++)
        *(float4*)&s_gf[wid][j][base + 4 * q] = make_float4(gf[4 * q], gf[4 * q + 1], gf[4 * q + 2], gf[4 * q + 3]);

    float part[8];
#pragma unroll
    for (int h = 0; h < 8; h++) part[h] = 0.f;
#pragma unroll
    for (int c = 0; c < 32; c++) {
        float v = gf[c];
        const float4* wr = (const float4*)&s_wg1[(base + c) * 8];
        float4 wa = wr[0], wb = wr[1];
        part[0] = fmaf(v, wa.x, part[0]); part[1] = fmaf(v, wa.y, part[1]);
        part[2] = fmaf(v, wa.z, part[2]); part[3] = fmaf(v, wa.w, part[3]);
        part[4] = fmaf(v, wb.x, part[4]); part[5] = fmaf(v, wb.y, part[5]);
        part[6] = fmaf(v, wb.z, part[6]); part[7] = fmaf(v, wb.w, part[7]);
    }
    __syncwarp();

    // channel max over K (lane owns channels lane, lane+32), then mxW = mx @ W1
    float mx0 = -3.0e38f, mx1 = -3.0e38f;
    int cl = lane;
#pragma unroll
    for (int jj = 0; jj < 16; jj++) {
        mx0 = fmaxf(mx0, s_gf[wid][jj][cl]);
        mx1 = fmaxf(mx1, s_gf[wid][jj][cl + 32]);
    }
    float mw[8];
    {
        const float4* wr0 = (const float4*)&s_wg1[cl * 8];
        const float4* wr1 = (const float4*)&s_wg1[(cl + 32) * 8];
        float4 a0 = wr0[0], a1 = wr0[1], b0 = wr1[0], b1v = wr1[1];
        mw[0] = fmaf(mx0, a0.x, mx1 * b0.x); mw[1] = fmaf(mx0, a0.y, mx1 * b0.y);
        mw[2] = fmaf(mx0, a0.z, mx1 * b0.z); mw[3] = fmaf(mx0, a0.w, mx1 * b0.w);
        mw[4] = fmaf(mx0, a1.x, mx1 * b1v.x); mw[5] = fmaf(mx0, a1.y, mx1 * b1v.y);
        mw[6] = fmaf(mx0, a1.z, mx1 * b1v.z); mw[7] = fmaf(mx0, a1.w, mx1 * b1v.w);
    }
#pragma unroll
    for (int s = 16; s >= 1; s >>= 1) {
#pragma unroll
        for (int h = 0; h < 8; h++) mw[h] += __shfl_xor_sync(FULL, mw[h], s);
    }
#pragma unroll
    for (int h = 0; h < 8; h++) part[h] += __shfl_xor_sync(FULL, part[h], 1);

    float s1v[8];
#pragma unroll
    for (int h = 0; h < 8; h++) s1v[h] = relu_f(part[h] - mw[h] + s_bg1[h]);
    float sc[8];
#pragma unroll
    for (int h2 = 0; h2 < 8; h2++) {
        float a = s_bg2[h2];
        const float4* wr = (const float4*)&s_wg2t[h2 * 8];
        float4 wa = wr[0], wb = wr[1];
        a = fmaf(s1v[0], wa.x, a); a = fmaf(s1v[1], wa.y, a);
        a = fmaf(s1v[2], wa.z, a); a = fmaf(s1v[3], wa.w, a);
        a = fmaf(s1v[4], wb.x, a); a = fmaf(s1v[5], wb.y, a);
        a = fmaf(s1v[6], wb.z, a); a = fmaf(s1v[7], wb.w, a);
        sc[h2] = 1.f / (1.f + expf(-a));
    }

    // WeightNet 12->8->8->16 (transposed weights, float4 LDS)
    float h1[8];
#pragma unroll
    for (int o = 0; o < 8; o++) {
        float a = s_bn1[o];
        const float4* wr = (const float4*)&s_wn1t[o * 12];
        float4 w0 = wr[0], w1v = wr[1], w2 = wr[2];
        a = fmaf(vi[0], w0.x, a); a = fmaf(vi[1], w0.y, a);
        a = fmaf(vi[2], w0.z, a); a = fmaf(vi[3], w0.w, a);
        a = fmaf(vi[4], w1v.x, a); a = fmaf(vi[5], w1v.y, a);
        a = fmaf(vi[6], w1v.z, a); a = fmaf(vi[7], w1v.w, a);
        a = fmaf(vi[8], w2.x, a); a = fmaf(vi[9], w2.y, a);
        a = fmaf(vi[10], w2.z, a); a = fmaf(vi[11], w2.w, a);
        h1[o] = relu_f(a);
    }
    float h2v[8];
#pragma unroll
    for (int o = 0; o < 8; o++) {
        float a = s_bn2[o];
        const float4* wr = (const float4*)&s_wn2t[o * 8];
        float4 wa = wr[0], wb = wr[1];
        a = fmaf(h1[0], wa.x, a); a = fmaf(h1[1], wa.y, a);
        a = fmaf(h1[2], wa.z, a); a = fmaf(h1[3], wa.w, a);
        a = fmaf(h1[4], wb.x, a); a = fmaf(h1[5], wb.y, a);
        a = fmaf(h1[6], wb.z, a); a = fmaf(h1[7], wb.w, a);
        h2v[o] = relu_f(a);
    }
#pragma unroll
    for (int oo = 0; oo < 8; oo++) {
        int o = half * 8 + oo;
        float a = s_bn3[o];
        const float4* wr = (const float4*)&s_wn3t[o * 8];
        float4 wa = wr[0], wb = wr[1];
        a = fmaf(h2v[0], wa.x, a); a = fmaf(h2v[1], wa.y, a);
        a = fmaf(h2v[2], wa.z, a); a = fmaf(h2v[3], wa.w, a);
        a = fmaf(h2v[4], wb.x, a); a = fmaf(h2v[5], wb.y, a);
        a = fmaf(h2v[6], wb.z, a); a = fmaf(h2v[7], wb.w, a);
        s_w[wid][j][o] = relu_f(a);
    }

    // nf = gathered feats_x * scores[head], head = c>>2
    {
        const float4* fp = (const float4*)(g_fx + (size_t)idx * 32 + half * 16);
#pragma unroll
        for (int q = 0; q < 4; q++) {
            float4 v = fp[q];
            int c0 = half * 16 + 4 * q;
            float s = sc[c0 >> 2];
            *(float4*)&s_nf[wid][j][c0] = make_float4(v.x * s, v.y * s, v.z * s, v.w * s);
        }
    }

    // shortcut maxpool of dense feats over neighborhood
    {
        float m0 = -3.0e38f, m1 = -3.0e38f;
#pragma unroll
        for (int jj = 0; jj < 16; jj++) {
            int ix = __shfl_sync(FULL, idx, jj * 2);
            m0 = fmaxf(m0, __ldg(&df[(size_t)ix * 64 + lane]));
            m1 = fmaxf(m1, __ldg(&df[(size_t)ix * 64 + 32 + lane]));
        }
        g_sf[(size_t)m * 64 + lane] = m0;
        g_sf[(size_t)m * 64 + 32 + lane] = m1;
    }
    __syncwarp();

    // agg[c][w] = sum_j nf[j][c] * w[j][w]
    float acc[16];
#pragma unroll
    for (int w = 0; w < 16; w++) acc[w] = 0.f;
    int c = lane;
#pragma unroll
    for (int jj = 0; jj < 16; jj++) {
        float a = s_nf[wid][jj][c];
        const float4* wp = (const float4*)&s_w[wid][jj][0];
        float4 w0 = wp[0], w1v = wp[1], w2 = wp[2], w3 = wp[3];
        acc[0] = fmaf(a, w0.x, acc[0]);  acc[1] = fmaf(a, w0.y, acc[1]);
        acc[2] = fmaf(a, w0.z, acc[2]);  acc[3] = fmaf(a, w0.w, acc[3]);
        acc[4] = fmaf(a, w1v.x, acc[4]); acc[5] = fmaf(a, w1v.y, acc[5]);
        acc[6] = fmaf(a, w1v.z, acc[6]); acc[7] = fmaf(a, w1v.w, acc[7]);
        acc[8] = fmaf(a, w2.x, acc[8]);  acc[9] = fmaf(a, w2.y, acc[9]);
        acc[10] = fmaf(a, w2.z, acc[10]); acc[11] = fmaf(a, w2.w, acc[11]);
        acc[12] = fmaf(a, w3.x, acc[12]); acc[13] = fmaf(a, w3.y, acc[13]);
        acc[14] = fmaf(a, w3.z, acc[14]); acc[15] = fmaf(a, w3.w, acc[15]);
    }
    float4* op = (float4*)(g_agg + (size_t)m * 512 + c * 16);
    op[0] = make_float4(acc[0], acc[1], acc[2], acc[3]);
    op[1] = make_float4(acc[4], acc[5], acc[6], acc[7]);
    op[2] = make_float4(acc[8], acc[9], acc[10], acc[11]);
    op[3] = make_float4(acc[12], acc[13], acc[14], acc[15]);
}

// ======================= K3: output GEMM + epilogue ========================
// 64 points x 64 outs per block; thread = 4 pts x 4 ch micro-tile.
__global__ void __launch_bounds__(256) k3_out(
    const float* __restrict__ wlin, const float* __restrict__ blin,
    const float* __restrict__ wu2, const float* __restrict__ bu2,
    const float* __restrict__ wsc, const float* __restrict__ bsc,
    float* __restrict__ out) {
    __shared__ union {
        struct { float a[64][68]; float w[64][64]; } s1;
        struct { float o[64][68]; float sf[64][68]; } s2;
    } u;
    int t = threadIdx.x;
    int m0 = blockIdx.x * 64;
    int r = t >> 4, cg = t & 15;
    int c4 = cg * 4;

    float acc[4][4];
#pragma unroll
    for (int i = 0; i < 4; i++)
#pragma unroll
        for (int q = 0; q < 4; q++) acc[i][q] = 0.f;

#pragma unroll 1
    for (int kt = 0; kt < 8; kt++) {
        int k0 = kt * 64;
#pragma unroll
        for (int q = 0; q < 4; q++) {  // stage A 64x64
            int id = t + q * 256;
            int pp = id >> 4, kk = (id & 15) * 4;
            int gm = m0 + pp; if (gm >= MPTS) gm = MPTS - 1;
            *(float4*)&u.s1.a[pp][kk] = *(const float4*)(g_agg + (size_t)gm * 512 + k0 + kk);
        }
#pragma unroll
        for (int q = 0; q < 4; q++) {  // stage W 64x64
            int id = t + q * 256;
            int kk = id >> 4, cc = (id & 15) * 4;
            *(float4*)&u.s1.w[kk][cc] = __ldg((const float4*)(wlin + (size_t)(k0 + kk) * 64 + cc));
        }
        __syncthreads();
#pragma unroll
        for (int kq = 0; kq < 16; kq++) {
            int kb = kq * 4;
            float4 a0 = *(const float4*)&u.s1.a[r * 4 + 0][kb];
            float4 a1 = *(const float4*)&u.s1.a[r * 4 + 1][kb];
            float4 a2 = *(const float4*)&u.s1.a[r * 4 + 2][kb];
            float4 a3 = *(const float4*)&u.s1.a[r * 4 + 3][kb];
#pragma unroll
            for (int q = 0; q < 4; q++) {
                float4 w = *(const float4*)&u.s1.w[kb + q][c4];
                float av0 = q == 0 ? a0.x : q == 1 ? a0.y : q == 2 ? a0.z : a0.w;
                float av1 = q == 0 ? a1.x : q == 1 ? a1.y : q == 2 ? a1.z : a1.w;
                float av2 = q == 0 ? a2.x : q == 1 ? a2.y : q == 2 ? a2.z : a2.w;
                float av3 = q == 0 ? a3.x : q == 1 ? a3.y : q == 2 ? a3.z : a3.w;
                acc[0][0] = fmaf(av0, w.x, acc[0][0]); acc[0][1] = fmaf(av0, w.y, acc[0][1]);
                acc[0][2] = fmaf(av0, w.z, acc[0][2]); acc[0][3] = fmaf(av0, w.w, acc[0][3]);
                acc[1][0] = fmaf(av1, w.x, acc[1][0]); acc[1][1] = fmaf(av1, w.y, acc[1][1]);
                acc[1][2] = fmaf(av1, w.z, acc[1][2]); acc[1][3] = fmaf(av1, w.w, acc[1][3]);
                acc[2][0] = fmaf(av2, w.x, acc[2][0]); acc[2][1] = fmaf(av2, w.y, acc[2][1]);
                acc[2][2] = fmaf(av2, w.z, acc[2][2]); acc[2][3] = fmaf(av2, w.w, acc[2][3]);
                acc[3][0] = fmaf(av3, w.x, acc[3][0]); acc[3][1] = fmaf(av3, w.y, acc[3][1]);
                acc[3][2] = fmaf(av3, w.z, acc[3][2]); acc[3][3] = fmaf(av3, w.w, acc[3][3]);
            }
        }
        __syncthreads();
    }

    {   // relu(acc + blin) -> s2.o
        float4 bl = __ldg((const float4*)(blin + c4));
#pragma unroll
        for (int i = 0; i < 4; i++) {
            *(float4*)&u.s2.o[r * 4 + i][c4] = make_float4(
                relu_f(acc[i][0] + bl.x), relu_f(acc[i][1] + bl.y),
                relu_f(acc[i][2] + bl.z), relu_f(acc[i][3] + bl.w));
        }
    }
#pragma unroll
    for (int q = 0; q < 4; q++) {  // stage sf 64x64
        int id = t + q * 256;
        int pp = id >> 4, kk = (id & 15) * 4;
        int gm = m0 + pp; if (gm >= MPTS) gm = MPTS - 1;
        *(float4*)&u.s2.sf[pp][kk] = *(const float4*)(g_sf + (size_t)gm * 64 + kk);
    }
    __syncthreads();

    // out128 = o @ wu2 + sf @ wsc + biases -> leaky(0.1); thread: 4 pts x 8 ch
    int ob = cg * 8;
    float r8[4][8];
    {
        float4 ba = __ldg((const float4*)(bu2 + ob));
        float4 bb = __ldg((const float4*)(bu2 + ob + 4));
        float4 sa = __ldg((const float4*)(bsc + ob));
        float4 sb = __ldg((const float4*)(bsc + ob + 4));
        float binit[8] = {ba.x + sa.x, ba.y + sa.y, ba.z + sa.z, ba.w + sa.w,
                          bb.x + sb.x, bb.y + sb.y, bb.z + sb.z, bb.w + sb.w};
#pragma unroll
        for (int i = 0; i < 4; i++)
#pragma unroll
            for (int q = 0; q < 8; q++) r8[i][q] = binit[q];
    }
#pragma unroll
    for (int k = 0; k < 64; k++) {
        float4 wa = __ldg((const float4*)(wu2 + (size_t)k * 128 + ob));
        float4 wb = __ldg((const float4*)(wu2 + (size_t)k * 128 + ob + 4));
        float4 va = __ldg((const float4*)(wsc + (size_t)k * 128 + ob));
        float4 vb = __ldg((const float4*)(wsc + (size_t)k * 128 + ob + 4));
#pragma unroll
        for (int i = 0; i < 4; i++) {
            float x = u.s2.o[r * 4 + i][k];
            float s = u.s2.sf[r * 4 + i][k];
            r8[i][0] = fmaf(x, wa.x, r8[i][0]); r8[i][1] = fmaf(x, wa.y, r8[i][1]);
            r8[i][2] = fmaf(x, wa.z, r8[i][2]); r8[i][3] = fmaf(x, wa.w, r8[i][3]);
            r8[i][4] = fmaf(x, wb.x, r8[i][4]); r8[i][5] = fmaf(x, wb.y, r8[i][5]);
            r8[i][6] = fmaf(x, wb.z, r8[i][6]); r8[i][7] = fmaf(x, wb.w, r8[i][7]);
            r8[i][0] = fmaf(s, va.x, r8[i][0]); r8[i][1] = fmaf(s, va.y, r8[i][1]);
            r8[i][2] = fmaf(s, va.z, r8[i][2]); r8[i][3] = fmaf(s, va.w, r8[i][3]);
            r8[i][4] = fmaf(s, vb.x, r8[i][4]); r8[i][5] = fmaf(s, vb.y, r8[i][5]);
            r8[i][6] = fmaf(s, vb.z, r8[i][6]); r8[i][7] = fmaf(s, vb.w, r8[i][7]);
        }
    }
#pragma unroll
    for (int i = 0; i < 4; i++) {
        int m = m0 + r * 4 + i;
        if (m < MPTS) {
            float4* op = (float4*)(out + (size_t)m * 128 + ob);
            op[0] = make_float4(lrelu_f(r8[i][0]), lrelu_f(r8[i][1]), lrelu_f(r8[i][2]), lrelu_f(r8[i][3]));
            op[1] = make_float4(lrelu_f(r8[i][4]), lrelu_f(r8[i][5]), lrelu_f(r8[i][6]), lrelu_f(r8[i][7]));
        }
    }
}

// ======================= launch ============================================
extern "C" void kernel_launch(void* const* d_in, const int* in_sizes, int n_in,
                              void* d_out, int out_size) {
    const float* df  = (const float*)d_in[1];   // dense_feats
    const float* vi  = (const float*)d_in[5];   // vi_features
    const int*   nei = (const int*)d_in[6];     // nei_inds
    const float* w1  = (const float*)d_in[7];
    const float* b1  = (const float*)d_in[8];
    const float* wgu = (const float*)d_in[9];
    const float* bgu = (const float*)d_in[10];
    const float* wpe = (const float*)d_in[11];
    const float* bpe = (const float*)d_in[12];
    const float* wg1 = (const float*)d_in[13];
    const float* bg1 = (const float*)d_in[14];
    const float* wg2 = (const float*)d_in[15];
    const float* bg2 = (const float*)d_in[16];
    const float* wn1 = (const float*)d_in[17];
    const float* bn1 = (const float*)d_in[18];
    const float* wn2 = (const float*)d_in[19];
    const float* bn2 = (const float*)d_in[20];
    const float* wn3 = (const float*)d_in[21];
    const float* bn3 = (const float*)d_in[22];
    const float* wlin = (const float*)d_in[23];
    const float* blin = (const float*)d_in[24];
    const float* wu2 = (const float*)d_in[25];
    const float* bu2 = (const float*)d_in[26];
    const float* wsc = (const float*)d_in[27];
    const float* bsc = (const float*)d_in[28];
    float* out = (float*)d_out;

    k1_dense<<<NPTS / 32, 256>>>(df, w1, b1, wgu, bgu);
    k2_point<<<MPTS / 8, 256>>>(df, vi, nei,
                                wpe, bpe, wg1, bg1, wg2, bg2,
                                wn1, bn1, wn2, bn2, wn3, bn3);
    k3_out<<<(MPTS + 63) / 64, 256>>>(wlin, blin, wu2, bu2, wsc, bsc, out);
}

// round 3
// speedup vs baseline: 1.4201x; 1.2499x over previous
#include <cuda_runtime.h>
#include <math.h>

#define NPTS 200000
#define MPTS 100000

// ---------------- scratch (device globals: allocation-free rule) ----------
__device__ float g_fx[NPTS * 32];            // feats_x        25.6 MB
__device__ float g_gx[NPTS * 32];            // guidance_x     25.6 MB
__device__ float g_agg[(size_t)MPTS * 512];  // agg            204.8 MB
__device__ float g_sf[MPTS * 64];            // maxpooled dense feats 25.6 MB

__device__ __forceinline__ float relu_f(float x) { return x > 0.f ? x : 0.f; }
__device__ __forceinline__ float lrelu_f(float x) { return x > 0.f ? x : 0.1f * x; }

// ======================= K1: dense transform ==============================
// 128 points/block, 256 threads; micro-tile = 4 pts x 4 ch.
__global__ void __launch_bounds__(256) k1_dense(
    const float* __restrict__ df,
    const float* __restrict__ w1, const float* __restrict__ b1,
    const float* __restrict__ wgu, const float* __restrict__ bgu) {
    __shared__ __align__(16) float s_w1[64 * 32];
    __shared__ __align__(16) float s_wgu[32 * 32];
    __shared__ union {
        float f[128][68];
        float fx[128][36];
    } u;
    int t = threadIdx.x;
    int p0 = blockIdx.x * 128;
    for (int i = t; i < 2048; i += 256) s_w1[i] = w1[i];
    for (int i = t; i < 1024; i += 256) s_wgu[i] = wgu[i];
#pragma unroll
    for (int q = 0; q < 8; q++) {
        int id = t + q * 256;
        int pp = id >> 4, kk = (id & 15) * 4;
        int gm = p0 + pp; if (gm >= NPTS) gm = NPTS - 1;
        *(float4*)&u.f[pp][kk] = *(const float4*)(df + (size_t)gm * 64 + kk);
    }
    __syncthreads();

    int pg = t >> 3, cg = t & 7;     // 32 pt-groups x 8 ch-groups
    int c4 = cg * 4;
    float4 bb = *(const float4*)(b1 + c4);
    float acc[4][4];
#pragma unroll
    for (int i = 0; i < 4; i++) { acc[i][0] = bb.x; acc[i][1] = bb.y; acc[i][2] = bb.z; acc[i][3] = bb.w; }
#pragma unroll
    for (int kb = 0; kb < 64; kb += 4) {
        float4 a[4];
#pragma unroll
        for (int i = 0; i < 4; i++) a[i] = *(const float4*)&u.f[pg * 4 + i][kb];
#pragma unroll
        for (int q = 0; q < 4; q++) {
            float4 w = *(const float4*)&s_w1[(kb + q) * 32 + c4];
#pragma unroll
            for (int i = 0; i < 4; i++) {
                float av = q == 0 ? a[i].x : q == 1 ? a[i].y : q == 2 ? a[i].z : a[i].w;
                acc[i][0] = fmaf(av, w.x, acc[i][0]); acc[i][1] = fmaf(av, w.y, acc[i][1]);
                acc[i][2] = fmaf(av, w.z, acc[i][2]); acc[i][3] = fmaf(av, w.w, acc[i][3]);
            }
        }
    }
    float4 fxv[4];
#pragma unroll
    for (int i = 0; i < 4; i++)
        fxv[i] = make_float4(lrelu_f(acc[i][0]), lrelu_f(acc[i][1]), lrelu_f(acc[i][2]), lrelu_f(acc[i][3]));
    __syncthreads();  // all reads of u.f done
#pragma unroll
    for (int i = 0; i < 4; i++) {
        int gm = p0 + pg * 4 + i;
        *(float4*)&u.fx[pg * 4 + i][c4] = fxv[i];
        if (gm < NPTS) *(float4*)(g_fx + (size_t)gm * 32 + c4) = fxv[i];
    }
    __syncthreads();

    float4 bg = *(const float4*)(bgu + c4);
    float gac[4][4];
#pragma unroll
    for (int i = 0; i < 4; i++) { gac[i][0] = bg.x; gac[i][1] = bg.y; gac[i][2] = bg.z; gac[i][3] = bg.w; }
#pragma unroll
    for (int kb = 0; kb < 32; kb += 4) {
        float4 a[4];
#pragma unroll
        for (int i = 0; i < 4; i++) a[i] = *(const float4*)&u.fx[pg * 4 + i][kb];
#pragma unroll
        for (int q = 0; q < 4; q++) {
            float4 w = *(const float4*)&s_wgu[(kb + q) * 32 + c4];
#pragma unroll
            for (int i = 0; i < 4; i++) {
                float av = q == 0 ? a[i].x : q == 1 ? a[i].y : q == 2 ? a[i].z : a[i].w;
                gac[i][0] = fmaf(av, w.x, gac[i][0]); gac[i][1] = fmaf(av, w.y, gac[i][1]);
                gac[i][2] = fmaf(av, w.z, gac[i][2]); gac[i][3] = fmaf(av, w.w, gac[i][3]);
            }
        }
    }
#pragma unroll
    for (int i = 0; i < 4; i++) {
        int gm = p0 + pg * 4 + i;
        if (gm < NPTS)
            *(float4*)(g_gx + (size_t)gm * 32 + c4) =
                make_float4(gac[i][0], gac[i][1], gac[i][2], gac[i][3]);
    }
}

// ======================= K2: per-sparse-point pipeline =====================
// warp per point; lane = (j = lane>>1, half = lane&1). NO divergent halves:
// every lane gathers 16 guidance ch AND computes 16 PE channels.
__global__ void __launch_bounds__(256) k2_point(
    const float* __restrict__ df,
    const float* __restrict__ vi_f,
    const int* __restrict__ nei,
    const float* __restrict__ wpe, const float* __restrict__ bpe,
    const float* __restrict__ wg1, const float* __restrict__ bg1,
    const float* __restrict__ wg2, const float* __restrict__ bg2,
    const float* __restrict__ wn1, const float* __restrict__ bn1,
    const float* __restrict__ wn2, const float* __restrict__ bn2,
    const float* __restrict__ wn3, const float* __restrict__ bn3) {
    __shared__ __align__(16) float s_wpet[32 * 12];  // [c][i]
    __shared__ __align__(16) float s_wg1[64 * 8];    // [c][h]
    __shared__ __align__(16) float s_wg2t[8 * 8];    // [h2][h]
    __shared__ __align__(16) float s_wn1t[8 * 12];   // [o][i]
    __shared__ __align__(16) float s_wn2t[8 * 8];    // [o][i]
    __shared__ __align__(16) float s_wn3t[16 * 8];   // [o][i]
    __shared__ float s_bpe[32], s_bg1[8], s_bg2[8], s_bn1[8], s_bn2[8], s_bn3[16];
    __shared__ __align__(16) float s_gf[8][16][68];  // padded (bank spread)
    __shared__ __align__(16) float s_nf[8][16][36];
    __shared__ __align__(16) float s_w[8][16][20];
    int t = threadIdx.x;
    for (int i = t; i < 384; i += 256) { int c = i / 12, ii = i % 12; s_wpet[i] = wpe[ii * 32 + c]; }
    for (int i = t; i < 512; i += 256) s_wg1[i] = wg1[i];
    if (t < 64) s_wg2t[t] = wg2[(t & 7) * 8 + (t >> 3)];
    if (t < 96) { int o = t / 12, ii = t % 12; s_wn1t[t] = wn1[ii * 8 + o]; }
    if (t < 64) s_wn2t[t] = wn2[(t & 7) * 8 + (t >> 3)];
    if (t < 128) { int o = t >> 3, ii = t & 7; s_wn3t[t] = wn3[ii * 16 + o]; }
    if (t < 32) s_bpe[t] = bpe[t];
    if (t < 8) { s_bg1[t] = bg1[t]; s_bg2[t] = bg2[t]; s_bn1[t] = bn1[t]; s_bn2[t] = bn2[t]; }
    if (t < 16) s_bn3[t] = bn3[t];
    __syncthreads();

    const unsigned FULL = 0xffffffffu;
    int wid = t >> 5, lane = t & 31;
    int j = lane >> 1, half = lane & 1;
    int m = blockIdx.x * 8 + wid;
    int idx = __ldg(&nei[m * 16 + j]);

    // VI features for this neighbor (both lanes of pair load)
    float vi[12];
    {
        const float4* vp = (const float4*)(vi_f + ((size_t)m * 16 + j) * 12);
        float4 a = vp[0], b = vp[1], c = vp[2];
        vi[0] = a.x; vi[1] = a.y; vi[2] = a.z; vi[3] = a.w;
        vi[4] = b.x; vi[5] = b.y; vi[6] = b.z; vi[7] = b.w;
        vi[8] = c.x; vi[9] = c.y; vi[10] = c.z; vi[11] = c.w;
    }

    // gather half of guidance (16 floats)
    float gg[16];
    {
        const float4* gp = (const float4*)(g_gx + (size_t)idx * 32 + half * 16);
#pragma unroll
        for (int q = 0; q < 4; q++) {
            float4 v = gp[q];
            gg[4 * q] = v.x; gg[4 * q + 1] = v.y; gg[4 * q + 2] = v.z; gg[4 * q + 3] = v.w;
            *(float4*)&s_gf[wid][j][half * 16 + 4 * q] = v;
        }
    }
    // compute half of PE (16 channels)
    float pe[16];
#pragma unroll
    for (int c16 = 0; c16 < 16; c16++) {
        int c = half * 16 + c16;
        float a = s_bpe[c];
        const float4* wr = (const float4*)&s_wpet[c * 12];
        float4 w0 = wr[0], w1v = wr[1], w2 = wr[2];
        a = fmaf(vi[0], w0.x, a); a = fmaf(vi[1], w0.y, a);
        a = fmaf(vi[2], w0.z, a); a = fmaf(vi[3], w0.w, a);
        a = fmaf(vi[4], w1v.x, a); a = fmaf(vi[5], w1v.y, a);
        a = fmaf(vi[6], w1v.z, a); a = fmaf(vi[7], w1v.w, a);
        a = fmaf(vi[8], w2.x, a); a = fmaf(vi[9], w2.y, a);
        a = fmaf(vi[10], w2.z, a); a = fmaf(vi[11], w2.w, a);
        float r = relu_f(a);
        pe[c16] = r;
        s_gf[wid][j][32 + c] = r;
    }

    // W1 partial over this lane's 32 owned channels
    float part[8];
#pragma unroll
    for (int h = 0; h < 8; h++) part[h] = 0.f;
#pragma unroll
    for (int c16 = 0; c16 < 16; c16++) {
        float v = gg[c16];
        const float4* wr = (const float4*)&s_wg1[(half * 16 + c16) * 8];
        float4 wa = wr[0], wb = wr[1];
        part[0] = fmaf(v, wa.x, part[0]); part[1] = fmaf(v, wa.y, part[1]);
        part[2] = fmaf(v, wa.z, part[2]); part[3] = fmaf(v, wa.w, part[3]);
        part[4] = fmaf(v, wb.x, part[4]); part[5] = fmaf(v, wb.y, part[5]);
        part[6] = fmaf(v, wb.z, part[6]); part[7] = fmaf(v, wb.w, part[7]);
    }
#pragma unroll
    for (int c16 = 0; c16 < 16; c16++) {
        float v = pe[c16];
        const float4* wr = (const float4*)&s_wg1[(32 + half * 16 + c16) * 8];
        float4 wa = wr[0], wb = wr[1];
        part[0] = fmaf(v, wa.x, part[0]); part[1] = fmaf(v, wa.y, part[1]);
        part[2] = fmaf(v, wa.z, part[2]); part[3] = fmaf(v, wa.w, part[3]);
        part[4] = fmaf(v, wb.x, part[4]); part[5] = fmaf(v, wb.y, part[5]);
        part[6] = fmaf(v, wb.z, part[6]); part[7] = fmaf(v, wb.w, part[7]);
    }
    __syncwarp();

    // channel max over K (lane owns channels lane, lane+32), then mxW = mx @ W1
    float mx0 = -3.0e38f, mx1 = -3.0e38f;
    int cl = lane;
#pragma unroll
    for (int jj = 0; jj < 16; jj++) {
        mx0 = fmaxf(mx0, s_gf[wid][jj][cl]);
        mx1 = fmaxf(mx1, s_gf[wid][jj][cl + 32]);
    }
    float mw[8];
    {
        const float4* wr0 = (const float4*)&s_wg1[cl * 8];
        const float4* wr1 = (const float4*)&s_wg1[(cl + 32) * 8];
        float4 a0 = wr0[0], a1 = wr0[1], b0 = wr1[0], b1v = wr1[1];
        mw[0] = fmaf(mx0, a0.x, mx1 * b0.x); mw[1] = fmaf(mx0, a0.y, mx1 * b0.y);
        mw[2] = fmaf(mx0, a0.z, mx1 * b0.z); mw[3] = fmaf(mx0, a0.w, mx1 * b0.w);
        mw[4] = fmaf(mx0, a1.x, mx1 * b1v.x); mw[5] = fmaf(mx0, a1.y, mx1 * b1v.y);
        mw[6] = fmaf(mx0, a1.z, mx1 * b1v.z); mw[7] = fmaf(mx0, a1.w, mx1 * b1v.w);
    }
#pragma unroll
    for (int s = 16; s >= 1; s >>= 1) {
#pragma unroll
        for (int h = 0; h < 8; h++) mw[h] += __shfl_xor_sync(FULL, mw[h], s);
    }
#pragma unroll
    for (int h = 0; h < 8; h++) part[h] += __shfl_xor_sync(FULL, part[h], 1);

    float s1v[8];
#pragma unroll
    for (int h = 0; h < 8; h++) s1v[h] = relu_f(part[h] - mw[h] + s_bg1[h]);
    float sc[8];
#pragma unroll
    for (int h2 = 0; h2 < 8; h2++) {
        float a = s_bg2[h2];
        const float4* wr = (const float4*)&s_wg2t[h2 * 8];
        float4 wa = wr[0], wb = wr[1];
        a = fmaf(s1v[0], wa.x, a); a = fmaf(s1v[1], wa.y, a);
        a = fmaf(s1v[2], wa.z, a); a = fmaf(s1v[3], wa.w, a);
        a = fmaf(s1v[4], wb.x, a); a = fmaf(s1v[5], wb.y, a);
        a = fmaf(s1v[6], wb.z, a); a = fmaf(s1v[7], wb.w, a);
        sc[h2] = 1.f / (1.f + __expf(-a));
    }

    // WeightNet 12->8->8->16 (hidden full per lane, final split by half)
    float h1[8];
#pragma unroll
    for (int o = 0; o < 8; o++) {
        float a = s_bn1[o];
        const float4* wr = (const float4*)&s_wn1t[o * 12];
        float4 w0 = wr[0], w1v = wr[1], w2 = wr[2];
        a = fmaf(vi[0], w0.x, a); a = fmaf(vi[1], w0.y, a);
        a = fmaf(vi[2], w0.z, a); a = fmaf(vi[3], w0.w, a);
        a = fmaf(vi[4], w1v.x, a); a = fmaf(vi[5], w1v.y, a);
        a = fmaf(vi[6], w1v.z, a); a = fmaf(vi[7], w1v.w, a);
        a = fmaf(vi[8], w2.x, a); a = fmaf(vi[9], w2.y, a);
        a = fmaf(vi[10], w2.z, a); a = fmaf(vi[11], w2.w, a);
        h1[o] = relu_f(a);
    }
    float h2v[8];
#pragma unroll
    for (int o = 0; o < 8; o++) {
        float a = s_bn2[o];
        const float4* wr = (const float4*)&s_wn2t[o * 8];
        float4 wa = wr[0], wb = wr[1];
        a = fmaf(h1[0], wa.x, a); a = fmaf(h1[1], wa.y, a);
        a = fmaf(h1[2], wa.z, a); a = fmaf(h1[3], wa.w, a);
        a = fmaf(h1[4], wb.x, a); a = fmaf(h1[5], wb.y, a);
        a = fmaf(h1[6], wb.z, a); a = fmaf(h1[7], wb.w, a);
        h2v[o] = relu_f(a);
    }
#pragma unroll
    for (int oo = 0; oo < 8; oo++) {
        int o = half * 8 + oo;
        float a = s_bn3[o];
        const float4* wr = (const float4*)&s_wn3t[o * 8];
        float4 wa = wr[0], wb = wr[1];
        a = fmaf(h2v[0], wa.x, a); a = fmaf(h2v[1], wa.y, a);
        a = fmaf(h2v[2], wa.z, a); a = fmaf(h2v[3], wa.w, a);
        a = fmaf(h2v[4], wb.x, a); a = fmaf(h2v[5], wb.y, a);
        a = fmaf(h2v[6], wb.z, a); a = fmaf(h2v[7], wb.w, a);
        s_w[wid][j][o] = relu_f(a);
    }

    // nf = gathered feats_x * scores[head], head = c>>2
    {
        const float4* fp = (const float4*)(g_fx + (size_t)idx * 32 + half * 16);
#pragma unroll
        for (int q = 0; q < 4; q++) {
            float4 v = fp[q];
            int c0 = half * 16 + 4 * q;
            float s = sc[c0 >> 2];
            *(float4*)&s_nf[wid][j][c0] = make_float4(v.x * s, v.y * s, v.z * s, v.w * s);
        }
    }

    // shortcut maxpool of dense feats over neighborhood
    {
        float m0 = -3.0e38f, m1 = -3.0e38f;
#pragma unroll
        for (int jj = 0; jj < 16; jj++) {
            int ix = __shfl_sync(FULL, idx, jj * 2);
            m0 = fmaxf(m0, __ldg(&df[(size_t)ix * 64 + lane]));
            m1 = fmaxf(m1, __ldg(&df[(size_t)ix * 64 + 32 + lane]));
        }
        g_sf[(size_t)m * 64 + lane] = m0;
        g_sf[(size_t)m * 64 + 32 + lane] = m1;
    }
    __syncwarp();

    // agg[c][w] = sum_j nf[j][c] * w[j][w]
    float acc[16];
#pragma unroll
    for (int w = 0; w < 16; w++) acc[w] = 0.f;
    int c = lane;
#pragma unroll
    for (int jj = 0; jj < 16; jj++) {
        float a = s_nf[wid][jj][c];
        const float4* wp = (const float4*)&s_w[wid][jj][0];
        float4 w0 = wp[0], w1v = wp[1], w2 = wp[2], w3 = wp[3];
        acc[0] = fmaf(a, w0.x, acc[0]);  acc[1] = fmaf(a, w0.y, acc[1]);
        acc[2] = fmaf(a, w0.z, acc[2]);  acc[3] = fmaf(a, w0.w, acc[3]);
        acc[4] = fmaf(a, w1v.x, acc[4]); acc[5] = fmaf(a, w1v.y, acc[5]);
        acc[6] = fmaf(a, w1v.z, acc[6]); acc[7] = fmaf(a, w1v.w, acc[7]);
        acc[8] = fmaf(a, w2.x, acc[8]);  acc[9] = fmaf(a, w2.y, acc[9]);
        acc[10] = fmaf(a, w2.z, acc[10]); acc[11] = fmaf(a, w2.w, acc[11]);
        acc[12] = fmaf(a, w3.x, acc[12]); acc[13] = fmaf(a, w3.y, acc[13]);
        acc[14] = fmaf(a, w3.z, acc[14]); acc[15] = fmaf(a, w3.w, acc[15]);
    }
    float4* op = (float4*)(g_agg + (size_t)m * 512 + c * 16);
    op[0] = make_float4(acc[0], acc[1], acc[2], acc[3]);
    op[1] = make_float4(acc[4], acc[5], acc[6], acc[7]);
    op[2] = make_float4(acc[8], acc[9], acc[10], acc[11]);
    op[3] = make_float4(acc[12], acc[13], acc[14], acc[15]);
}

// ======================= K3: output GEMM + epilogue ========================
// 128 points x 64 outs per block, 256 threads; micro-tile 8 pts x 4 ch.
__global__ void __launch_bounds__(256) k3_out(
    const float* __restrict__ wlin, const float* __restrict__ blin,
    const float* __restrict__ wu2, const float* __restrict__ bu2,
    const float* __restrict__ wsc, const float* __restrict__ bsc,
    float* __restrict__ out) {
    __shared__ union {
        struct { float a[128][68]; float w[64][64]; } s1;
        struct { float o[128][64]; float sf[128][64]; } s2;
    } u;
    int t = threadIdx.x;
    int m0 = blockIdx.x * 128;
    int r = t >> 4, cg = t & 15;
    int c4 = cg * 4;

    float acc[8][4];
#pragma unroll
    for (int i = 0; i < 8; i++)
#pragma unroll
        for (int q = 0; q < 4; q++) acc[i][q] = 0.f;

#pragma unroll 1
    for (int kt = 0; kt < 8; kt++) {
        int k0 = kt * 64;
#pragma unroll
        for (int q = 0; q < 8; q++) {  // stage A 128x64
            int id = t + q * 256;
            int pp = id >> 4, kk = (id & 15) * 4;
            int gm = m0 + pp; if (gm >= MPTS) gm = MPTS - 1;
            *(float4*)&u.s1.a[pp][kk] = *(const float4*)(g_agg + (size_t)gm * 512 + k0 + kk);
        }
#pragma unroll
        for (int q = 0; q < 4; q++) {  // stage W 64x64
            int id = t + q * 256;
            int kk = id >> 4, cc = (id & 15) * 4;
            *(float4*)&u.s1.w[kk][cc] = __ldg((const float4*)(wlin + (size_t)(k0 + kk) * 64 + cc));
        }
        __syncthreads();
#pragma unroll
        for (int kq = 0; kq < 16; kq++) {
            int kb = kq * 4;
            float4 a[8];
#pragma unroll
            for (int i = 0; i < 8; i++) a[i] = *(const float4*)&u.s1.a[r * 8 + i][kb];
#pragma unroll
            for (int q = 0; q < 4; q++) {
                float4 w = *(const float4*)&u.s1.w[kb + q][c4];
#pragma unroll
                for (int i = 0; i < 8; i++) {
                    float av = q == 0 ? a[i].x : q == 1 ? a[i].y : q == 2 ? a[i].z : a[i].w;
                    acc[i][0] = fmaf(av, w.x, acc[i][0]); acc[i][1] = fmaf(av, w.y, acc[i][1]);
                    acc[i][2] = fmaf(av, w.z, acc[i][2]); acc[i][3] = fmaf(av, w.w, acc[i][3]);
                }
            }
        }
        __syncthreads();
    }

    {   // relu(acc + blin) -> s2.o  (overlaps s1: all reads done)
        float4 bl = __ldg((const float4*)(blin + c4));
#pragma unroll
        for (int i = 0; i < 8; i++) {
            *(float4*)&u.s2.o[r * 8 + i][c4] = make_float4(
                relu_f(acc[i][0] + bl.x), relu_f(acc[i][1] + bl.y),
                relu_f(acc[i][2] + bl.z), relu_f(acc[i][3] + bl.w));
        }
    }
#pragma unroll
    for (int q = 0; q < 8; q++) {  // stage sf 128x64
        int id = t + q * 256;
        int pp = id >> 4, kk = (id & 15) * 4;
        int gm = m0 + pp; if (gm >= MPTS) gm = MPTS - 1;
        *(float4*)&u.s2.sf[pp][kk] = *(const float4*)(g_sf + (size_t)gm * 64 + kk);
    }
    __syncthreads();

    // out128 = o @ wu2 + sf @ wsc + biases -> leaky(0.1); thread: 8 pts x 8 ch
    int ob = cg * 8;
    float r8[8][8];
    {
        float4 ba = __ldg((const float4*)(bu2 + ob));
        float4 bb = __ldg((const float4*)(bu2 + ob + 4));
        float4 sa = __ldg((const float4*)(bsc + ob));
        float4 sb = __ldg((const float4*)(bsc + ob + 4));
        float binit[8] = {ba.x + sa.x, ba.y + sa.y, ba.z + sa.z, ba.w + sa.w,
                          bb.x + sb.x, bb.y + sb.y, bb.z + sb.z, bb.w + sb.w};
#pragma unroll
        for (int i = 0; i < 8; i++)
#pragma unroll
            for (int q = 0; q < 8; q++) r8[i][q] = binit[q];
    }
#pragma unroll 4
    for (int k = 0; k < 64; k++) {
        float4 wa = __ldg((const float4*)(wu2 + (size_t)k * 128 + ob));
        float4 wb = __ldg((const float4*)(wu2 + (size_t)k * 128 + ob + 4));
        float4 va = __ldg((const float4*)(wsc + (size_t)k * 128 + ob));
        float4 vb = __ldg((const float4*)(wsc + (size_t)k * 128 + ob + 4));
#pragma unroll
        for (int i = 0; i < 8; i++) {
            float x = u.s2.o[r * 8 + i][k];
            float s = u.s2.sf[r * 8 + i][k];
            r8[i][0] = fmaf(x, wa.x, r8[i][0]); r8[i][1] = fmaf(x, wa.y, r8[i][1]);
            r8[i][2] = fmaf(x, wa.z, r8[i][2]); r8[i][3] = fmaf(x, wa.w, r8[i][3]);
            r8[i][4] = fmaf(x, wb.x, r8[i][4]); r8[i][5] = fmaf(x, wb.y, r8[i][5]);
            r8[i][6] = fmaf(x, wb.z, r8[i][6]); r8[i][7] = fmaf(x, wb.w, r8[i][7]);
            r8[i][0] = fmaf(s, va.x, r8[i][0]); r8[i][1] = fmaf(s, va.y, r8[i][1]);
            r8[i][2] = fmaf(s, va.z, r8[i][2]); r8[i][3] = fmaf(s, va.w, r8[i][3]);
            r8[i][4] = fmaf(s, vb.x, r8[i][4]); r8[i][5] = fmaf(s, vb.y, r8[i][5]);
            r8[i][6] = fmaf(s, vb.z, r8[i][6]); r8[i][7] = fmaf(s, vb.w, r8[i][7]);
        }
    }
#pragma unroll
    for (int i = 0; i < 8; i++) {
        int m = m0 + r * 8 + i;
        if (m < MPTS) {
            float4* op = (float4*)(out + (size_t)m * 128 + ob);
            op[0] = make_float4(lrelu_f(r8[i][0]), lrelu_f(r8[i][1]), lrelu_f(r8[i][2]), lrelu_f(r8[i][3]));
            op[1] = make_float4(lrelu_f(r8[i][4]), lrelu_f(r8[i][5]), lrelu_f(r8[i][6]), lrelu_f(r8[i][7]));
        }
    }
}

// ======================= launch ============================================
extern "C" void kernel_launch(void* const* d_in, const int* in_sizes, int n_in,
                              void* d_out, int out_size) {
    const float* df  = (const float*)d_in[1];   // dense_feats
    const float* vi  = (const float*)d_in[5];   // vi_features
    const int*   nei = (const int*)d_in[6];     // nei_inds
    const float* w1  = (const float*)d_in[7];
    const float* b1  = (const float*)d_in[8];
    const float* wgu = (const float*)d_in[9];
    const float* bgu = (const float*)d_in[10];
    const float* wpe = (const float*)d_in[11];
    const float* bpe = (const float*)d_in[12];
    const float* wg1 = (const float*)d_in[13];
    const float* bg1 = (const float*)d_in[14];
    const float* wg2 = (const float*)d_in[15];
    const float* bg2 = (const float*)d_in[16];
    const float* wn1 = (const float*)d_in[17];
    const float* bn1 = (const float*)d_in[18];
    const float* wn2 = (const float*)d_in[19];
    const float* bn2 = (const float*)d_in[20];
    const float* wn3 = (const float*)d_in[21];
    const float* bn3 = (const float*)d_in[22];
    const float* wlin = (const float*)d_in[23];
    const float* blin = (const float*)d_in[24];
    const float* wu2 = (const float*)d_in[25];
    const float* bu2 = (const float*)d_in[26];
    const float* wsc = (const float*)d_in[27];
    const float* bsc = (const float*)d_in[28];
    float* out = (float*)d_out;

    k1_dense<<<(NPTS + 127) / 128, 256>>>(df, w1, b1, wgu, bgu);
    k2_point<<<MPTS / 8, 256>>>(df, vi, nei,
                                wpe, bpe, wg1, bg1, wg2, bg2,
                                wn1, bn1, wn2, bn2, wn3, bn3);
    k3_out<<<(MPTS + 127) / 128, 256>>>(wlin, blin, wu2, bu2, wsc, bsc, out);
}

// round 5
// speedup vs baseline: 1.5815x; 1.1136x over previous
#include <cuda_runtime.h>
#include <cuda_bf16.h>
#include <math.h>
#include <stdint.h>

#define NPTS 200000
#define MPTS 100000

// ---------------- scratch (device globals: allocation-free rule) ----------
__device__ float g_fx[NPTS * 32];                     // feats_x     25.6 MB
__device__ float g_gx[NPTS * 32];                     // guidance_x  25.6 MB
__device__ __nv_bfloat16 g_aggh[(size_t)MPTS * 512];  // agg hi     102.4 MB
__device__ __nv_bfloat16 g_aggl[(size_t)MPTS * 512];  // agg lo     102.4 MB
__device__ float g_sf[MPTS * 64];                     // maxpooled feats
__device__ __nv_bfloat16 g_bh[64 * 512];              // w_lin^T hi  [n][k]
__device__ __nv_bfloat16 g_bl[64 * 512];              // w_lin^T lo  [n][k]

__device__ __forceinline__ float relu_f(float x) { return x > 0.f ? x : 0.f; }
__device__ __forceinline__ float lrelu_f(float x) { return x > 0.f ? x : 0.1f * x; }

__device__ __forceinline__ uint32_t smem_u32(const void* p) {
    uint32_t a;
    asm("{ .reg .u64 t; cvta.to.shared.u64 t, %1; cvt.u32.u64 %0, t; }" : "=r"(a) : "l"(p));
    return a;
}
__device__ __forceinline__ void ldsm4(uint32_t* r, uint32_t a) {
    asm volatile("ldmatrix.sync.aligned.m8n8.x4.shared.b16 {%0,%1,%2,%3}, [%4];"
                 : "=r"(r[0]), "=r"(r[1]), "=r"(r[2]), "=r"(r[3]) : "r"(a));
}
__device__ __forceinline__ void mma16816(float* d, const uint32_t* a, const uint32_t* b) {
    asm volatile(
        "mma.sync.aligned.m16n8k16.row.col.f32.bf16.bf16.f32 "
        "{%0,%1,%2,%3}, {%4,%5,%6,%7}, {%8,%9}, {%0,%1,%2,%3};"
        : "+f"(d[0]), "+f"(d[1]), "+f"(d[2]), "+f"(d[3])
        : "r"(a[0]), "r"(a[1]), "r"(a[2]), "r"(a[3]), "r"(b[0]), "r"(b[1]));
}

// ======================= K0: w_lin -> bf16 hi/lo transposed ================
__global__ void __launch_bounds__(256) k0_wconv(const float* __restrict__ wlin) {
    int i = blockIdx.x * 256 + threadIdx.x;
    if (i < 512 * 64) {
        int n = i >> 9, k = i & 511;
        float v = __ldg(&wlin[k * 64 + n]);
        __nv_bfloat16 h = __float2bfloat16(v);
        g_bh[i] = h;
        g_bl[i] = __float2bfloat16(v - __bfloat162float(h));
    }
}

// ======================= K1: dense transform ==============================
__global__ void __launch_bounds__(256) k1_dense(
    const float* __restrict__ df,
    const float* __restrict__ w1, const float* __restrict__ b1,
    const float* __restrict__ wgu, const float* __restrict__ bgu) {
    __shared__ __align__(16) float s_w1[64 * 32];
    __shared__ __align__(16) float s_wgu[32 * 32];
    __shared__ union {
        float f[128][68];
        float fx[128][36];
    } u;
    int t = threadIdx.x;
    int p0 = blockIdx.x * 128;
    for (int i = t; i < 2048; i += 256) s_w1[i] = w1[i];
    for (int i = t; i < 1024; i += 256) s_wgu[i] = wgu[i];
#pragma unroll
    for (int q = 0; q < 8; q++) {
        int id = t + q * 256;
        int pp = id >> 4, kk = (id & 15) * 4;
        int gm = p0 + pp; if (gm >= NPTS) gm = NPTS - 1;
        *(float4*)&u.f[pp][kk] = *(const float4*)(df + (size_t)gm * 64 + kk);
    }
    __syncthreads();

    int pg = t >> 3, cg = t & 7;
    int c4 = cg * 4;
    float4 bb = *(const float4*)(b1 + c4);
    float acc[4][4];
#pragma unroll
    for (int i = 0; i < 4; i++) { acc[i][0] = bb.x; acc[i][1] = bb.y; acc[i][2] = bb.z; acc[i][3] = bb.w; }
#pragma unroll
    for (int kb = 0; kb < 64; kb += 4) {
        float4 a[4];
#pragma unroll
        for (int i = 0; i < 4; i++) a[i] = *(const float4*)&u.f[pg * 4 + i][kb];
#pragma unroll
        for (int q = 0; q < 4; q++) {
            float4 w = *(const float4*)&s_w1[(kb + q) * 32 + c4];
#pragma unroll
            for (int i = 0; i < 4; i++) {
                float av = q == 0 ? a[i].x : q == 1 ? a[i].y : q == 2 ? a[i].z : a[i].w;
                acc[i][0] = fmaf(av, w.x, acc[i][0]); acc[i][1] = fmaf(av, w.y, acc[i][1]);
                acc[i][2] = fmaf(av, w.z, acc[i][2]); acc[i][3] = fmaf(av, w.w, acc[i][3]);
            }
        }
    }
    float4 fxv[4];
#pragma unroll
    for (int i = 0; i < 4; i++)
        fxv[i] = make_float4(lrelu_f(acc[i][0]), lrelu_f(acc[i][1]), lrelu_f(acc[i][2]), lrelu_f(acc[i][3]));
    __syncthreads();
#pragma unroll
    for (int i = 0; i < 4; i++) {
        int gm = p0 + pg * 4 + i;
        *(float4*)&u.fx[pg * 4 + i][c4] = fxv[i];
        if (gm < NPTS) *(float4*)(g_fx + (size_t)gm * 32 + c4) = fxv[i];
    }
    __syncthreads();

    float4 bg = *(const float4*)(bgu + c4);
    float gac[4][4];
#pragma unroll
    for (int i = 0; i < 4; i++) { gac[i][0] = bg.x; gac[i][1] = bg.y; gac[i][2] = bg.z; gac[i][3] = bg.w; }
#pragma unroll
    for (int kb = 0; kb < 32; kb += 4) {
        float4 a[4];
#pragma unroll
        for (int i = 0; i < 4; i++) a[i] = *(const float4*)&u.fx[pg * 4 + i][kb];
#pragma unroll
        for (int q = 0; q < 4; q++) {
            float4 w = *(const float4*)&s_wgu[(kb + q) * 32 + c4];
#pragma unroll
            for (int i = 0; i < 4; i++) {
                float av = q == 0 ? a[i].x : q == 1 ? a[i].y : q == 2 ? a[i].z : a[i].w;
                gac[i][0] = fmaf(av, w.x, gac[i][0]); gac[i][1] = fmaf(av, w.y, gac[i][1]);
                gac[i][2] = fmaf(av, w.z, gac[i][2]); gac[i][3] = fmaf(av, w.w, gac[i][3]);
            }
        }
    }
#pragma unroll
    for (int i = 0; i < 4; i++) {
        int gm = p0 + pg * 4 + i;
        if (gm < NPTS)
            *(float4*)(g_gx + (size_t)gm * 32 + c4) =
                make_float4(gac[i][0], gac[i][1], gac[i][2], gac[i][3]);
    }
}

// ======================= K2: per-sparse-point pipeline =====================
__global__ void __launch_bounds__(256) k2_point(
    const float* __restrict__ df,
    const float* __restrict__ vi_f,
    const int* __restrict__ nei,
    const float* __restrict__ wpe, const float* __restrict__ bpe,
    const float* __restrict__ wg1, const float* __restrict__ bg1,
    const float* __restrict__ wg2, const float* __restrict__ bg2,
    const float* __restrict__ wn1, const float* __restrict__ bn1,
    const float* __restrict__ wn2, const float* __restrict__ bn2,
    const float* __restrict__ wn3, const float* __restrict__ bn3) {
    __shared__ __align__(16) float s_wpet[32 * 12];
    __shared__ __align__(16) float s_wg1[64 * 8];
    __shared__ __align__(16) float s_wg2t[8 * 8];
    __shared__ __align__(16) float s_wn1t[8 * 12];
    __shared__ __align__(16) float s_wn2t[8 * 8];
    __shared__ __align__(16) float s_wn3t[16 * 8];
    __shared__ float s_bpe[32], s_bg1[8], s_bg2[8], s_bn1[8], s_bn2[8], s_bn3[16];
    __shared__ __align__(16) float s_gf[8][16][68];
    __shared__ __align__(16) float s_nf[8][16][36];
    __shared__ __align__(16) float s_w[8][16][20];
    int t = threadIdx.x;
    for (int i = t; i < 384; i += 256) { int c = i / 12, ii = i % 12; s_wpet[i] = wpe[ii * 32 + c]; }
    for (int i = t; i < 512; i += 256) s_wg1[i] = wg1[i];
    if (t < 64) s_wg2t[t] = wg2[(t & 7) * 8 + (t >> 3)];
    if (t < 96) { int o = t / 12, ii = t % 12; s_wn1t[t] = wn1[ii * 8 + o]; }
    if (t < 64) s_wn2t[t] = wn2[(t & 7) * 8 + (t >> 3)];
    if (t < 128) { int o = t >> 3, ii = t & 7; s_wn3t[t] = wn3[ii * 16 + o]; }
    if (t < 32) s_bpe[t] = bpe[t];
    if (t < 8) { s_bg1[t] = bg1[t]; s_bg2[t] = bg2[t]; s_bn1[t] = bn1[t]; s_bn2[t] = bn2[t]; }
    if (t < 16) s_bn3[t] = bn3[t];
    __syncthreads();

    const unsigned FULL = 0xffffffffu;
    int wid = t >> 5, lane = t & 31;
    int j = lane >> 1, half = lane & 1;
    int m = blockIdx.x * 8 + wid;
    int idx = __ldg(&nei[m * 16 + j]);

    float vi[12];
    {
        const float4* vp = (const float4*)(vi_f + ((size_t)m * 16 + j) * 12);
        float4 a = vp[0], b = vp[1], c = vp[2];
        vi[0] = a.x; vi[1] = a.y; vi[2] = a.z; vi[3] = a.w;
        vi[4] = b.x; vi[5] = b.y; vi[6] = b.z; vi[7] = b.w;
        vi[8] = c.x; vi[9] = c.y; vi[10] = c.z; vi[11] = c.w;
    }

    float gg[16];
    {
        const float4* gp = (const float4*)(g_gx + (size_t)idx * 32 + half * 16);
#pragma unroll
        for (int q = 0; q < 4; q++) {
            float4 v = gp[q];
            gg[4 * q] = v.x; gg[4 * q + 1] = v.y; gg[4 * q + 2] = v.z; gg[4 * q + 3] = v.w;
            *(float4*)&s_gf[wid][j][half * 16 + 4 * q] = v;
        }
    }
    float pe[16];
#pragma unroll
    for (int c16 = 0; c16 < 16; c16++) {
        int c = half * 16 + c16;
        float a = s_bpe[c];
        const float4* wr = (const float4*)&s_wpet[c * 12];
        float4 w0 = wr[0], w1v = wr[1], w2 = wr[2];
        a = fmaf(vi[0], w0.x, a); a = fmaf(vi[1], w0.y, a);
        a = fmaf(vi[2], w0.z, a); a = fmaf(vi[3], w0.w, a);
        a = fmaf(vi[4], w1v.x, a); a = fmaf(vi[5], w1v.y, a);
        a = fmaf(vi[6], w1v.z, a); a = fmaf(vi[7], w1v.w, a);
        a = fmaf(vi[8], w2.x, a); a = fmaf(vi[9], w2.y, a);
        a = fmaf(vi[10], w2.z, a); a = fmaf(vi[11], w2.w, a);
        float r = relu_f(a);
        pe[c16] = r;
        s_gf[wid][j][32 + c] = r;
    }

    float part[8];
#pragma unroll
    for (int h = 0; h < 8; h++) part[h] = 0.f;
#pragma unroll
    for (int c16 = 0; c16 < 16; c16++) {
        float v = gg[c16];
        const float4* wr = (const float4*)&s_wg1[(half * 16 + c16) * 8];
        float4 wa = wr[0], wb = wr[1];
        part[0] = fmaf(v, wa.x, part[0]); part[1] = fmaf(v, wa.y, part[1]);
        part[2] = fmaf(v, wa.z, part[2]); part[3] = fmaf(v, wa.w, part[3]);
        part[4] = fmaf(v, wb.x, part[4]); part[5] = fmaf(v, wb.y, part[5]);
        part[6] = fmaf(v, wb.z, part[6]); part[7] = fmaf(v, wb.w, part[7]);
    }
#pragma unroll
    for (int c16 = 0; c16 < 16; c16++) {
        float v = pe[c16];
        const float4* wr = (const float4*)&s_wg1[(32 + half * 16 + c16) * 8];
        float4 wa = wr[0], wb = wr[1];
        part[0] = fmaf(v, wa.x, part[0]); part[1] = fmaf(v, wa.y, part[1]);
        part[2] = fmaf(v, wa.z, part[2]); part[3] = fmaf(v, wa.w, part[3]);
        part[4] = fmaf(v, wb.x, part[4]); part[5] = fmaf(v, wb.y, part[5]);
        part[6] = fmaf(v, wb.z, part[6]); part[7] = fmaf(v, wb.w, part[7]);
    }
    __syncwarp();

    float mx0 = -3.0e38f, mx1 = -3.0e38f;
    int cl = lane;
#pragma unroll
    for (int jj = 0; jj < 16; jj++) {
        mx0 = fmaxf(mx0, s_gf[wid][jj][cl]);
        mx1 = fmaxf(mx1, s_gf[wid][jj][cl + 32]);
    }
    float mw[8];
    {
        const float4* wr0 = (const float4*)&s_wg1[cl * 8];
        const float4* wr1 = (const float4*)&s_wg1[(cl + 32) * 8];
        float4 a0 = wr0[0], a1 = wr0[1], b0 = wr1[0], b1v = wr1[1];
        mw[0] = fmaf(mx0, a0.x, mx1 * b0.x); mw[1] = fmaf(mx0, a0.y, mx1 * b0.y);
        mw[2] = fmaf(mx0, a0.z, mx1 * b0.z); mw[3] = fmaf(mx0, a0.w, mx1 * b0.w);
        mw[4] = fmaf(mx0, a1.x, mx1 * b1v.x); mw[5] = fmaf(mx0, a1.y, mx1 * b1v.y);
        mw[6] = fmaf(mx0, a1.z, mx1 * b1v.z); mw[7] = fmaf(mx0, a1.w, mx1 * b1v.w);
    }
#pragma unroll
    for (int s = 16; s >= 1; s >>= 1) {
#pragma unroll
        for (int h = 0; h < 8; h++) mw[h] += __shfl_xor_sync(FULL, mw[h], s);
    }
#pragma unroll
    for (int h = 0; h < 8; h++) part[h] += __shfl_xor_sync(FULL, part[h], 1);

    float s1v[8];
#pragma unroll
    for (int h = 0; h < 8; h++) s1v[h] = relu_f(part[h] - mw[h] + s_bg1[h]);
    float sc[8];
#pragma unroll
    for (int h2 = 0; h2 < 8; h2++) {
        float a = s_bg2[h2];
        const float4* wr = (const float4*)&s_wg2t[h2 * 8];
        float4 wa = wr[0], wb = wr[1];
        a = fmaf(s1v[0], wa.x, a); a = fmaf(s1v[1], wa.y, a);
        a = fmaf(s1v[2], wa.z, a); a = fmaf(s1v[3], wa.w, a);
        a = fmaf(s1v[4], wb.x, a); a = fmaf(s1v[5], wb.y, a);
        a = fmaf(s1v[6], wb.z, a); a = fmaf(s1v[7], wb.w, a);
        sc[h2] = 1.f / (1.f + __expf(-a));
    }

    float h1[8];
#pragma unroll
    for (int o = 0; o < 8; o++) {
        float a = s_bn1[o];
        const float4* wr = (const float4*)&s_wn1t[o * 12];
        float4 w0 = wr[0], w1v = wr[1], w2 = wr[2];
        a = fmaf(vi[0], w0.x, a); a = fmaf(vi[1], w0.y, a);
        a = fmaf(vi[2], w0.z, a); a = fmaf(vi[3], w0.w, a);
        a = fmaf(vi[4], w1v.x, a); a = fmaf(vi[5], w1v.y, a);
        a = fmaf(vi[6], w1v.z, a); a = fmaf(vi[7], w1v.w, a);
        a = fmaf(vi[8], w2.x, a); a = fmaf(vi[9], w2.y, a);
        a = fmaf(vi[10], w2.z, a); a = fmaf(vi[11], w2.w, a);
        h1[o] = relu_f(a);
    }
    float h2v[8];
#pragma unroll
    for (int o = 0; o < 8; o++) {
        float a = s_bn2[o];
        const float4* wr = (const float4*)&s_wn2t[o * 8];
        float4 wa = wr[0], wb = wr[1];
        a = fmaf(h1[0], wa.x, a); a = fmaf(h1[1], wa.y, a);
        a = fmaf(h1[2], wa.z, a); a = fmaf(h1[3], wa.w, a);
        a = fmaf(h1[4], wb.x, a); a = fmaf(h1[5], wb.y, a);
        a = fmaf(h1[6], wb.z, a); a = fmaf(h1[7], wb.w, a);
        h2v[o] = relu_f(a);
    }
#pragma unroll
    for (int oo = 0; oo < 8; oo++) {
        int o = half * 8 + oo;
        float a = s_bn3[o];
        const float4* wr = (const float4*)&s_wn3t[o * 8];
        float4 wa = wr[0], wb = wr[1];
        a = fmaf(h2v[0], wa.x, a); a = fmaf(h2v[1], wa.y, a);
        a = fmaf(h2v[2], wa.z, a); a = fmaf(h2v[3], wa.w, a);
        a = fmaf(h2v[4], wb.x, a); a = fmaf(h2v[5], wb.y, a);
        a = fmaf(h2v[6], wb.z, a); a = fmaf(h2v[7], wb.w, a);
        s_w[wid][j][o] = relu_f(a);
    }

    {
        const float4* fp = (const float4*)(g_fx + (size_t)idx * 32 + half * 16);
#pragma unroll
        for (int q = 0; q < 4; q++) {
            float4 v = fp[q];
            int c0 = half * 16 + 4 * q;
            float s = sc[c0 >> 2];
            *(float4*)&s_nf[wid][j][c0] = make_float4(v.x * s, v.y * s, v.z * s, v.w * s);
        }
    }

    {
        float m0 = -3.0e38f, m1 = -3.0e38f;
#pragma unroll
        for (int jj = 0; jj < 16; jj++) {
            int ix = __shfl_sync(FULL, idx, jj * 2);
            m0 = fmaxf(m0, __ldg(&df[(size_t)ix * 64 + lane]));
            m1 = fmaxf(m1, __ldg(&df[(size_t)ix * 64 + 32 + lane]));
        }
        g_sf[(size_t)m * 64 + lane] = m0;
        g_sf[(size_t)m * 64 + 32 + lane] = m1;
    }
    __syncwarp();

    float acc[16];
#pragma unroll
    for (int w = 0; w < 16; w++) acc[w] = 0.f;
    int c = lane;
#pragma unroll
    for (int jj = 0; jj < 16; jj++) {
        float a = s_nf[wid][jj][c];
        const float4* wp = (const float4*)&s_w[wid][jj][0];
        float4 w0 = wp[0], w1v = wp[1], w2 = wp[2], w3 = wp[3];
        acc[0] = fmaf(a, w0.x, acc[0]);  acc[1] = fmaf(a, w0.y, acc[1]);
        acc[2] = fmaf(a, w0.z, acc[2]);  acc[3] = fmaf(a, w0.w, acc[3]);
        acc[4] = fmaf(a, w1v.x, acc[4]); acc[5] = fmaf(a, w1v.y, acc[5]);
        acc[6] = fmaf(a, w1v.z, acc[6]); acc[7] = fmaf(a, w1v.w, acc[7]);
        acc[8] = fmaf(a, w2.x, acc[8]);  acc[9] = fmaf(a, w2.y, acc[9]);
        acc[10] = fmaf(a, w2.z, acc[10]); acc[11] = fmaf(a, w2.w, acc[11]);
        acc[12] = fmaf(a, w3.x, acc[12]); acc[13] = fmaf(a, w3.y, acc[13]);
        acc[14] = fmaf(a, w3.z, acc[14]); acc[15] = fmaf(a, w3.w, acc[15]);
    }
    __align__(16) __nv_bfloat16 hb[16];
    __align__(16) __nv_bfloat16 lb[16];
#pragma unroll
    for (int w = 0; w < 16; w++) {
        float v = acc[w];
        __nv_bfloat16 h = __float2bfloat16(v);
        hb[w] = h;
        lb[w] = __float2bfloat16(v - __bfloat162float(h));
    }
    size_t bo = (size_t)m * 512 + c * 16;
    ((uint4*)(g_aggh + bo))[0] = ((uint4*)hb)[0];
    ((uint4*)(g_aggh + bo))[1] = ((uint4*)hb)[1];
    ((uint4*)(g_aggl + bo))[0] = ((uint4*)lb)[0];
    ((uint4*)(g_aggl + bo))[1] = ((uint4*)lb)[1];
}

// ======================= K3: mma.sync GEMM + epilogue ======================
// 128 pts x 64 outs per block, 8 warps; warp = 16-row strip (acc 16x64).
// Split-bf16: D = Ah*Bh + Al*Bh + Ah*Bl (fp32 accum).
// smem rows padded to 144 B -> LDSM conflict-free.
#define K3_A_HI 0u
#define K3_A_LO 18432u
#define K3_B_HI 36864u
#define K3_B_LO 46080u
#define K3_SF   33280u              // epilogue: o[128][65] @0, sf[128][64] @33280
#define K3_SMEM 66048

__global__ void __launch_bounds__(256) k3_out(
    const float* __restrict__ blin,
    const float* __restrict__ wu2, const float* __restrict__ bu2,
    const float* __restrict__ wsc, const float* __restrict__ bsc,
    float* __restrict__ out) {
    extern __shared__ __align__(16) char dsm[];
    uint32_t sb = smem_u32(dsm);
    int t = threadIdx.x;
    int wid = t >> 5, lane = t & 31;
    int m0 = blockIdx.x * 128;
    int wm = wid * 16;

    float acc[8][4];
#pragma unroll
    for (int nt = 0; nt < 8; nt++)
#pragma unroll
        for (int q = 0; q < 4; q++) acc[nt][q] = 0.f;

    int qq = lane >> 3, rr = lane & 7;

#pragma unroll 1
    for (int kt = 0; kt < 8; kt++) {
        // stage A hi/lo: 128 rows x 64 bf16, row stride 144 B
#pragma unroll
        for (int q = 0; q < 4; q++) {
            int id = t + q * 256;
            int row = id >> 3, seg = id & 7;
            int gm = m0 + row; if (gm >= MPTS) gm = MPTS - 1;
            size_t go = (size_t)gm * 512 + kt * 64 + seg * 8;
            uint32_t so_ = (uint32_t)(row * 144 + seg * 16);
            *(uint4*)(dsm + K3_A_HI + so_) = *(const uint4*)(g_aggh + go);
            *(uint4*)(dsm + K3_A_LO + so_) = *(const uint4*)(g_aggl + go);
        }
        // stage B hi/lo: 64 rows x 64 bf16
#pragma unroll
        for (int q = 0; q < 2; q++) {
            int id = t + q * 256;
            int n = id >> 3, seg = id & 7;
            size_t go = (size_t)n * 512 + kt * 64 + seg * 8;
            uint32_t so_ = (uint32_t)(n * 144 + seg * 16);
            *(uint4*)(dsm + K3_B_HI + so_) = *(const uint4*)(g_bh + go);
            *(uint4*)(dsm + K3_B_LO + so_) = *(const uint4*)(g_bl + go);
        }
        __syncthreads();

#pragma unroll
        for (int ks = 0; ks < 4; ks++) {
            int k0 = ks * 16;
            uint32_t ah[4], al[4];
            {
                int row = wm + rr + (qq & 1) * 8;
                int col = k0 + (qq >> 1) * 8;
                uint32_t ad = sb + K3_A_HI + (uint32_t)(row * 144 + col * 2);
                ldsm4(ah, ad);
                ldsm4(al, ad + (K3_A_LO - K3_A_HI));
            }
#pragma unroll
            for (int p = 0; p < 4; p++) {
                uint32_t bh4[4], bl4[4];
                int noff = 16 * p + rr + (qq >> 1) * 8;
                int col = k0 + (qq & 1) * 8;
                uint32_t bd = sb + K3_B_HI + (uint32_t)(noff * 144 + col * 2);
                ldsm4(bh4, bd);
                ldsm4(bl4, bd + (K3_B_LO - K3_B_HI));
                mma16816(acc[2 * p], ah, bh4);
                mma16816(acc[2 * p + 1], ah, bh4 + 2);
                mma16816(acc[2 * p], al, bh4);
                mma16816(acc[2 * p + 1], al, bh4 + 2);
                mma16816(acc[2 * p], ah, bl4);
                mma16816(acc[2 * p + 1], ah, bl4 + 2);
            }
        }
        __syncthreads();
    }

    // acc -> o smem with bias + relu (overwrites A region; all MMA reads done)
    {
        int rrow = lane >> 2, cp = (lane & 3) * 2;
        float* so = (float*)dsm;
#pragma unroll
        for (int nt = 0; nt < 8; nt++) {
            int c0 = nt * 8 + cp;
            float b0v = __ldg(&blin[c0]), b1v = __ldg(&blin[c0 + 1]);
            so[(wm + rrow) * 65 + c0]       = relu_f(acc[nt][0] + b0v);
            so[(wm + rrow) * 65 + c0 + 1]   = relu_f(acc[nt][1] + b1v);
            so[(wm + rrow + 8) * 65 + c0]     = relu_f(acc[nt][2] + b0v);
            so[(wm + rrow + 8) * 65 + c0 + 1] = relu_f(acc[nt][3] + b1v);
        }
    }
    // stage sf
#pragma unroll
    for (int q = 0; q < 8; q++) {
        int id = t + q * 256;
        int pp = id >> 4, kk = (id & 15) * 4;
        int gm = m0 + pp; if (gm >= MPTS) gm = MPTS - 1;
        *(float4*)(dsm + K3_SF + (uint32_t)(pp * 64 + kk) * 4) =
            *(const float4*)(g_sf + (size_t)gm * 64 + kk);
    }
    __syncthreads();

    // epilogue: out128 = o @ wu2 + sf @ wsc + biases -> leaky(0.1); 8 pts x 8 ch
    const float* so = (const float*)dsm;
    const float* ssf = (const float*)(dsm + K3_SF);
    int r_ = t >> 4, cg = t & 15;
    int ob = cg * 8;
    float r8[8][8];
    {
        float4 ba = __ldg((const float4*)(bu2 + ob));
        float4 bb = __ldg((const float4*)(bu2 + ob + 4));
        float4 sa = __ldg((const float4*)(bsc + ob));
        float4 sbv = __ldg((const float4*)(bsc + ob + 4));
        float binit[8] = {ba.x + sa.x, ba.y + sa.y, ba.z + sa.z, ba.w + sa.w,
                          bb.x + sbv.x, bb.y + sbv.y, bb.z + sbv.z, bb.w + sbv.w};
#pragma unroll
        for (int i = 0; i < 8; i++)
#pragma unroll
            for (int q = 0; q < 8; q++) r8[i][q] = binit[q];
    }
#pragma unroll 4
    for (int k = 0; k < 64; k++) {
        float4 wa = __ldg((const float4*)(wu2 + (size_t)k * 128 + ob));
        float4 wb = __ldg((const float4*)(wu2 + (size_t)k * 128 + ob + 4));
        float4 va = __ldg((const float4*)(wsc + (size_t)k * 128 + ob));
        float4 vb = __ldg((const float4*)(wsc + (size_t)k * 128 + ob + 4));
#pragma unroll
        for (int i = 0; i < 8; i++) {
            float x = so[(r_ * 8 + i) * 65 + k];
            float s = ssf[(r_ * 8 + i) * 64 + k];
            r8[i][0] = fmaf(x, wa.x, r8[i][0]); r8[i][1] = fmaf(x, wa.y, r8[i][1]);
            r8[i][2] = fmaf(x, wa.z, r8[i][2]); r8[i][3] = fmaf(x, wa.w, r8[i][3]);
            r8[i][4] = fmaf(x, wb.x, r8[i][4]); r8[i][5] = fmaf(x, wb.y, r8[i][5]);
            r8[i][6] = fmaf(x, wb.z, r8[i][6]); r8[i][7] = fmaf(x, wb.w, r8[i][7]);
            r8[i][0] = fmaf(s, va.x, r8[i][0]); r8[i][1] = fmaf(s, va.y, r8[i][1]);
            r8[i][2] = fmaf(s, va.z, r8[i][2]); r8[i][3] = fmaf(s, va.w, r8[i][3]);
            r8[i][4] = fmaf(s, vb.x, r8[i][4]); r8[i][5] = fmaf(s, vb.y, r8[i][5]);
            r8[i][6] = fmaf(s, vb.z, r8[i][6]); r8[i][7] = fmaf(s, vb.w, r8[i][7]);
        }
    }
#pragma unroll
    for (int i = 0; i < 8; i++) {
        int m = m0 + r_ * 8 + i;
        if (m < MPTS) {
            float4* op = (float4*)(out + (size_t)m * 128 + ob);
            op[0] = make_float4(lrelu_f(r8[i][0]), lrelu_f(r8[i][1]), lrelu_f(r8[i][2]), lrelu_f(r8[i][3]));
            op[1] = make_float4(lrelu_f(r8[i][4]), lrelu_f(r8[i][5]), lrelu_f(r8[i][6]), lrelu_f(r8[i][7]));
        }
    }
}

// ======================= launch ============================================
extern "C" void kernel_launch(void* const* d_in, const int* in_sizes, int n_in,
                              void* d_out, int out_size) {
    const float* df  = (const float*)d_in[1];
    const float* vi  = (const float*)d_in[5];
    const int*   nei = (const int*)d_in[6];
    const float* w1  = (const float*)d_in[7];
    const float* b1  = (const float*)d_in[8];
    const float* wgu = (const float*)d_in[9];
    const float* bgu = (const float*)d_in[10];
    const float* wpe = (const float*)d_in[11];
    const float* bpe = (const float*)d_in[12];
    const float* wg1 = (const float*)d_in[13];
    const float* bg1 = (const float*)d_in[14];
    const float* wg2 = (const float*)d_in[15];
    const float* bg2 = (const float*)d_in[16];
    const float* wn1 = (const float*)d_in[17];
    const float* bn1 = (const float*)d_in[18];
    const float* wn2 = (const float*)d_in[19];
    const float* bn2 = (const float*)d_in[20];
    const float* wn3 = (const float*)d_in[21];
    const float* bn3 = (const float*)d_in[22];
    const float* wlin = (const float*)d_in[23];
    const float* blin = (const float*)d_in[24];
    const float* wu2 = (const float*)d_in[25];
    const float* bu2 = (const float*)d_in[26];
    const float* wsc = (const float*)d_in[27];
    const float* bsc = (const float*)d_in[28];
    float* out = (float*)d_out;

    cudaFuncSetAttribute(k3_out, cudaFuncAttributeMaxDynamicSharedMemorySize, K3_SMEM);

    k0_wconv<<<128, 256>>>(wlin);
    k1_dense<<<(NPTS + 127) / 128, 256>>>(df, w1, b1, wgu, bgu);
    k2_point<<<MPTS / 8, 256>>>(df, vi, nei,
                                wpe, bpe, wg1, bg1, wg2, bg2,
                                wn1, bn1, wn2, bn2, wn3, bn3);
    k3_out<<<(MPTS + 127) / 128, 256, K3_SMEM>>>(blin, wu2, bu2, wsc, bsc, out);
}

// round 6
// speedup vs baseline: 1.9267x; 1.2183x over previous
#include <cuda_runtime.h>
#include <cuda_bf16.h>
#include <math.h>
#include <stdint.h>

#define NPTS 200000
#define MPTS 100000

// ---------------- scratch (device globals: allocation-free rule) ----------
__device__ float g_fx[NPTS * 32];                     // feats_x     25.6 MB
__device__ float g_gx[NPTS * 32];                     // guidance_x  25.6 MB
__device__ __nv_bfloat16 g_aggh[(size_t)MPTS * 512];  // agg hi     102.4 MB
__device__ __nv_bfloat16 g_aggl[(size_t)MPTS * 512];  // agg lo     102.4 MB
__device__ __nv_bfloat16 g_oh[(size_t)MPTS * 64];     // o hi (relu'd mid)
__device__ __nv_bfloat16 g_ol[(size_t)MPTS * 64];     // o lo
__device__ __nv_bfloat16 g_sfh[(size_t)MPTS * 64];    // sf hi
__device__ __nv_bfloat16 g_sfl[(size_t)MPTS * 64];    // sf lo
__device__ __nv_bfloat16 g_bh[64 * 512];              // w_lin^T hi  [n][k]
__device__ __nv_bfloat16 g_bl[64 * 512];              // w_lin^T lo
__device__ __nv_bfloat16 g_b2h[128 * 128];            // [wu2;wsc]^T hi [n][k]
__device__ __nv_bfloat16 g_b2l[128 * 128];            // lo

__device__ __forceinline__ float relu_f(float x) { return x > 0.f ? x : 0.f; }
__device__ __forceinline__ float lrelu_f(float x) { return x > 0.f ? x : 0.1f * x; }

__device__ __forceinline__ uint32_t smem_u32(const void* p) {
    uint32_t a;
    asm("{ .reg .u64 t; cvta.to.shared.u64 t, %1; cvt.u32.u64 %0, t; }" : "=r"(a) : "l"(p));
    return a;
}
__device__ __forceinline__ void ldsm4(uint32_t* r, uint32_t a) {
    asm volatile("ldmatrix.sync.aligned.m8n8.x4.shared.b16 {%0,%1,%2,%3}, [%4];"
                 : "=r"(r[0]), "=r"(r[1]), "=r"(r[2]), "=r"(r[3]) : "r"(a));
}
__device__ __forceinline__ void mma16816(float* d, const uint32_t* a, const uint32_t* b) {
    asm volatile(
        "mma.sync.aligned.m16n8k16.row.col.f32.bf16.bf16.f32 "
        "{%0,%1,%2,%3}, {%4,%5,%6,%7}, {%8,%9}, {%0,%1,%2,%3};"
        : "+f"(d[0]), "+f"(d[1]), "+f"(d[2]), "+f"(d[3])
        : "r"(a[0]), "r"(a[1]), "r"(a[2]), "r"(a[3]), "r"(b[0]), "r"(b[1]));
}

// ======================= K0: weight conversions ============================
__global__ void __launch_bounds__(256) k0_wconv(
    const float* __restrict__ wlin, const float* __restrict__ wu2,
    const float* __restrict__ wsc) {
    int i = blockIdx.x * 256 + threadIdx.x;
    if (i < 512 * 64) {
        int n = i >> 9, k = i & 511;
        float v = __ldg(&wlin[k * 64 + n]);
        __nv_bfloat16 h = __float2bfloat16(v);
        g_bh[i] = h;
        g_bl[i] = __float2bfloat16(v - __bfloat162float(h));
    }
    if (i < 128 * 128) {
        int n = i >> 7, k = i & 127;
        float v = (k < 64) ? __ldg(&wu2[k * 128 + n]) : __ldg(&wsc[(k - 64) * 128 + n]);
        __nv_bfloat16 h = __float2bfloat16(v);
        g_b2h[i] = h;
        g_b2l[i] = __float2bfloat16(v - __bfloat162float(h));
    }
}

// ======================= K1: dense transform ==============================
__global__ void __launch_bounds__(256) k1_dense(
    const float* __restrict__ df,
    const float* __restrict__ w1, const float* __restrict__ b1,
    const float* __restrict__ wgu, const float* __restrict__ bgu) {
    __shared__ __align__(16) float s_w1[64 * 32];
    __shared__ __align__(16) float s_wgu[32 * 32];
    __shared__ union {
        float f[128][68];
        float fx[128][36];
    } u;
    int t = threadIdx.x;
    int p0 = blockIdx.x * 128;
    for (int i = t; i < 2048; i += 256) s_w1[i] = w1[i];
    for (int i = t; i < 1024; i += 256) s_wgu[i] = wgu[i];
#pragma unroll
    for (int q = 0; q < 8; q++) {
        int id = t + q * 256;
        int pp = id >> 4, kk = (id & 15) * 4;
        int gm = p0 + pp; if (gm >= NPTS) gm = NPTS - 1;
        *(float4*)&u.f[pp][kk] = *(const float4*)(df + (size_t)gm * 64 + kk);
    }
    __syncthreads();

    int pg = t >> 3, cg = t & 7;
    int c4 = cg * 4;
    float4 bb = *(const float4*)(b1 + c4);
    float acc[4][4];
#pragma unroll
    for (int i = 0; i < 4; i++) { acc[i][0] = bb.x; acc[i][1] = bb.y; acc[i][2] = bb.z; acc[i][3] = bb.w; }
#pragma unroll
    for (int kb = 0; kb < 64; kb += 4) {
        float4 a[4];
#pragma unroll
        for (int i = 0; i < 4; i++) a[i] = *(const float4*)&u.f[pg * 4 + i][kb];
#pragma unroll
        for (int q = 0; q < 4; q++) {
            float4 w = *(const float4*)&s_w1[(kb + q) * 32 + c4];
#pragma unroll
            for (int i = 0; i < 4; i++) {
                float av = q == 0 ? a[i].x : q == 1 ? a[i].y : q == 2 ? a[i].z : a[i].w;
                acc[i][0] = fmaf(av, w.x, acc[i][0]); acc[i][1] = fmaf(av, w.y, acc[i][1]);
                acc[i][2] = fmaf(av, w.z, acc[i][2]); acc[i][3] = fmaf(av, w.w, acc[i][3]);
            }
        }
    }
    float4 fxv[4];
#pragma unroll
    for (int i = 0; i < 4; i++)
        fxv[i] = make_float4(lrelu_f(acc[i][0]), lrelu_f(acc[i][1]), lrelu_f(acc[i][2]), lrelu_f(acc[i][3]));
    __syncthreads();
#pragma unroll
    for (int i = 0; i < 4; i++) {
        int gm = p0 + pg * 4 + i;
        *(float4*)&u.fx[pg * 4 + i][c4] = fxv[i];
        if (gm < NPTS) *(float4*)(g_fx + (size_t)gm * 32 + c4) = fxv[i];
    }
    __syncthreads();

    float4 bg = *(const float4*)(bgu + c4);
    float gac[4][4];
#pragma unroll
    for (int i = 0; i < 4; i++) { gac[i][0] = bg.x; gac[i][1] = bg.y; gac[i][2] = bg.z; gac[i][3] = bg.w; }
#pragma unroll
    for (int kb = 0; kb < 32; kb += 4) {
        float4 a[4];
#pragma unroll
        for (int i = 0; i < 4; i++) a[i] = *(const float4*)&u.fx[pg * 4 + i][kb];
#pragma unroll
        for (int q = 0; q < 4; q++) {
            float4 w = *(const float4*)&s_wgu[(kb + q) * 32 + c4];
#pragma unroll
            for (int i = 0; i < 4; i++) {
                float av = q == 0 ? a[i].x : q == 1 ? a[i].y : q == 2 ? a[i].z : a[i].w;
                gac[i][0] = fmaf(av, w.x, gac[i][0]); gac[i][1] = fmaf(av, w.y, gac[i][1]);
                gac[i][2] = fmaf(av, w.z, gac[i][2]); gac[i][3] = fmaf(av, w.w, gac[i][3]);
            }
        }
    }
#pragma unroll
    for (int i = 0; i < 4; i++) {
        int gm = p0 + pg * 4 + i;
        if (gm < NPTS)
            *(float4*)(g_gx + (size_t)gm * 32 + c4) =
                make_float4(gac[i][0], gac[i][1], gac[i][2], gac[i][3]);
    }
}

// ======================= K2: per-sparse-point pipeline =====================
__global__ void __launch_bounds__(256, 2) k2_point(
    const float* __restrict__ df,
    const float* __restrict__ vi_f,
    const int* __restrict__ nei,
    const float* __restrict__ wpe, const float* __restrict__ bpe,
    const float* __restrict__ wg1, const float* __restrict__ bg1,
    const float* __restrict__ wg2, const float* __restrict__ bg2,
    const float* __restrict__ wn1, const float* __restrict__ bn1,
    const float* __restrict__ wn2, const float* __restrict__ bn2,
    const float* __restrict__ wn3, const float* __restrict__ bn3) {
    __shared__ __align__(16) float s_wpet[32 * 12];
    __shared__ __align__(16) float s_wg1[64 * 8];
    __shared__ __align__(16) float s_wg2t[8 * 8];
    __shared__ __align__(16) float s_wn1t[8 * 12];
    __shared__ __align__(16) float s_wn2t[8 * 8];
    __shared__ __align__(16) float s_wn3t[16 * 8];
    __shared__ float s_bpe[32], s_bg1[8], s_bg2[8], s_bn1[8], s_bn2[8], s_bn3[16];
    __shared__ __align__(16) float s_gf[8][16][68];
    __shared__ __align__(16) float s_nf[8][16][36];
    __shared__ __align__(16) float s_w[8][16][20];
    int t = threadIdx.x;
    for (int i = t; i < 384; i += 256) { int c = i / 12, ii = i % 12; s_wpet[i] = wpe[ii * 32 + c]; }
    for (int i = t; i < 512; i += 256) s_wg1[i] = wg1[i];
    if (t < 64) s_wg2t[t] = wg2[(t & 7) * 8 + (t >> 3)];
    if (t < 96) { int o = t / 12, ii = t % 12; s_wn1t[t] = wn1[ii * 8 + o]; }
    if (t < 64) s_wn2t[t] = wn2[(t & 7) * 8 + (t >> 3)];
    if (t < 128) { int o = t >> 3, ii = t & 7; s_wn3t[t] = wn3[ii * 16 + o]; }
    if (t < 32) s_bpe[t] = bpe[t];
    if (t < 8) { s_bg1[t] = bg1[t]; s_bg2[t] = bg2[t]; s_bn1[t] = bn1[t]; s_bn2[t] = bn2[t]; }
    if (t < 16) s_bn3[t] = bn3[t];
    __syncthreads();

    const unsigned FULL = 0xffffffffu;
    int wid = t >> 5, lane = t & 31;
    int j = lane >> 1, half = lane & 1;
    int m = blockIdx.x * 8 + wid;
    int idx = __ldg(&nei[m * 16 + j]);

    float vi[12];
    {
        const float4* vp = (const float4*)(vi_f + ((size_t)m * 16 + j) * 12);
        float4 a = vp[0], b = vp[1], c = vp[2];
        vi[0] = a.x; vi[1] = a.y; vi[2] = a.z; vi[3] = a.w;
        vi[4] = b.x; vi[5] = b.y; vi[6] = b.z; vi[7] = b.w;
        vi[8] = c.x; vi[9] = c.y; vi[10] = c.z; vi[11] = c.w;
    }

    // gather half of guidance -> smem only (re-read later; saves 16 regs)
    {
        const float4* gp = (const float4*)(g_gx + (size_t)idx * 32 + half * 16);
#pragma unroll
        for (int q = 0; q < 4; q++)
            *(float4*)&s_gf[wid][j][half * 16 + 4 * q] = gp[q];
    }
    // compute half of PE (16 channels), keep in regs + smem
    float pe[16];
#pragma unroll
    for (int c16 = 0; c16 < 16; c16++) {
        int c = half * 16 + c16;
        float a = s_bpe[c];
        const float4* wr = (const float4*)&s_wpet[c * 12];
        float4 w0 = wr[0], w1v = wr[1], w2 = wr[2];
        a = fmaf(vi[0], w0.x, a); a = fmaf(vi[1], w0.y, a);
        a = fmaf(vi[2], w0.z, a); a = fmaf(vi[3], w0.w, a);
        a = fmaf(vi[4], w1v.x, a); a = fmaf(vi[5], w1v.y, a);
        a = fmaf(vi[6], w1v.z, a); a = fmaf(vi[7], w1v.w, a);
        a = fmaf(vi[8], w2.x, a); a = fmaf(vi[9], w2.y, a);
        a = fmaf(vi[10], w2.z, a); a = fmaf(vi[11], w2.w, a);
        float r = relu_f(a);
        pe[c16] = r;
        s_gf[wid][j][32 + c] = r;
    }

    float part[8];
#pragma unroll
    for (int h = 0; h < 8; h++) part[h] = 0.f;
#pragma unroll
    for (int q4 = 0; q4 < 4; q4++) {   // gathered guidance from smem
        float4 v4 = *(const float4*)&s_gf[wid][j][half * 16 + q4 * 4];
#pragma unroll
        for (int e = 0; e < 4; e++) {
            float v = e == 0 ? v4.x : e == 1 ? v4.y : e == 2 ? v4.z : v4.w;
            const float4* wr = (const float4*)&s_wg1[(half * 16 + q4 * 4 + e) * 8];
            float4 wa = wr[0], wb = wr[1];
            part[0] = fmaf(v, wa.x, part[0]); part[1] = fmaf(v, wa.y, part[1]);
            part[2] = fmaf(v, wa.z, part[2]); part[3] = fmaf(v, wa.w, part[3]);
            part[4] = fmaf(v, wb.x, part[4]); part[5] = fmaf(v, wb.y, part[5]);
            part[6] = fmaf(v, wb.z, part[6]); part[7] = fmaf(v, wb.w, part[7]);
        }
    }
#pragma unroll
    for (int c16 = 0; c16 < 16; c16++) {
        float v = pe[c16];
        const float4* wr = (const float4*)&s_wg1[(32 + half * 16 + c16) * 8];
        float4 wa = wr[0], wb = wr[1];
        part[0] = fmaf(v, wa.x, part[0]); part[1] = fmaf(v, wa.y, part[1]);
        part[2] = fmaf(v, wa.z, part[2]); part[3] = fmaf(v, wa.w, part[3]);
        part[4] = fmaf(v, wb.x, part[4]); part[5] = fmaf(v, wb.y, part[5]);
        part[6] = fmaf(v, wb.z, part[6]); part[7] = fmaf(v, wb.w, part[7]);
    }
    __syncwarp();

    float mx0 = -3.0e38f, mx1 = -3.0e38f;
    int cl = lane;
#pragma unroll
    for (int jj = 0; jj < 16; jj++) {
        mx0 = fmaxf(mx0, s_gf[wid][jj][cl]);
        mx1 = fmaxf(mx1, s_gf[wid][jj][cl + 32]);
    }
    float mw[8];
    {
        const float4* wr0 = (const float4*)&s_wg1[cl * 8];
        const float4* wr1 = (const float4*)&s_wg1[(cl + 32) * 8];
        float4 a0 = wr0[0], a1 = wr0[1], b0 = wr1[0], b1v = wr1[1];
        mw[0] = fmaf(mx0, a0.x, mx1 * b0.x); mw[1] = fmaf(mx0, a0.y, mx1 * b0.y);
        mw[2] = fmaf(mx0, a0.z, mx1 * b0.z); mw[3] = fmaf(mx0, a0.w, mx1 * b0.w);
        mw[4] = fmaf(mx0, a1.x, mx1 * b1v.x); mw[5] = fmaf(mx0, a1.y, mx1 * b1v.y);
        mw[6] = fmaf(mx0, a1.z, mx1 * b1v.z); mw[7] = fmaf(mx0, a1.w, mx1 * b1v.w);
    }
#pragma unroll
    for (int s = 16; s >= 1; s >>= 1) {
#pragma unroll
        for (int h = 0; h < 8; h++) mw[h] += __shfl_xor_sync(FULL, mw[h], s);
    }
#pragma unroll
    for (int h = 0; h < 8; h++) part[h] += __shfl_xor_sync(FULL, part[h], 1);

    float s1v[8];
#pragma unroll
    for (int h = 0; h < 8; h++) s1v[h] = relu_f(part[h] - mw[h] + s_bg1[h]);
    // only this lane's 4 heads needed (heads half*4 .. half*4+3)
    float sc4[4];
#pragma unroll
    for (int hq = 0; hq < 4; hq++) {
        int h2 = half * 4 + hq;
        float a = s_bg2[h2];
        const float4* wr = (const float4*)&s_wg2t[h2 * 8];
        float4 wa = wr[0], wb = wr[1];
        a = fmaf(s1v[0], wa.x, a); a = fmaf(s1v[1], wa.y, a);
        a = fmaf(s1v[2], wa.z, a); a = fmaf(s1v[3], wa.w, a);
        a = fmaf(s1v[4], wb.x, a); a = fmaf(s1v[5], wb.y, a);
        a = fmaf(s1v[6], wb.z, a); a = fmaf(s1v[7], wb.w, a);
        sc4[hq] = 1.f / (1.f + __expf(-a));
    }

    float h1[8];
#pragma unroll
    for (int o = 0; o < 8; o++) {
        float a = s_bn1[o];
        const float4* wr = (const float4*)&s_wn1t[o * 12];
        float4 w0 = wr[0], w1v = wr[1], w2 = wr[2];
        a = fmaf(vi[0], w0.x, a); a = fmaf(vi[1], w0.y, a);
        a = fmaf(vi[2], w0.z, a); a = fmaf(vi[3], w0.w, a);
        a = fmaf(vi[4], w1v.x, a); a = fmaf(vi[5], w1v.y, a);
        a = fmaf(vi[6], w1v.z, a); a = fmaf(vi[7], w1v.w, a);
        a = fmaf(vi[8], w2.x, a); a = fmaf(vi[9], w2.y, a);
        a = fmaf(vi[10], w2.z, a); a = fmaf(vi[11], w2.w, a);
        h1[o] = relu_f(a);
    }
    float h2v[8];
#pragma unroll
    for (int o = 0; o < 8; o++) {
        float a = s_bn2[o];
        const float4* wr = (const float4*)&s_wn2t[o * 8];
        float4 wa = wr[0], wb = wr[1];
        a = fmaf(h1[0], wa.x, a); a = fmaf(h1[1], wa.y, a);
        a = fmaf(h1[2], wa.z, a); a = fmaf(h1[3], wa.w, a);
        a = fmaf(h1[4], wb.x, a); a = fmaf(h1[5], wb.y, a);
        a = fmaf(h1[6], wb.z, a); a = fmaf(h1[7], wb.w, a);
        h2v[o] = relu_f(a);
    }
#pragma unroll
    for (int oo = 0; oo < 8; oo++) {
        int o = half * 8 + oo;
        float a = s_bn3[o];
        const float4* wr = (const float4*)&s_wn3t[o * 8];
        float4 wa = wr[0], wb = wr[1];
        a = fmaf(h2v[0], wa.x, a); a = fmaf(h2v[1], wa.y, a);
        a = fmaf(h2v[2], wa.z, a); a = fmaf(h2v[3], wa.w, a);
        a = fmaf(h2v[4], wb.x, a); a = fmaf(h2v[5], wb.y, a);
        a = fmaf(h2v[6], wb.z, a); a = fmaf(h2v[7], wb.w, a);
        s_w[wid][j][o] = relu_f(a);
    }

    {
        const float4* fp = (const float4*)(g_fx + (size_t)idx * 32 + half * 16);
#pragma unroll
        for (int q = 0; q < 4; q++) {
            float4 v = fp[q];
            int c0 = half * 16 + 4 * q;
            float s = sc4[q];
            *(float4*)&s_nf[wid][j][c0] = make_float4(v.x * s, v.y * s, v.z * s, v.w * s);
        }
    }

    // shortcut maxpool -> bf16 hi/lo
    {
        float m0v = -3.0e38f, m1v = -3.0e38f;
#pragma unroll
        for (int jj = 0; jj < 16; jj++) {
            int ix = __shfl_sync(FULL, idx, jj * 2);
            m0v = fmaxf(m0v, __ldg(&df[(size_t)ix * 64 + lane]));
            m1v = fmaxf(m1v, __ldg(&df[(size_t)ix * 64 + 32 + lane]));
        }
        __nv_bfloat16 h0 = __float2bfloat16(m0v);
        __nv_bfloat16 h1b = __float2bfloat16(m1v);
        g_sfh[(size_t)m * 64 + lane] = h0;
        g_sfl[(size_t)m * 64 + lane] = __float2bfloat16(m0v - __bfloat162float(h0));
        g_sfh[(size_t)m * 64 + 32 + lane] = h1b;
        g_sfl[(size_t)m * 64 + 32 + lane] = __float2bfloat16(m1v - __bfloat162float(h1b));
    }
    __syncwarp();

    float acc[16];
#pragma unroll
    for (int w = 0; w < 16; w++) acc[w] = 0.f;
    int c = lane;
#pragma unroll
    for (int jj = 0; jj < 16; jj++) {
        float a = s_nf[wid][jj][c];
        const float4* wp = (const float4*)&s_w[wid][jj][0];
        float4 w0 = wp[0], w1v = wp[1], w2 = wp[2], w3 = wp[3];
        acc[0] = fmaf(a, w0.x, acc[0]);  acc[1] = fmaf(a, w0.y, acc[1]);
        acc[2] = fmaf(a, w0.z, acc[2]);  acc[3] = fmaf(a, w0.w, acc[3]);
        acc[4] = fmaf(a, w1v.x, acc[4]); acc[5] = fmaf(a, w1v.y, acc[5]);
        acc[6] = fmaf(a, w1v.z, acc[6]); acc[7] = fmaf(a, w1v.w, acc[7]);
        acc[8] = fmaf(a, w2.x, acc[8]);  acc[9] = fmaf(a, w2.y, acc[9]);
        acc[10] = fmaf(a, w2.z, acc[10]); acc[11] = fmaf(a, w2.w, acc[11]);
        acc[12] = fmaf(a, w3.x, acc[12]); acc[13] = fmaf(a, w3.y, acc[13]);
        acc[14] = fmaf(a, w3.z, acc[14]); acc[15] = fmaf(a, w3.w, acc[15]);
    }
    __align__(16) __nv_bfloat16 hb[16];
    __align__(16) __nv_bfloat16 lb[16];
#pragma unroll
    for (int w = 0; w < 16; w++) {
        float v = acc[w];
        __nv_bfloat16 h = __float2bfloat16(v);
        hb[w] = h;
        lb[w] = __float2bfloat16(v - __bfloat162float(h));
    }
    size_t bo = (size_t)m * 512 + c * 16;
    ((uint4*)(g_aggh + bo))[0] = ((uint4*)hb)[0];
    ((uint4*)(g_aggh + bo))[1] = ((uint4*)hb)[1];
    ((uint4*)(g_aggl + bo))[0] = ((uint4*)lb)[0];
    ((uint4*)(g_aggl + bo))[1] = ((uint4*)lb)[1];
}

// ======================= K3: MMA GEMM1 -> o bf16 ===========================
// 128 pts x 64 outs, 8 warps, warp = 16-row strip.
#define K3_A_HI 0u
#define K3_A_LO 18432u
#define K3_B_HI 36864u
#define K3_B_LO 46080u
#define K3_SMEM 55296

__global__ void __launch_bounds__(256, 2) k3_out(const float* __restrict__ blin) {
    extern __shared__ __align__(16) char dsm[];
    uint32_t sb = smem_u32(dsm);
    int t = threadIdx.x;
    int wid = t >> 5, lane = t & 31;
    int m0 = blockIdx.x * 128;
    int wm = wid * 16;

    float acc[8][4];
#pragma unroll
    for (int nt = 0; nt < 8; nt++)
#pragma unroll
        for (int q = 0; q < 4; q++) acc[nt][q] = 0.f;

    int qq = lane >> 3, rr = lane & 7;

#pragma unroll 1
    for (int kt = 0; kt < 8; kt++) {
#pragma unroll
        for (int q = 0; q < 4; q++) {
            int id = t + q * 256;
            int row = id >> 3, seg = id & 7;
            int gm = m0 + row; if (gm >= MPTS) gm = MPTS - 1;
            size_t go = (size_t)gm * 512 + kt * 64 + seg * 8;
            uint32_t so_ = (uint32_t)(row * 144 + seg * 16);
            *(uint4*)(dsm + K3_A_HI + so_) = *(const uint4*)(g_aggh + go);
            *(uint4*)(dsm + K3_A_LO + so_) = *(const uint4*)(g_aggl + go);
        }
#pragma unroll
        for (int q = 0; q < 2; q++) {
            int id = t + q * 256;
            int n = id >> 3, seg = id & 7;
            size_t go = (size_t)n * 512 + kt * 64 + seg * 8;
            uint32_t so_ = (uint32_t)(n * 144 + seg * 16);
            *(uint4*)(dsm + K3_B_HI + so_) = *(const uint4*)(g_bh + go);
            *(uint4*)(dsm + K3_B_LO + so_) = *(const uint4*)(g_bl + go);
        }
        __syncthreads();

#pragma unroll
        for (int ks = 0; ks < 4; ks++) {
            int k0 = ks * 16;
            uint32_t ah[4], al[4];
            {
                int row = wm + rr + (qq & 1) * 8;
                int col = k0 + (qq >> 1) * 8;
                uint32_t ad = sb + K3_A_HI + (uint32_t)(row * 144 + col * 2);
                ldsm4(ah, ad);
                ldsm4(al, ad + (K3_A_LO - K3_A_HI));
            }
#pragma unroll
            for (int p = 0; p < 4; p++) {
                uint32_t bh4[4], bl4[4];
                int noff = 16 * p + rr + (qq >> 1) * 8;
                int col = k0 + (qq & 1) * 8;
                uint32_t bd = sb + K3_B_HI + (uint32_t)(noff * 144 + col * 2);
                ldsm4(bh4, bd);
                ldsm4(bl4, bd + (K3_B_LO - K3_B_HI));
                mma16816(acc[2 * p], ah, bh4);
                mma16816(acc[2 * p + 1], ah, bh4 + 2);
                mma16816(acc[2 * p], al, bh4);
                mma16816(acc[2 * p + 1], al, bh4 + 2);
                mma16816(acc[2 * p], ah, bl4);
                mma16816(acc[2 * p + 1], ah, bl4 + 2);
            }
        }
        __syncthreads();
    }

    // acc -> o smem f32 with bias + relu (reuses A region)
    {
        int rrow = lane >> 2, cp = (lane & 3) * 2;
        float* so = (float*)dsm;
#pragma unroll
        for (int nt = 0; nt < 8; nt++) {
            int c0 = nt * 8 + cp;
            float b0v = __ldg(&blin[c0]), b1v = __ldg(&blin[c0 + 1]);
            so[(wm + rrow) * 65 + c0]         = relu_f(acc[nt][0] + b0v);
            so[(wm + rrow) * 65 + c0 + 1]     = relu_f(acc[nt][1] + b1v);
            so[(wm + rrow + 8) * 65 + c0]     = relu_f(acc[nt][2] + b0v);
            so[(wm + rrow + 8) * 65 + c0 + 1] = relu_f(acc[nt][3] + b1v);
        }
    }
    __syncthreads();

    // convert o -> bf16 hi/lo, store coalesced
    const float* so = (const float*)dsm;
#pragma unroll
    for (int q = 0; q < 4; q++) {
        int id = t + q * 256;
        int row = id >> 3, c8 = (id & 7) * 8;
        int gm = m0 + row;
        if (gm < MPTS) {
            __align__(16) __nv_bfloat16 hb[8];
            __align__(16) __nv_bfloat16 lb[8];
#pragma unroll
            for (int i = 0; i < 8; i++) {
                float v = so[row * 65 + c8 + i];
                __nv_bfloat16 h = __float2bfloat16(v);
                hb[i] = h;
                lb[i] = __float2bfloat16(v - __bfloat162float(h));
            }
            *(uint4*)(g_oh + (size_t)gm * 64 + c8) = *(uint4*)hb;
            *(uint4*)(g_ol + (size_t)gm * 64 + c8) = *(uint4*)lb;
        }
    }
}

// ======================= K4: MMA GEMM2 + final epilogue ====================
// out[128p,128c] = leaky([o|sf] @ [wu2;wsc]^T + bu2 + bsc).
// A: kt=0 -> o hi/lo, kt=1 -> sf hi/lo (K=64 each). B: g_b2h/l [n=128][k=128].
#define K4_A_HI 0u
#define K4_A_LO 18432u
#define K4_B_HI 36864u
#define K4_B_LO 55296u
#define K4_SMEM 73728

__global__ void __launch_bounds__(256, 2) k4_out(
    const float* __restrict__ bu2, const float* __restrict__ bsc,
    float* __restrict__ out) {
    extern __shared__ __align__(16) char dsm[];
    uint32_t sb = smem_u32(dsm);
    int t = threadIdx.x;
    int wid = t >> 5, lane = t & 31;
    int m0 = blockIdx.x * 128;
    int wm = wid * 16;

    float acc[16][4];
#pragma unroll
    for (int nt = 0; nt < 16; nt++)
#pragma unroll
        for (int q = 0; q < 4; q++) acc[nt][q] = 0.f;

    int qq = lane >> 3, rr = lane & 7;

#pragma unroll 1
    for (int kt = 0; kt < 2; kt++) {
        const __nv_bfloat16* ah_src = kt ? g_sfh : g_oh;
        const __nv_bfloat16* al_src = kt ? g_sfl : g_ol;
#pragma unroll
        for (int q = 0; q < 4; q++) {
            int id = t + q * 256;
            int row = id >> 3, seg = id & 7;
            int gm = m0 + row; if (gm >= MPTS) gm = MPTS - 1;
            size_t go = (size_t)gm * 64 + seg * 8;
            uint32_t so_ = (uint32_t)(row * 144 + seg * 16);
            *(uint4*)(dsm + K4_A_HI + so_) = *(const uint4*)(ah_src + go);
            *(uint4*)(dsm + K4_A_LO + so_) = *(const uint4*)(al_src + go);
        }
#pragma unroll
        for (int q = 0; q < 4; q++) {
            int id = t + q * 256;
            int n = id >> 3, seg = id & 7;
            size_t go = (size_t)n * 128 + kt * 64 + seg * 8;
            uint32_t so_ = (uint32_t)(n * 144 + seg * 16);
            *(uint4*)(dsm + K4_B_HI + so_) = *(const uint4*)(g_b2h + go);
            *(uint4*)(dsm + K4_B_LO + so_) = *(const uint4*)(g_b2l + go);
        }
        __syncthreads();

#pragma unroll
        for (int ks = 0; ks < 4; ks++) {
            int k0 = ks * 16;
            uint32_t ah[4], al[4];
            {
                int row = wm + rr + (qq & 1) * 8;
                int col = k0 + (qq >> 1) * 8;
                uint32_t ad = sb + K4_A_HI + (uint32_t)(row * 144 + col * 2);
                ldsm4(ah, ad);
                ldsm4(al, ad + (K4_A_LO - K4_A_HI));
            }
#pragma unroll
            for (int p = 0; p < 8; p++) {
                uint32_t bh4[4], bl4[4];
                int noff = 16 * p + rr + (qq >> 1) * 8;
                int col = k0 + (qq & 1) * 8;
                uint32_t bd = sb + K4_B_HI + (uint32_t)(noff * 144 + col * 2);
                ldsm4(bh4, bd);
                ldsm4(bl4, bd + (K4_B_LO - K4_B_HI));
                mma16816(acc[2 * p], ah, bh4);
                mma16816(acc[2 * p + 1], ah, bh4 + 2);
                mma16816(acc[2 * p], al, bh4);
                mma16816(acc[2 * p + 1], al, bh4 + 2);
                mma16816(acc[2 * p], ah, bl4);
                mma16816(acc[2 * p + 1], ah, bl4 + 2);
            }
        }
        __syncthreads();
    }

    // epilogue: bias + leaky -> out (float2 per fragment pair)
    int r0 = lane >> 2, cp = (lane & 3) * 2;
    int mA = m0 + wm + r0, mB = mA + 8;
#pragma unroll
    for (int nt = 0; nt < 16; nt++) {
        int c0 = nt * 8 + cp;
        float b0v = __ldg(&bu2[c0]) + __ldg(&bsc[c0]);
        float b1v = __ldg(&bu2[c0 + 1]) + __ldg(&bsc[c0 + 1]);
        if (mA < MPTS)
            *(float2*)(out + (size_t)mA * 128 + c0) =
                make_float2(lrelu_f(acc[nt][0] + b0v), lrelu_f(acc[nt][1] + b1v));
        if (mB < MPTS)
            *(float2*)(out + (size_t)mB * 128 + c0) =
                make_float2(lrelu_f(acc[nt][2] + b0v), lrelu_f(acc[nt][3] + b1v));
    }
}

// ======================= launch ============================================
extern "C" void kernel_launch(void* const* d_in, const int* in_sizes, int n_in,
                              void* d_out, int out_size) {
    const float* df  = (const float*)d_in[1];
    const float* vi  = (const float*)d_in[5];
    const int*   nei = (const int*)d_in[6];
    const float* w1  = (const float*)d_in[7];
    const float* b1  = (const float*)d_in[8];
    const float* wgu = (const float*)d_in[9];
    const float* bgu = (const float*)d_in[10];
    const float* wpe = (const float*)d_in[11];
    const float* bpe = (const float*)d_in[12];
    const float* wg1 = (const float*)d_in[13];
    const float* bg1 = (const float*)d_in[14];
    const float* wg2 = (const float*)d_in[15];
    const float* bg2 = (const float*)d_in[16];
    const float* wn1 = (const float*)d_in[17];
    const float* bn1 = (const float*)d_in[18];
    const float* wn2 = (const float*)d_in[19];
    const float* bn2 = (const float*)d_in[20];
    const float* wn3 = (const float*)d_in[21];
    const float* bn3 = (const float*)d_in[22];
    const float* wlin = (const float*)d_in[23];
    const float* blin = (const float*)d_in[24];
    const float* wu2 = (const float*)d_in[25];
    const float* bu2 = (const float*)d_in[26];
    const float* wsc = (const float*)d_in[27];
    const float* bsc = (const float*)d_in[28];
    float* out = (float*)d_out;

    cudaFuncSetAttribute(k3_out, cudaFuncAttributeMaxDynamicSharedMemorySize, K3_SMEM);
    cudaFuncSetAttribute(k4_out, cudaFuncAttributeMaxDynamicSharedMemorySize, K4_SMEM);

    k0_wconv<<<128, 256>>>(wlin, wu2, wsc);
    k1_dense<<<(NPTS + 127) / 128, 256>>>(df, w1, b1, wgu, bgu);
    k2_point<<<MPTS / 8, 256>>>(df, vi, nei,
                                wpe, bpe, wg1, bg1, wg2, bg2,
                                wn1, bn1, wn2, bn2, wn3, bn3);
    k3_out<<<(MPTS + 127) / 128, 256, K3_SMEM>>>(blin);
    k4_out<<<(MPTS + 127) / 128, 256, K4_SMEM>>>(bu2, bsc, out);
}

// round 7
// speedup vs baseline: 1.9814x; 1.0284x over previous
#include <cuda_runtime.h>
#include <cuda_bf16.h>
#include <math.h>
#include <stdint.h>

#define NPTS 200000
#define MPTS 100000

// ---------------- scratch (device globals: allocation-free rule) ----------
__device__ float g_fx[NPTS * 32];                     // feats_x     25.6 MB
__device__ float g_gx[NPTS * 32];                     // guidance_x  25.6 MB
__device__ float g_gw1[NPTS * 8];                     // guidance@W1lo 6.4 MB
__device__ __nv_bfloat16 g_aggh[(size_t)MPTS * 512];  // agg hi     102.4 MB
__device__ __nv_bfloat16 g_aggl[(size_t)MPTS * 512];  // agg lo     102.4 MB
__device__ __nv_bfloat16 g_oh[(size_t)MPTS * 64];     // o hi (relu'd mid)
__device__ __nv_bfloat16 g_ol[(size_t)MPTS * 64];     // o lo
__device__ __nv_bfloat16 g_sfh[(size_t)MPTS * 64];    // sf hi
__device__ __nv_bfloat16 g_sfl[(size_t)MPTS * 64];    // sf lo
__device__ __nv_bfloat16 g_bh[64 * 512];              // w_lin^T hi  [n][k]
__device__ __nv_bfloat16 g_bl[64 * 512];              // w_lin^T lo
__device__ __nv_bfloat16 g_b2h[128 * 128];            // [wu2;wsc]^T hi [n][k]
__device__ __nv_bfloat16 g_b2l[128 * 128];            // lo

__device__ __forceinline__ float relu_f(float x) { return x > 0.f ? x : 0.f; }
__device__ __forceinline__ float lrelu_f(float x) { return x > 0.f ? x : 0.1f * x; }

__device__ __forceinline__ uint32_t smem_u32(const void* p) {
    uint32_t a;
    asm("{ .reg .u64 t; cvta.to.shared.u64 t, %1; cvt.u32.u64 %0, t; }" : "=r"(a) : "l"(p));
    return a;
}
__device__ __forceinline__ void ldsm4(uint32_t* r, uint32_t a) {
    asm volatile("ldmatrix.sync.aligned.m8n8.x4.shared.b16 {%0,%1,%2,%3}, [%4];"
                 : "=r"(r[0]), "=r"(r[1]), "=r"(r[2]), "=r"(r[3]) : "r"(a));
}
__device__ __forceinline__ void mma16816(float* d, const uint32_t* a, const uint32_t* b) {
    asm volatile(
        "mma.sync.aligned.m16n8k16.row.col.f32.bf16.bf16.f32 "
        "{%0,%1,%2,%3}, {%4,%5,%6,%7}, {%8,%9}, {%0,%1,%2,%3};"
        : "+f"(d[0]), "+f"(d[1]), "+f"(d[2]), "+f"(d[3])
        : "r"(a[0]), "r"(a[1]), "r"(a[2]), "r"(a[3]), "r"(b[0]), "r"(b[1]));
}
__device__ __forceinline__ void cp16(uint32_t dst, const void* src) {
    asm volatile("cp.async.cg.shared.global [%0], [%1], 16;" :: "r"(dst), "l"(src));
}
#define CP_COMMIT() asm volatile("cp.async.commit_group;" ::: "memory")
#define CP_WAIT1() asm volatile("cp.async.wait_group 1;" ::: "memory")
#define CP_WAIT0() asm volatile("cp.async.wait_group 0;" ::: "memory")

// ======================= K0: weight conversions ============================
__global__ void __launch_bounds__(256) k0_wconv(
    const float* __restrict__ wlin, const float* __restrict__ wu2,
    const float* __restrict__ wsc) {
    int i = blockIdx.x * 256 + threadIdx.x;
    if (i < 512 * 64) {
        int n = i >> 9, k = i & 511;
        float v = __ldg(&wlin[k * 64 + n]);
        __nv_bfloat16 h = __float2bfloat16(v);
        g_bh[i] = h;
        g_bl[i] = __float2bfloat16(v - __bfloat162float(h));
    }
    if (i < 128 * 128) {
        int n = i >> 7, k = i & 127;
        float v = (k < 64) ? __ldg(&wu2[k * 128 + n]) : __ldg(&wsc[(k - 64) * 128 + n]);
        __nv_bfloat16 h = __float2bfloat16(v);
        g_b2h[i] = h;
        g_b2l[i] = __float2bfloat16(v - __bfloat162float(h));
    }
}

// ======================= K1: dense transform + gw1 =========================
__global__ void __launch_bounds__(256) k1_dense(
    const float* __restrict__ df,
    const float* __restrict__ w1, const float* __restrict__ b1,
    const float* __restrict__ wgu, const float* __restrict__ bgu,
    const float* __restrict__ wg1) {
    __shared__ __align__(16) float s_w1[64 * 32];
    __shared__ __align__(16) float s_wgu[32 * 32];
    __shared__ __align__(16) float s_wg1k[32 * 8];   // W1 rows 0..31
    __shared__ union {
        float f[128][68];
        float fx[128][36];
    } u;
    int t = threadIdx.x;
    int p0 = blockIdx.x * 128;
    for (int i = t; i < 2048; i += 256) s_w1[i] = w1[i];
    for (int i = t; i < 1024; i += 256) s_wgu[i] = wgu[i];
    if (t < 256) s_wg1k[t] = wg1[t];
#pragma unroll
    for (int q = 0; q < 8; q++) {
        int id = t + q * 256;
        int pp = id >> 4, kk = (id & 15) * 4;
        int gm = p0 + pp; if (gm >= NPTS) gm = NPTS - 1;
        *(float4*)&u.f[pp][kk] = *(const float4*)(df + (size_t)gm * 64 + kk);
    }
    __syncthreads();

    int pg = t >> 3, cg = t & 7;
    int c4 = cg * 4;
    float4 bb = *(const float4*)(b1 + c4);
    float acc[4][4];
#pragma unroll
    for (int i = 0; i < 4; i++) { acc[i][0] = bb.x; acc[i][1] = bb.y; acc[i][2] = bb.z; acc[i][3] = bb.w; }
#pragma unroll
    for (int kb = 0; kb < 64; kb += 4) {
        float4 a[4];
#pragma unroll
        for (int i = 0; i < 4; i++) a[i] = *(const float4*)&u.f[pg * 4 + i][kb];
#pragma unroll
        for (int q = 0; q < 4; q++) {
            float4 w = *(const float4*)&s_w1[(kb + q) * 32 + c4];
#pragma unroll
            for (int i = 0; i < 4; i++) {
                float av = q == 0 ? a[i].x : q == 1 ? a[i].y : q == 2 ? a[i].z : a[i].w;
                acc[i][0] = fmaf(av, w.x, acc[i][0]); acc[i][1] = fmaf(av, w.y, acc[i][1]);
                acc[i][2] = fmaf(av, w.z, acc[i][2]); acc[i][3] = fmaf(av, w.w, acc[i][3]);
            }
        }
    }
    float4 fxv[4];
#pragma unroll
    for (int i = 0; i < 4; i++)
        fxv[i] = make_float4(lrelu_f(acc[i][0]), lrelu_f(acc[i][1]), lrelu_f(acc[i][2]), lrelu_f(acc[i][3]));
    __syncthreads();
#pragma unroll
    for (int i = 0; i < 4; i++) {
        int gm = p0 + pg * 4 + i;
        *(float4*)&u.fx[pg * 4 + i][c4] = fxv[i];
        if (gm < NPTS) *(float4*)(g_fx + (size_t)gm * 32 + c4) = fxv[i];
    }
    __syncthreads();

    float4 bg = *(const float4*)(bgu + c4);
    float gac[4][4];
#pragma unroll
    for (int i = 0; i < 4; i++) { gac[i][0] = bg.x; gac[i][1] = bg.y; gac[i][2] = bg.z; gac[i][3] = bg.w; }
#pragma unroll
    for (int kb = 0; kb < 32; kb += 4) {
        float4 a[4];
#pragma unroll
        for (int i = 0; i < 4; i++) a[i] = *(const float4*)&u.fx[pg * 4 + i][kb];
#pragma unroll
        for (int q = 0; q < 4; q++) {
            float4 w = *(const float4*)&s_wgu[(kb + q) * 32 + c4];
#pragma unroll
            for (int i = 0; i < 4; i++) {
                float av = q == 0 ? a[i].x : q == 1 ? a[i].y : q == 2 ? a[i].z : a[i].w;
                gac[i][0] = fmaf(av, w.x, gac[i][0]); gac[i][1] = fmaf(av, w.y, gac[i][1]);
                gac[i][2] = fmaf(av, w.z, gac[i][2]); gac[i][3] = fmaf(av, w.w, gac[i][3]);
            }
        }
    }
    __syncthreads();   // all reads of u.fx (feats_x) done
#pragma unroll
    for (int i = 0; i < 4; i++) {
        int gm = p0 + pg * 4 + i;
        *(float4*)&u.fx[pg * 4 + i][c4] =
            make_float4(gac[i][0], gac[i][1], gac[i][2], gac[i][3]);
        if (gm < NPTS)
            *(float4*)(g_gx + (size_t)gm * 32 + c4) =
                make_float4(gac[i][0], gac[i][1], gac[i][2], gac[i][3]);
    }
    __syncthreads();

    // gw1: thread = (point p2 = t>>1, half of 8 outs)
    {
        int p2 = t >> 1, h4 = (t & 1) * 4;
        float o4[4] = {0.f, 0.f, 0.f, 0.f};
#pragma unroll
        for (int c = 0; c < 32; c++) {
            float g = u.fx[p2][c];
            float4 w = *(const float4*)&s_wg1k[c * 8 + h4];
            o4[0] = fmaf(g, w.x, o4[0]); o4[1] = fmaf(g, w.y, o4[1]);
            o4[2] = fmaf(g, w.z, o4[2]); o4[3] = fmaf(g, w.w, o4[3]);
        }
        int gm = p0 + p2;
        if (gm < NPTS)
            *(float4*)(g_gw1 + (size_t)gm * 8 + h4) = make_float4(o4[0], o4[1], o4[2], o4[3]);
    }
}

// ======================= K2: per-sparse-point pipeline =====================
__global__ void __launch_bounds__(256, 3) k2_point(
    const float* __restrict__ df,
    const float* __restrict__ vi_f,
    const int* __restrict__ nei,
    const float* __restrict__ wpe, const float* __restrict__ bpe,
    const float* __restrict__ wg1, const float* __restrict__ bg1,
    const float* __restrict__ wg2, const float* __restrict__ bg2,
    const float* __restrict__ wn1, const float* __restrict__ bn1,
    const float* __restrict__ wn2, const float* __restrict__ bn2,
    const float* __restrict__ wn3, const float* __restrict__ bn3) {
    __shared__ __align__(16) float s_wpet[32 * 12];
    __shared__ __align__(16) float s_wg1[64 * 8];
    __shared__ __align__(16) float s_wg2t[8 * 8];
    __shared__ __align__(16) float s_wn1t[8 * 12];
    __shared__ __align__(16) float s_wn2t[8 * 8];
    __shared__ __align__(16) float s_wn3t[16 * 8];
    __shared__ float s_bpe[32], s_bg1[8], s_bg2[8], s_bn1[8], s_bn2[8], s_bn3[16];
    __shared__ __align__(16) float s_gf[8][16][68];
    __shared__ __align__(16) float s_nf[8][16][36];
    __shared__ __align__(16) float s_w[8][16][20];
    int t = threadIdx.x;
    for (int i = t; i < 384; i += 256) { int c = i / 12, ii = i % 12; s_wpet[i] = wpe[ii * 32 + c]; }
    for (int i = t; i < 512; i += 256) s_wg1[i] = wg1[i];
    if (t < 64) s_wg2t[t] = wg2[(t & 7) * 8 + (t >> 3)];
    if (t < 96) { int o = t / 12, ii = t % 12; s_wn1t[t] = wn1[ii * 8 + o]; }
    if (t < 64) s_wn2t[t] = wn2[(t & 7) * 8 + (t >> 3)];
    if (t < 128) { int o = t >> 3, ii = t & 7; s_wn3t[t] = wn3[ii * 16 + o]; }
    if (t < 32) s_bpe[t] = bpe[t];
    if (t < 8) { s_bg1[t] = bg1[t]; s_bg2[t] = bg2[t]; s_bn1[t] = bn1[t]; s_bn2[t] = bn2[t]; }
    if (t < 16) s_bn3[t] = bn3[t];
    __syncthreads();

    const unsigned FULL = 0xffffffffu;
    int wid = t >> 5, lane = t & 31;
    int j = lane >> 1, half = lane & 1;
    int m = blockIdx.x * 8 + wid;
    int idx = __ldg(&nei[m * 16 + j]);

    float vi[12];
    {
        const float4* vp = (const float4*)(vi_f + ((size_t)m * 16 + j) * 12);
        float4 a = vp[0], b = vp[1], c = vp[2];
        vi[0] = a.x; vi[1] = a.y; vi[2] = a.z; vi[3] = a.w;
        vi[4] = b.x; vi[5] = b.y; vi[6] = b.z; vi[7] = b.w;
        vi[8] = c.x; vi[9] = c.y; vi[10] = c.z; vi[11] = c.w;
    }

    // part init: half==0 lane adds precomputed gathered-guidance @ W1lo
    float part[8];
    if (half == 0) {
        float4 a0 = __ldg((const float4*)(g_gw1 + (size_t)idx * 8));
        float4 a1 = __ldg((const float4*)(g_gw1 + (size_t)idx * 8 + 4));
        part[0] = a0.x; part[1] = a0.y; part[2] = a0.z; part[3] = a0.w;
        part[4] = a1.x; part[5] = a1.y; part[6] = a1.z; part[7] = a1.w;
    } else {
#pragma unroll
        for (int h = 0; h < 8; h++) part[h] = 0.f;
    }

    // gather half of guidance -> smem (for channel max)
    {
        const float4* gp = (const float4*)(g_gx + (size_t)idx * 32 + half * 16);
#pragma unroll
        for (int q = 0; q < 4; q++)
            *(float4*)&s_gf[wid][j][half * 16 + 4 * q] = gp[q];
    }
    // compute half of PE (16 channels)
    float pe[16];
#pragma unroll
    for (int c16 = 0; c16 < 16; c16++) {
        int c = half * 16 + c16;
        float a = s_bpe[c];
        const float4* wr = (const float4*)&s_wpet[c * 12];
        float4 w0 = wr[0], w1v = wr[1], w2 = wr[2];
        a = fmaf(vi[0], w0.x, a); a = fmaf(vi[1], w0.y, a);
        a = fmaf(vi[2], w0.z, a); a = fmaf(vi[3], w0.w, a);
        a = fmaf(vi[4], w1v.x, a); a = fmaf(vi[5], w1v.y, a);
        a = fmaf(vi[6], w1v.z, a); a = fmaf(vi[7], w1v.w, a);
        a = fmaf(vi[8], w2.x, a); a = fmaf(vi[9], w2.y, a);
        a = fmaf(vi[10], w2.z, a); a = fmaf(vi[11], w2.w, a);
        float r = relu_f(a);
        pe[c16] = r;
        s_gf[wid][j][32 + c] = r;
    }

#pragma unroll
    for (int c16 = 0; c16 < 16; c16++) {   // PE contribution through W1hi
        float v = pe[c16];
        const float4* wr = (const float4*)&s_wg1[(32 + half * 16 + c16) * 8];
        float4 wa = wr[0], wb = wr[1];
        part[0] = fmaf(v, wa.x, part[0]); part[1] = fmaf(v, wa.y, part[1]);
        part[2] = fmaf(v, wa.z, part[2]); part[3] = fmaf(v, wa.w, part[3]);
        part[4] = fmaf(v, wb.x, part[4]); part[5] = fmaf(v, wb.y, part[5]);
        part[6] = fmaf(v, wb.z, part[6]); part[7] = fmaf(v, wb.w, part[7]);
    }
    __syncwarp();

    float mx0 = -3.0e38f, mx1 = -3.0e38f;
    int cl = lane;
#pragma unroll
    for (int jj = 0; jj < 16; jj++) {
        mx0 = fmaxf(mx0, s_gf[wid][jj][cl]);
        mx1 = fmaxf(mx1, s_gf[wid][jj][cl + 32]);
    }
    float mw[8];
    {
        const float4* wr0 = (const float4*)&s_wg1[cl * 8];
        const float4* wr1 = (const float4*)&s_wg1[(cl + 32) * 8];
        float4 a0 = wr0[0], a1 = wr0[1], b0 = wr1[0], b1v = wr1[1];
        mw[0] = fmaf(mx0, a0.x, mx1 * b0.x); mw[1] = fmaf(mx0, a0.y, mx1 * b0.y);
        mw[2] = fmaf(mx0, a0.z, mx1 * b0.z); mw[3] = fmaf(mx0, a0.w, mx1 * b0.w);
        mw[4] = fmaf(mx0, a1.x, mx1 * b1v.x); mw[5] = fmaf(mx0, a1.y, mx1 * b1v.y);
        mw[6] = fmaf(mx0, a1.z, mx1 * b1v.z); mw[7] = fmaf(mx0, a1.w, mx1 * b1v.w);
    }
#pragma unroll
    for (int s = 16; s >= 1; s >>= 1) {
#pragma unroll
        for (int h = 0; h < 8; h++) mw[h] += __shfl_xor_sync(FULL, mw[h], s);
    }
#pragma unroll
    for (int h = 0; h < 8; h++) part[h] += __shfl_xor_sync(FULL, part[h], 1);

    float s1v[8];
#pragma unroll
    for (int h = 0; h < 8; h++) s1v[h] = relu_f(part[h] - mw[h] + s_bg1[h]);
    float sc4[4];
#pragma unroll
    for (int hq = 0; hq < 4; hq++) {
        int h2 = half * 4 + hq;
        float a = s_bg2[h2];
        const float4* wr = (const float4*)&s_wg2t[h2 * 8];
        float4 wa = wr[0], wb = wr[1];
        a = fmaf(s1v[0], wa.x, a); a = fmaf(s1v[1], wa.y, a);
        a = fmaf(s1v[2], wa.z, a); a = fmaf(s1v[3], wa.w, a);
        a = fmaf(s1v[4], wb.x, a); a = fmaf(s1v[5], wb.y, a);
        a = fmaf(s1v[6], wb.z, a); a = fmaf(s1v[7], wb.w, a);
        sc4[hq] = 1.f / (1.f + __expf(-a));
    }

    float h1[8];
#pragma unroll
    for (int o = 0; o < 8; o++) {
        float a = s_bn1[o];
        const float4* wr = (const float4*)&s_wn1t[o * 12];
        float4 w0 = wr[0], w1v = wr[1], w2 = wr[2];
        a = fmaf(vi[0], w0.x, a); a = fmaf(vi[1], w0.y, a);
        a = fmaf(vi[2], w0.z, a); a = fmaf(vi[3], w0.w, a);
        a = fmaf(vi[4], w1v.x, a); a = fmaf(vi[5], w1v.y, a);
        a = fmaf(vi[6], w1v.z, a); a = fmaf(vi[7], w1v.w, a);
        a = fmaf(vi[8], w2.x, a); a = fmaf(vi[9], w2.y, a);
        a = fmaf(vi[10], w2.z, a); a = fmaf(vi[11], w2.w, a);
        h1[o] = relu_f(a);
    }
    float h2v[8];
#pragma unroll
    for (int o = 0; o < 8; o++) {
        float a = s_bn2[o];
        const float4* wr = (const float4*)&s_wn2t[o * 8];
        float4 wa = wr[0], wb = wr[1];
        a = fmaf(h1[0], wa.x, a); a = fmaf(h1[1], wa.y, a);
        a = fmaf(h1[2], wa.z, a); a = fmaf(h1[3], wa.w, a);
        a = fmaf(h1[4], wb.x, a); a = fmaf(h1[5], wb.y, a);
        a = fmaf(h1[6], wb.z, a); a = fmaf(h1[7], wb.w, a);
        h2v[o] = relu_f(a);
    }
#pragma unroll
    for (int oo = 0; oo < 8; oo++) {
        int o = half * 8 + oo;
        float a = s_bn3[o];
        const float4* wr = (const float4*)&s_wn3t[o * 8];
        float4 wa = wr[0], wb = wr[1];
        a = fmaf(h2v[0], wa.x, a); a = fmaf(h2v[1], wa.y, a);
        a = fmaf(h2v[2], wa.z, a); a = fmaf(h2v[3], wa.w, a);
        a = fmaf(h2v[4], wb.x, a); a = fmaf(h2v[5], wb.y, a);
        a = fmaf(h2v[6], wb.z, a); a = fmaf(h2v[7], wb.w, a);
        s_w[wid][j][o] = relu_f(a);
    }

    {
        const float4* fp = (const float4*)(g_fx + (size_t)idx * 32 + half * 16);
#pragma unroll
        for (int q = 0; q < 4; q++) {
            float4 v = fp[q];
            int c0 = half * 16 + 4 * q;
            float s = sc4[q];
            *(float4*)&s_nf[wid][j][c0] = make_float4(v.x * s, v.y * s, v.z * s, v.w * s);
        }
    }

    // shortcut maxpool -> bf16 hi/lo
    {
        float m0v = -3.0e38f, m1v = -3.0e38f;
#pragma unroll
        for (int jj = 0; jj < 16; jj++) {
            int ix = __shfl_sync(FULL, idx, jj * 2);
            m0v = fmaxf(m0v, __ldg(&df[(size_t)ix * 64 + lane]));
            m1v = fmaxf(m1v, __ldg(&df[(size_t)ix * 64 + 32 + lane]));
        }
        __nv_bfloat16 h0 = __float2bfloat16(m0v);
        __nv_bfloat16 h1b = __float2bfloat16(m1v);
        g_sfh[(size_t)m * 64 + lane] = h0;
        g_sfl[(size_t)m * 64 + lane] = __float2bfloat16(m0v - __bfloat162float(h0));
        g_sfh[(size_t)m * 64 + 32 + lane] = h1b;
        g_sfl[(size_t)m * 64 + 32 + lane] = __float2bfloat16(m1v - __bfloat162float(h1b));
    }
    __syncwarp();

    float acc[16];
#pragma unroll
    for (int w = 0; w < 16; w++) acc[w] = 0.f;
    int c = lane;
#pragma unroll
    for (int jj = 0; jj < 16; jj++) {
        float a = s_nf[wid][jj][c];
        const float4* wp = (const float4*)&s_w[wid][jj][0];
        float4 w0 = wp[0], w1v = wp[1], w2 = wp[2], w3 = wp[3];
        acc[0] = fmaf(a, w0.x, acc[0]);  acc[1] = fmaf(a, w0.y, acc[1]);
        acc[2] = fmaf(a, w0.z, acc[2]);  acc[3] = fmaf(a, w0.w, acc[3]);
        acc[4] = fmaf(a, w1v.x, acc[4]); acc[5] = fmaf(a, w1v.y, acc[5]);
        acc[6] = fmaf(a, w1v.z, acc[6]); acc[7] = fmaf(a, w1v.w, acc[7]);
        acc[8] = fmaf(a, w2.x, acc[8]);  acc[9] = fmaf(a, w2.y, acc[9]);
        acc[10] = fmaf(a, w2.z, acc[10]); acc[11] = fmaf(a, w2.w, acc[11]);
        acc[12] = fmaf(a, w3.x, acc[12]); acc[13] = fmaf(a, w3.y, acc[13]);
        acc[14] = fmaf(a, w3.z, acc[14]); acc[15] = fmaf(a, w3.w, acc[15]);
    }
    __align__(16) __nv_bfloat16 hb[16];
    __align__(16) __nv_bfloat16 lb[16];
#pragma unroll
    for (int w = 0; w < 16; w++) {
        float v = acc[w];
        __nv_bfloat16 h = __float2bfloat16(v);
        hb[w] = h;
        lb[w] = __float2bfloat16(v - __bfloat162float(h));
    }
    size_t bo = (size_t)m * 512 + c * 16;
    ((uint4*)(g_aggh + bo))[0] = ((uint4*)hb)[0];
    ((uint4*)(g_aggh + bo))[1] = ((uint4*)hb)[1];
    ((uint4*)(g_aggl + bo))[0] = ((uint4*)lb)[0];
    ((uint4*)(g_aggl + bo))[1] = ((uint4*)lb)[1];
}

// ======================= K3: pipelined MMA GEMM1 -> o bf16 =================
// 128 pts x 64 outs, 8 warps; 2-stage cp.async pipeline over 8 K-tiles.
#define K3_A_HI 0u          // 2 stages x 18432
#define K3_A_LO 36864u      // 2 stages x 18432
#define K3_B_HI 73728u      // 2 stages x 9216
#define K3_B_LO 92160u      // 2 stages x 9216
#define K3_SMEM 110592

__device__ __forceinline__ void k3_load(uint32_t sb, char* dsm, int t, int m0,
                                        int kt, int st) {
    uint32_t aofs = (uint32_t)st * 18432u;
    uint32_t bofs = (uint32_t)st * 9216u;
#pragma unroll
    for (int q = 0; q < 4; q++) {
        int id = t + q * 256;
        int row = id >> 3, seg = id & 7;
        int gm = m0 + row; if (gm >= MPTS) gm = MPTS - 1;
        size_t go = (size_t)gm * 512 + kt * 64 + seg * 8;
        uint32_t so_ = (uint32_t)(row * 144 + seg * 16);
        cp16(sb + K3_A_HI + aofs + so_, g_aggh + go);
        cp16(sb + K3_A_LO + aofs + so_, g_aggl + go);
    }
#pragma unroll
    for (int q = 0; q < 2; q++) {
        int id = t + q * 256;
        int n = id >> 3, seg = id & 7;
        size_t go = (size_t)n * 512 + kt * 64 + seg * 8;
        uint32_t so_ = (uint32_t)(n * 144 + seg * 16);
        cp16(sb + K3_B_HI + bofs + so_, g_bh + go);
        cp16(sb + K3_B_LO + bofs + so_, g_bl + go);
    }
}

__global__ void __launch_bounds__(256, 2) k3_out(const float* __restrict__ blin) {
    extern __shared__ __align__(16) char dsm[];
    uint32_t sb = smem_u32(dsm);
    int t = threadIdx.x;
    int wid = t >> 5, lane = t & 31;
    int m0 = blockIdx.x * 128;
    int wm = wid * 16;

    float acc[8][4];
#pragma unroll
    for (int nt = 0; nt < 8; nt++)
#pragma unroll
        for (int q = 0; q < 4; q++) acc[nt][q] = 0.f;

    int qq = lane >> 3, rr = lane & 7;

    k3_load(sb, dsm, t, m0, 0, 0);
    CP_COMMIT();

#pragma unroll 1
    for (int kt = 0; kt < 8; kt++) {
        int st = kt & 1;
        if (kt < 7) {
            k3_load(sb, dsm, t, m0, kt + 1, st ^ 1);
            CP_COMMIT();
            CP_WAIT1();
        } else {
            CP_WAIT0();
        }
        __syncthreads();

        uint32_t aofs = (uint32_t)st * 18432u;
        uint32_t bofs = (uint32_t)st * 9216u;
#pragma unroll
        for (int ks = 0; ks < 4; ks++) {
            int k0 = ks * 16;
            uint32_t ah[4], al[4];
            {
                int row = wm + rr + (qq & 1) * 8;
                int col = k0 + (qq >> 1) * 8;
                uint32_t ad = sb + K3_A_HI + aofs + (uint32_t)(row * 144 + col * 2);
                ldsm4(ah, ad);
                ldsm4(al, ad + (K3_A_LO - K3_A_HI));
            }
#pragma unroll
            for (int p = 0; p < 4; p++) {
                uint32_t bh4[4], bl4[4];
                int noff = 16 * p + rr + (qq >> 1) * 8;
                int col = k0 + (qq & 1) * 8;
                uint32_t bd = sb + K3_B_HI + bofs + (uint32_t)(noff * 144 + col * 2);
                ldsm4(bh4, bd);
                ldsm4(bl4, bd + (K3_B_LO - K3_B_HI));
                mma16816(acc[2 * p], ah, bh4);
                mma16816(acc[2 * p + 1], ah, bh4 + 2);
                mma16816(acc[2 * p], al, bh4);
                mma16816(acc[2 * p + 1], al, bh4 + 2);
                mma16816(acc[2 * p], ah, bl4);
                mma16816(acc[2 * p + 1], ah, bl4 + 2);
            }
        }
        __syncthreads();
    }

    // acc -> o smem f32 with bias + relu (reuses stage-0 A region)
    {
        int rrow = lane >> 2, cp = (lane & 3) * 2;
        float* so = (float*)dsm;
#pragma unroll
        for (int nt = 0; nt < 8; nt++) {
            int c0 = nt * 8 + cp;
            float b0v = __ldg(&blin[c0]), b1v = __ldg(&blin[c0 + 1]);
            so[(wm + rrow) * 65 + c0]         = relu_f(acc[nt][0] + b0v);
            so[(wm + rrow) * 65 + c0 + 1]     = relu_f(acc[nt][1] + b1v);
            so[(wm + rrow + 8) * 65 + c0]     = relu_f(acc[nt][2] + b0v);
            so[(wm + rrow + 8) * 65 + c0 + 1] = relu_f(acc[nt][3] + b1v);
        }
    }
    __syncthreads();

    const float* so = (const float*)dsm;
#pragma unroll
    for (int q = 0; q < 4; q++) {
        int id = t + q * 256;
        int row = id >> 3, c8 = (id & 7) * 8;
        int gm = m0 + row;
        if (gm < MPTS) {
            __align__(16) __nv_bfloat16 hb[8];
            __align__(16) __nv_bfloat16 lb[8];
#pragma unroll
            for (int i = 0; i < 8; i++) {
                float v = so[row * 65 + c8 + i];
                __nv_bfloat16 h = __float2bfloat16(v);
                hb[i] = h;
                lb[i] = __float2bfloat16(v - __bfloat162float(h));
            }
            *(uint4*)(g_oh + (size_t)gm * 64 + c8) = *(uint4*)hb;
            *(uint4*)(g_ol + (size_t)gm * 64 + c8) = *(uint4*)lb;
        }
    }
}

// ======================= K4: MMA GEMM2 + final epilogue ====================
#define K4_A_HI 0u
#define K4_A_LO 18432u
#define K4_B_HI 36864u
#define K4_B_LO 55296u
#define K4_SMEM 73728

__global__ void __launch_bounds__(256, 2) k4_out(
    const float* __restrict__ bu2, const float* __restrict__ bsc,
    float* __restrict__ out) {
    extern __shared__ __align__(16) char dsm[];
    uint32_t sb = smem_u32(dsm);
    int t = threadIdx.x;
    int wid = t >> 5, lane = t & 31;
    int m0 = blockIdx.x * 128;
    int wm = wid * 16;

    float acc[16][4];
#pragma unroll
    for (int nt = 0; nt < 16; nt++)
#pragma unroll
        for (int q = 0; q < 4; q++) acc[nt][q] = 0.f;

    int qq = lane >> 3, rr = lane & 7;

#pragma unroll 1
    for (int kt = 0; kt < 2; kt++) {
        const __nv_bfloat16* ah_src = kt ? g_sfh : g_oh;
        const __nv_bfloat16* al_src = kt ? g_sfl : g_ol;
#pragma unroll
        for (int q = 0; q < 4; q++) {
            int id = t + q * 256;
            int row = id >> 3, seg = id & 7;
            int gm = m0 + row; if (gm >= MPTS) gm = MPTS - 1;
            size_t go = (size_t)gm * 64 + seg * 8;
            uint32_t so_ = (uint32_t)(row * 144 + seg * 16);
            *(uint4*)(dsm + K4_A_HI + so_) = *(const uint4*)(ah_src + go);
            *(uint4*)(dsm + K4_A_LO + so_) = *(const uint4*)(al_src + go);
        }
#pragma unroll
        for (int q = 0; q < 4; q++) {
            int id = t + q * 256;
            int n = id >> 3, seg = id & 7;
            size_t go = (size_t)n * 128 + kt * 64 + seg * 8;
            uint32_t so_ = (uint32_t)(n * 144 + seg * 16);
            *(uint4*)(dsm + K4_B_HI + so_) = *(const uint4*)(g_b2h + go);
            *(uint4*)(dsm + K4_B_LO + so_) = *(const uint4*)(g_b2l + go);
        }
        __syncthreads();

#pragma unroll
        for (int ks = 0; ks < 4; ks++) {
            int k0 = ks * 16;
            uint32_t ah[4], al[4];
            {
                int row = wm + rr + (qq & 1) * 8;
                int col = k0 + (qq >> 1) * 8;
                uint32_t ad = sb + K4_A_HI + (uint32_t)(row * 144 + col * 2);
                ldsm4(ah, ad);
                ldsm4(al, ad + (K4_A_LO - K4_A_HI));
            }
#pragma unroll
            for (int p = 0; p < 8; p++) {
                uint32_t bh4[4], bl4[4];
                int noff = 16 * p + rr + (qq >> 1) * 8;
                int col = k0 + (qq & 1) * 8;
                uint32_t bd = sb + K4_B_HI + (uint32_t)(noff * 144 + col * 2);
                ldsm4(bh4, bd);
                ldsm4(bl4, bd + (K4_B_LO - K4_B_HI));
                mma16816(acc[2 * p], ah, bh4);
                mma16816(acc[2 * p + 1], ah, bh4 + 2);
                mma16816(acc[2 * p], al, bh4);
                mma16816(acc[2 * p + 1], al, bh4 + 2);
                mma16816(acc[2 * p], ah, bl4);
                mma16816(acc[2 * p + 1], ah, bl4 + 2);
            }
        }
        __syncthreads();
    }

    int r0 = lane >> 2, cp = (lane & 3) * 2;
    int mA = m0 + wm + r0, mB = mA + 8;
#pragma unroll
    for (int nt = 0; nt < 16; nt++) {
        int c0 = nt * 8 + cp;
        float b0v = __ldg(&bu2[c0]) + __ldg(&bsc[c0]);
        float b1v = __ldg(&bu2[c0 + 1]) + __ldg(&bsc[c0 + 1]);
        if (mA < MPTS)
            *(float2*)(out + (size_t)mA * 128 + c0) =
                make_float2(lrelu_f(acc[nt][0] + b0v), lrelu_f(acc[nt][1] + b1v));
        if (mB < MPTS)
            *(float2*)(out + (size_t)mB * 128 + c0) =
                make_float2(lrelu_f(acc[nt][2] + b0v), lrelu_f(acc[nt][3] + b1v));
    }
}

// ======================= launch ============================================
extern "C" void kernel_launch(void* const* d_in, const int* in_sizes, int n_in,
                              void* d_out, int out_size) {
    const float* df  = (const float*)d_in[1];
    const float* vi  = (const float*)d_in[5];
    const int*   nei = (const int*)d_in[6];
    const float* w1  = (const float*)d_in[7];
    const float* b1  = (const float*)d_in[8];
    const float* wgu = (const float*)d_in[9];
    const float* bgu = (const float*)d_in[10];
    const float* wpe = (const float*)d_in[11];
    const float* bpe = (const float*)d_in[12];
    const float* wg1 = (const float*)d_in[13];
    const float* bg1 = (const float*)d_in[14];
    const float* wg2 = (const float*)d_in[15];
    const float* bg2 = (const float*)d_in[16];
    const float* wn1 = (const float*)d_in[17];
    const float* bn1 = (const float*)d_in[18];
    const float* wn2 = (const float*)d_in[19];
    const float* bn2 = (const float*)d_in[20];
    const float* wn3 = (const float*)d_in[21];
    const float* bn3 = (const float*)d_in[22];
    const float* wlin = (const float*)d_in[23];
    const float* blin = (const float*)d_in[24];
    const float* wu2 = (const float*)d_in[25];
    const float* bu2 = (const float*)d_in[26];
    const float* wsc = (const float*)d_in[27];
    const float* bsc = (const float*)d_in[28];
    float* out = (float*)d_out;

    cudaFuncSetAttribute(k3_out, cudaFuncAttributeMaxDynamicSharedMemorySize, K3_SMEM);
    cudaFuncSetAttribute(k4_out, cudaFuncAttributeMaxDynamicSharedMemorySize, K4_SMEM);

    k0_wconv<<<128, 256>>>(wlin, wu2, wsc);
    k1_dense<<<(NPTS + 127) / 128, 256>>>(df, w1, b1, wgu, bgu, wg1);
    k2_point<<<MPTS / 8, 256>>>(df, vi, nei,
                                wpe, bpe, wg1, bg1, wg2, bg2,
                                wn1, bn1, wn2, bn2, wn3, bn3);
    k3_out<<<(MPTS + 127) / 128, 256, K3_SMEM>>>(blin);
    k4_out<<<(MPTS + 127) / 128, 256, K4_SMEM>>>(bu2, bsc, out);
}

// round 8
// speedup vs baseline: 1.9846x; 1.0016x over previous
#include <cuda_runtime.h>
#include <cuda_bf16.h>
#include <math.h>
#include <stdint.h>

#define NPTS 200000
#define MPTS 100000

// ---------------- scratch (device globals: allocation-free rule) ----------
__device__ float g_fx[NPTS * 32];                     // feats_x     25.6 MB
__device__ float g_gx[NPTS * 32];                     // guidance_x  25.6 MB
__device__ float g_gw1[NPTS * 8];                     // guidance@W1lo 6.4 MB
__device__ __nv_bfloat16 g_aggh[(size_t)MPTS * 512];  // agg hi     102.4 MB
__device__ __nv_bfloat16 g_aggl[(size_t)MPTS * 512];  // agg lo     102.4 MB
__device__ __nv_bfloat16 g_oh[(size_t)MPTS * 64];     // o hi (relu'd mid)
__device__ __nv_bfloat16 g_ol[(size_t)MPTS * 64];     // o lo
__device__ __nv_bfloat16 g_sfh[(size_t)MPTS * 64];    // sf hi
__device__ __nv_bfloat16 g_sfl[(size_t)MPTS * 64];    // sf lo
__device__ __nv_bfloat16 g_bh[64 * 512];              // w_lin^T hi  [n][k]
__device__ __nv_bfloat16 g_bl[64 * 512];              // w_lin^T lo
__device__ __nv_bfloat16 g_b2h[128 * 128];            // [wu2;wsc]^T hi [n][k]
__device__ __nv_bfloat16 g_b2l[128 * 128];            // lo

__device__ __forceinline__ float relu_f(float x) { return x > 0.f ? x : 0.f; }
__device__ __forceinline__ float lrelu_f(float x) { return x > 0.f ? x : 0.1f * x; }

__device__ __forceinline__ uint32_t smem_u32(const void* p) {
    uint32_t a;
    asm("{ .reg .u64 t; cvta.to.shared.u64 t, %1; cvt.u32.u64 %0, t; }" : "=r"(a) : "l"(p));
    return a;
}
__device__ __forceinline__ void ldsm4(uint32_t* r, uint32_t a) {
    asm volatile("ldmatrix.sync.aligned.m8n8.x4.shared.b16 {%0,%1,%2,%3}, [%4];"
                 : "=r"(r[0]), "=r"(r[1]), "=r"(r[2]), "=r"(r[3]) : "r"(a));
}
__device__ __forceinline__ void mma16816(float* d, const uint32_t* a, const uint32_t* b) {
    asm volatile(
        "mma.sync.aligned.m16n8k16.row.col.f32.bf16.bf16.f32 "
        "{%0,%1,%2,%3}, {%4,%5,%6,%7}, {%8,%9}, {%0,%1,%2,%3};"
        : "+f"(d[0]), "+f"(d[1]), "+f"(d[2]), "+f"(d[3])
        : "r"(a[0]), "r"(a[1]), "r"(a[2]), "r"(a[3]), "r"(b[0]), "r"(b[1]));
}
__device__ __forceinline__ void cp16(uint32_t dst, const void* src) {
    asm volatile("cp.async.cg.shared.global [%0], [%1], 16;" :: "r"(dst), "l"(src));
}
#define CP_COMMIT() asm volatile("cp.async.commit_group;" ::: "memory")
#define CP_WAIT1() asm volatile("cp.async.wait_group 1;" ::: "memory")
#define CP_WAIT0() asm volatile("cp.async.wait_group 0;" ::: "memory")

// ======================= K0: weight conversions ============================
__global__ void __launch_bounds__(256) k0_wconv(
    const float* __restrict__ wlin, const float* __restrict__ wu2,
    const float* __restrict__ wsc) {
    int i = blockIdx.x * 256 + threadIdx.x;
    if (i < 512 * 64) {
        int n = i >> 9, k = i & 511;
        float v = __ldg(&wlin[k * 64 + n]);
        __nv_bfloat16 h = __float2bfloat16(v);
        g_bh[i] = h;
        g_bl[i] = __float2bfloat16(v - __bfloat162float(h));
    }
    if (i < 128 * 128) {
        int n = i >> 7, k = i & 127;
        float v = (k < 64) ? __ldg(&wu2[k * 128 + n]) : __ldg(&wsc[(k - 64) * 128 + n]);
        __nv_bfloat16 h = __float2bfloat16(v);
        g_b2h[i] = h;
        g_b2l[i] = __float2bfloat16(v - __bfloat162float(h));
    }
}

// ======================= K1: dense transform + gw1 =========================
__global__ void __launch_bounds__(256) k1_dense(
    const float* __restrict__ df,
    const float* __restrict__ w1, const float* __restrict__ b1,
    const float* __restrict__ wgu, const float* __restrict__ bgu,
    const float* __restrict__ wg1) {
    __shared__ __align__(16) float s_w1[64 * 32];
    __shared__ __align__(16) float s_wgu[32 * 32];
    __shared__ __align__(16) float s_wg1k[32 * 8];
    __shared__ union {
        float f[128][68];
        float fx[128][36];
    } u;
    int t = threadIdx.x;
    int p0 = blockIdx.x * 128;
    for (int i = t; i < 2048; i += 256) s_w1[i] = w1[i];
    for (int i = t; i < 1024; i += 256) s_wgu[i] = wgu[i];
    if (t < 256) s_wg1k[t] = wg1[t];
#pragma unroll
    for (int q = 0; q < 8; q++) {
        int id = t + q * 256;
        int pp = id >> 4, kk = (id & 15) * 4;
        int gm = p0 + pp; if (gm >= NPTS) gm = NPTS - 1;
        *(float4*)&u.f[pp][kk] = *(const float4*)(df + (size_t)gm * 64 + kk);
    }
    __syncthreads();

    int pg = t >> 3, cg = t & 7;
    int c4 = cg * 4;
    float4 bb = *(const float4*)(b1 + c4);
    float acc[4][4];
#pragma unroll
    for (int i = 0; i < 4; i++) { acc[i][0] = bb.x; acc[i][1] = bb.y; acc[i][2] = bb.z; acc[i][3] = bb.w; }
#pragma unroll
    for (int kb = 0; kb < 64; kb += 4) {
        float4 a[4];
#pragma unroll
        for (int i = 0; i < 4; i++) a[i] = *(const float4*)&u.f[pg * 4 + i][kb];
#pragma unroll
        for (int q = 0; q < 4; q++) {
            float4 w = *(const float4*)&s_w1[(kb + q) * 32 + c4];
#pragma unroll
            for (int i = 0; i < 4; i++) {
                float av = q == 0 ? a[i].x : q == 1 ? a[i].y : q == 2 ? a[i].z : a[i].w;
                acc[i][0] = fmaf(av, w.x, acc[i][0]); acc[i][1] = fmaf(av, w.y, acc[i][1]);
                acc[i][2] = fmaf(av, w.z, acc[i][2]); acc[i][3] = fmaf(av, w.w, acc[i][3]);
            }
        }
    }
    float4 fxv[4];
#pragma unroll
    for (int i = 0; i < 4; i++)
        fxv[i] = make_float4(lrelu_f(acc[i][0]), lrelu_f(acc[i][1]), lrelu_f(acc[i][2]), lrelu_f(acc[i][3]));
    __syncthreads();
#pragma unroll
    for (int i = 0; i < 4; i++) {
        int gm = p0 + pg * 4 + i;
        *(float4*)&u.fx[pg * 4 + i][c4] = fxv[i];
        if (gm < NPTS) *(float4*)(g_fx + (size_t)gm * 32 + c4) = fxv[i];
    }
    __syncthreads();

    float4 bg = *(const float4*)(bgu + c4);
    float gac[4][4];
#pragma unroll
    for (int i = 0; i < 4; i++) { gac[i][0] = bg.x; gac[i][1] = bg.y; gac[i][2] = bg.z; gac[i][3] = bg.w; }
#pragma unroll
    for (int kb = 0; kb < 32; kb += 4) {
        float4 a[4];
#pragma unroll
        for (int i = 0; i < 4; i++) a[i] = *(const float4*)&u.fx[pg * 4 + i][kb];
#pragma unroll
        for (int q = 0; q < 4; q++) {
            float4 w = *(const float4*)&s_wgu[(kb + q) * 32 + c4];
#pragma unroll
            for (int i = 0; i < 4; i++) {
                float av = q == 0 ? a[i].x : q == 1 ? a[i].y : q == 2 ? a[i].z : a[i].w;
                gac[i][0] = fmaf(av, w.x, gac[i][0]); gac[i][1] = fmaf(av, w.y, gac[i][1]);
                gac[i][2] = fmaf(av, w.z, gac[i][2]); gac[i][3] = fmaf(av, w.w, gac[i][3]);
            }
        }
    }
    __syncthreads();
#pragma unroll
    for (int i = 0; i < 4; i++) {
        int gm = p0 + pg * 4 + i;
        *(float4*)&u.fx[pg * 4 + i][c4] =
            make_float4(gac[i][0], gac[i][1], gac[i][2], gac[i][3]);
        if (gm < NPTS)
            *(float4*)(g_gx + (size_t)gm * 32 + c4) =
                make_float4(gac[i][0], gac[i][1], gac[i][2], gac[i][3]);
    }
    __syncthreads();

    {
        int p2 = t >> 1, h4 = (t & 1) * 4;
        float o4[4] = {0.f, 0.f, 0.f, 0.f};
#pragma unroll
        for (int c = 0; c < 32; c++) {
            float g = u.fx[p2][c];
            float4 w = *(const float4*)&s_wg1k[c * 8 + h4];
            o4[0] = fmaf(g, w.x, o4[0]); o4[1] = fmaf(g, w.y, o4[1]);
            o4[2] = fmaf(g, w.z, o4[2]); o4[3] = fmaf(g, w.w, o4[3]);
        }
        int gm = p0 + p2;
        if (gm < NPTS)
            *(float4*)(g_gw1 + (size_t)gm * 8 + h4) = make_float4(o4[0], o4[1], o4[2], o4[3]);
    }
}

// ======================= K2: per-sparse-point pipeline =====================
// warp per point; lane = (j = lane>>1, half = lane&1).
// All gathers issued via cp.async at warp start; compute overlaps memory.
__global__ void __launch_bounds__(256, 2) k2_point(
    const float* __restrict__ df,
    const float* __restrict__ vi_f,
    const int* __restrict__ nei,
    const float* __restrict__ wpe, const float* __restrict__ bpe,
    const float* __restrict__ wg1, const float* __restrict__ bg1,
    const float* __restrict__ wg2, const float* __restrict__ bg2,
    const float* __restrict__ wn1, const float* __restrict__ bn1,
    const float* __restrict__ wn2, const float* __restrict__ bn2,
    const float* __restrict__ wn3, const float* __restrict__ bn3) {
    __shared__ __align__(16) float s_wpet[32 * 12];
    __shared__ __align__(16) float s_wg1[64 * 8];
    __shared__ __align__(16) float s_wg2t[8 * 8];
    __shared__ __align__(16) float s_wn1t[8 * 12];
    __shared__ __align__(16) float s_wn2t[8 * 8];
    __shared__ __align__(16) float s_wn3t[16 * 8];
    __shared__ float s_bpe[32], s_bg1[8], s_bg2[8], s_bn1[8], s_bn2[8], s_bn3[16];
    __shared__ __align__(16) float s_gf[8][16][68];
    __shared__ __align__(16) float s_nf[8][16][36];   // fx gathered, scaled in place
    __shared__ __align__(16) float s_w[8][16][20];
    int t = threadIdx.x;
    for (int i = t; i < 384; i += 256) { int c = i / 12, ii = i % 12; s_wpet[i] = wpe[ii * 32 + c]; }
    for (int i = t; i < 512; i += 256) s_wg1[i] = wg1[i];
    if (t < 64) s_wg2t[t] = wg2[(t & 7) * 8 + (t >> 3)];
    if (t < 96) { int o = t / 12, ii = t % 12; s_wn1t[t] = wn1[ii * 8 + o]; }
    if (t < 64) s_wn2t[t] = wn2[(t & 7) * 8 + (t >> 3)];
    if (t < 128) { int o = t >> 3, ii = t & 7; s_wn3t[t] = wn3[ii * 16 + o]; }
    if (t < 32) s_bpe[t] = bpe[t];
    if (t < 8) { s_bg1[t] = bg1[t]; s_bg2[t] = bg2[t]; s_bn1[t] = bn1[t]; s_bn2[t] = bn2[t]; }
    if (t < 16) s_bn3[t] = bn3[t];
    __syncthreads();

    const unsigned FULL = 0xffffffffu;
    int wid = t >> 5, lane = t & 31;
    int j = lane >> 1, half = lane & 1;
    int m = blockIdx.x * 8 + wid;
    int idx = __ldg(&nei[m * 16 + j]);

    // ---- front-batched memory: async gathers into smem ----
    {
        const char* gsrc = (const char*)(g_gx + (size_t)idx * 32 + half * 16);
        uint32_t gdst = smem_u32(&s_gf[wid][j][half * 16]);
        cp16(gdst, gsrc); cp16(gdst + 16, gsrc + 16);
        cp16(gdst + 32, gsrc + 32); cp16(gdst + 48, gsrc + 48);
        const char* fsrc = (const char*)(g_fx + (size_t)idx * 32 + half * 16);
        uint32_t fdst = smem_u32(&s_nf[wid][j][half * 16]);
        cp16(fdst, fsrc); cp16(fdst + 16, fsrc + 16);
        cp16(fdst + 32, fsrc + 32); cp16(fdst + 48, fsrc + 48);
        CP_COMMIT();
    }
    // part init: half==0 lane has precomputed gathered-guidance @ W1lo
    float part[8];
    if (half == 0) {
        float4 a0 = __ldg((const float4*)(g_gw1 + (size_t)idx * 8));
        float4 a1 = __ldg((const float4*)(g_gw1 + (size_t)idx * 8 + 4));
        part[0] = a0.x; part[1] = a0.y; part[2] = a0.z; part[3] = a0.w;
        part[4] = a1.x; part[5] = a1.y; part[6] = a1.z; part[7] = a1.w;
    } else {
#pragma unroll
        for (int h = 0; h < 8; h++) part[h] = 0.f;
    }
    float vi[12];
    {
        const float4* vp = (const float4*)(vi_f + ((size_t)m * 16 + j) * 12);
        float4 a = vp[0], b = vp[1], c = vp[2];
        vi[0] = a.x; vi[1] = a.y; vi[2] = a.z; vi[3] = a.w;
        vi[4] = b.x; vi[5] = b.y; vi[6] = b.z; vi[7] = b.w;
        vi[8] = c.x; vi[9] = c.y; vi[10] = c.z; vi[11] = c.w;
    }
    // maxpool loads issued early (independent fmax chains, good MLP)
    float m0v = -3.0e38f, m1v = -3.0e38f;
#pragma unroll
    for (int jj = 0; jj < 16; jj++) {
        int ix = __shfl_sync(FULL, idx, jj * 2);
        m0v = fmaxf(m0v, __ldg(&df[(size_t)ix * 64 + lane]));
        m1v = fmaxf(m1v, __ldg(&df[(size_t)ix * 64 + 32 + lane]));
    }

    // ---- compute while gathers fly ----
    // PE (fused with its W1hi partial)
#pragma unroll
    for (int c16 = 0; c16 < 16; c16++) {
        int c = half * 16 + c16;
        float a = s_bpe[c];
        const float4* wr = (const float4*)&s_wpet[c * 12];
        float4 w0 = wr[0], w1v = wr[1], w2 = wr[2];
        a = fmaf(vi[0], w0.x, a); a = fmaf(vi[1], w0.y, a);
        a = fmaf(vi[2], w0.z, a); a = fmaf(vi[3], w0.w, a);
        a = fmaf(vi[4], w1v.x, a); a = fmaf(vi[5], w1v.y, a);
        a = fmaf(vi[6], w1v.z, a); a = fmaf(vi[7], w1v.w, a);
        a = fmaf(vi[8], w2.x, a); a = fmaf(vi[9], w2.y, a);
        a = fmaf(vi[10], w2.z, a); a = fmaf(vi[11], w2.w, a);
        float r = relu_f(a);
        s_gf[wid][j][32 + c] = r;
        const float4* pr = (const float4*)&s_wg1[(32 + c) * 8];
        float4 wa = pr[0], wb = pr[1];
        part[0] = fmaf(r, wa.x, part[0]); part[1] = fmaf(r, wa.y, part[1]);
        part[2] = fmaf(r, wa.z, part[2]); part[3] = fmaf(r, wa.w, part[3]);
        part[4] = fmaf(r, wb.x, part[4]); part[5] = fmaf(r, wb.y, part[5]);
        part[6] = fmaf(r, wb.z, part[6]); part[7] = fmaf(r, wb.w, part[7]);
    }

    // WeightNet 12->8->8->16 (independent of gathers)
    float h1[8];
#pragma unroll
    for (int o = 0; o < 8; o++) {
        float a = s_bn1[o];
        const float4* wr = (const float4*)&s_wn1t[o * 12];
        float4 w0 = wr[0], w1v = wr[1], w2 = wr[2];
        a = fmaf(vi[0], w0.x, a); a = fmaf(vi[1], w0.y, a);
        a = fmaf(vi[2], w0.z, a); a = fmaf(vi[3], w0.w, a);
        a = fmaf(vi[4], w1v.x, a); a = fmaf(vi[5], w1v.y, a);
        a = fmaf(vi[6], w1v.z, a); a = fmaf(vi[7], w1v.w, a);
        a = fmaf(vi[8], w2.x, a); a = fmaf(vi[9], w2.y, a);
        a = fmaf(vi[10], w2.z, a); a = fmaf(vi[11], w2.w, a);
        h1[o] = relu_f(a);
    }
    float h2v[8];
#pragma unroll
    for (int o = 0; o < 8; o++) {
        float a = s_bn2[o];
        const float4* wr = (const float4*)&s_wn2t[o * 8];
        float4 wa = wr[0], wb = wr[1];
        a = fmaf(h1[0], wa.x, a); a = fmaf(h1[1], wa.y, a);
        a = fmaf(h1[2], wa.z, a); a = fmaf(h1[3], wa.w, a);
        a = fmaf(h1[4], wb.x, a); a = fmaf(h1[5], wb.y, a);
        a = fmaf(h1[6], wb.z, a); a = fmaf(h1[7], wb.w, a);
        h2v[o] = relu_f(a);
    }
#pragma unroll
    for (int oo = 0; oo < 8; oo++) {
        int o = half * 8 + oo;
        float a = s_bn3[o];
        const float4* wr = (const float4*)&s_wn3t[o * 8];
        float4 wa = wr[0], wb = wr[1];
        a = fmaf(h2v[0], wa.x, a); a = fmaf(h2v[1], wa.y, a);
        a = fmaf(h2v[2], wa.z, a); a = fmaf(h2v[3], wa.w, a);
        a = fmaf(h2v[4], wb.x, a); a = fmaf(h2v[5], wb.y, a);
        a = fmaf(h2v[6], wb.z, a); a = fmaf(h2v[7], wb.w, a);
        s_w[wid][j][o] = relu_f(a);
    }

    // ---- gathers done: channel max + guidance tail ----
    CP_WAIT0();
    __syncwarp();

    float mx0 = -3.0e38f, mx1 = -3.0e38f;
    int cl = lane;
#pragma unroll
    for (int jj = 0; jj < 16; jj++) {
        mx0 = fmaxf(mx0, s_gf[wid][jj][cl]);
        mx1 = fmaxf(mx1, s_gf[wid][jj][cl + 32]);
    }
    float mw[8];
    {
        const float4* wr0 = (const float4*)&s_wg1[cl * 8];
        const float4* wr1 = (const float4*)&s_wg1[(cl + 32) * 8];
        float4 a0 = wr0[0], a1 = wr0[1], b0 = wr1[0], b1v = wr1[1];
        mw[0] = fmaf(mx0, a0.x, mx1 * b0.x); mw[1] = fmaf(mx0, a0.y, mx1 * b0.y);
        mw[2] = fmaf(mx0, a0.z, mx1 * b0.z); mw[3] = fmaf(mx0, a0.w, mx1 * b0.w);
        mw[4] = fmaf(mx0, a1.x, mx1 * b1v.x); mw[5] = fmaf(mx0, a1.y, mx1 * b1v.y);
        mw[6] = fmaf(mx0, a1.z, mx1 * b1v.z); mw[7] = fmaf(mx0, a1.w, mx1 * b1v.w);
    }
#pragma unroll
    for (int s = 16; s >= 1; s >>= 1) {
#pragma unroll
        for (int h = 0; h < 8; h++) mw[h] += __shfl_xor_sync(FULL, mw[h], s);
    }
#pragma unroll
    for (int h = 0; h < 8; h++) part[h] += __shfl_xor_sync(FULL, part[h], 1);

    float s1v[8];
#pragma unroll
    for (int h = 0; h < 8; h++) s1v[h] = relu_f(part[h] - mw[h] + s_bg1[h]);
    float sc4[4];
#pragma unroll
    for (int hq = 0; hq < 4; hq++) {
        int h2 = half * 4 + hq;
        float a = s_bg2[h2];
        const float4* wr = (const float4*)&s_wg2t[h2 * 8];
        float4 wa = wr[0], wb = wr[1];
        a = fmaf(s1v[0], wa.x, a); a = fmaf(s1v[1], wa.y, a);
        a = fmaf(s1v[2], wa.z, a); a = fmaf(s1v[3], wa.w, a);
        a = fmaf(s1v[4], wb.x, a); a = fmaf(s1v[5], wb.y, a);
        a = fmaf(s1v[6], wb.z, a); a = fmaf(s1v[7], wb.w, a);
        sc4[hq] = 1.f / (1.f + __expf(-a));
    }

    // nf = fx * score, in place in s_nf
#pragma unroll
    for (int q = 0; q < 4; q++) {
        int c0 = half * 16 + 4 * q;
        float4 v = *(const float4*)&s_nf[wid][j][c0];
        float s = sc4[q];
        *(float4*)&s_nf[wid][j][c0] = make_float4(v.x * s, v.y * s, v.z * s, v.w * s);
    }

    // shortcut maxpool -> bf16 hi/lo (values already computed)
    {
        __nv_bfloat16 h0 = __float2bfloat16(m0v);
        __nv_bfloat16 h1b = __float2bfloat16(m1v);
        g_sfh[(size_t)m * 64 + lane] = h0;
        g_sfl[(size_t)m * 64 + lane] = __float2bfloat16(m0v - __bfloat162float(h0));
        g_sfh[(size_t)m * 64 + 32 + lane] = h1b;
        g_sfl[(size_t)m * 64 + 32 + lane] = __float2bfloat16(m1v - __bfloat162float(h1b));
    }
    __syncwarp();

    float acc[16];
#pragma unroll
    for (int w = 0; w < 16; w++) acc[w] = 0.f;
    int c = lane;
#pragma unroll
    for (int jj = 0; jj < 16; jj++) {
        float a = s_nf[wid][jj][c];
        const float4* wp = (const float4*)&s_w[wid][jj][0];
        float4 w0 = wp[0], w1v = wp[1], w2 = wp[2], w3 = wp[3];
        acc[0] = fmaf(a, w0.x, acc[0]);  acc[1] = fmaf(a, w0.y, acc[1]);
        acc[2] = fmaf(a, w0.z, acc[2]);  acc[3] = fmaf(a, w0.w, acc[3]);
        acc[4] = fmaf(a, w1v.x, acc[4]); acc[5] = fmaf(a, w1v.y, acc[5]);
        acc[6] = fmaf(a, w1v.z, acc[6]); acc[7] = fmaf(a, w1v.w, acc[7]);
        acc[8] = fmaf(a, w2.x, acc[8]);  acc[9] = fmaf(a, w2.y, acc[9]);
        acc[10] = fmaf(a, w2.z, acc[10]); acc[11] = fmaf(a, w2.w, acc[11]);
        acc[12] = fmaf(a, w3.x, acc[12]); acc[13] = fmaf(a, w3.y, acc[13]);
        acc[14] = fmaf(a, w3.z, acc[14]); acc[15] = fmaf(a, w3.w, acc[15]);
    }
    __align__(16) __nv_bfloat16 hb[16];
    __align__(16) __nv_bfloat16 lb[16];
#pragma unroll
    for (int w = 0; w < 16; w++) {
        float v = acc[w];
        __nv_bfloat16 h = __float2bfloat16(v);
        hb[w] = h;
        lb[w] = __float2bfloat16(v - __bfloat162float(h));
    }
    size_t bo = (size_t)m * 512 + c * 16;
    ((uint4*)(g_aggh + bo))[0] = ((uint4*)hb)[0];
    ((uint4*)(g_aggh + bo))[1] = ((uint4*)hb)[1];
    ((uint4*)(g_aggl + bo))[0] = ((uint4*)lb)[0];
    ((uint4*)(g_aggl + bo))[1] = ((uint4*)lb)[1];
}

// ======================= K3: pipelined MMA GEMM1 -> o bf16 =================
#define K3_A_HI 0u
#define K3_A_LO 36864u
#define K3_B_HI 73728u
#define K3_B_LO 92160u
#define K3_SMEM 110592

__device__ __forceinline__ void k3_load(uint32_t sb, char* dsm, int t, int m0,
                                        int kt, int st) {
    uint32_t aofs = (uint32_t)st * 18432u;
    uint32_t bofs = (uint32_t)st * 9216u;
#pragma unroll
    for (int q = 0; q < 4; q++) {
        int id = t + q * 256;
        int row = id >> 3, seg = id & 7;
        int gm = m0 + row; if (gm >= MPTS) gm = MPTS - 1;
        size_t go = (size_t)gm * 512 + kt * 64 + seg * 8;
        uint32_t so_ = (uint32_t)(row * 144 + seg * 16);
        cp16(sb + K3_A_HI + aofs + so_, g_aggh + go);
        cp16(sb + K3_A_LO + aofs + so_, g_aggl + go);
    }
#pragma unroll
    for (int q = 0; q < 2; q++) {
        int id = t + q * 256;
        int n = id >> 3, seg = id & 7;
        size_t go = (size_t)n * 512 + kt * 64 + seg * 8;
        uint32_t so_ = (uint32_t)(n * 144 + seg * 16);
        cp16(sb + K3_B_HI + bofs + so_, g_bh + go);
        cp16(sb + K3_B_LO + bofs + so_, g_bl + go);
    }
}

__global__ void __launch_bounds__(256, 2) k3_out(const float* __restrict__ blin) {
    extern __shared__ __align__(16) char dsm[];
    uint32_t sb = smem_u32(dsm);
    int t = threadIdx.x;
    int wid = t >> 5, lane = t & 31;
    int m0 = blockIdx.x * 128;
    int wm = wid * 16;

    float acc[8][4];
#pragma unroll
    for (int nt = 0; nt < 8; nt++)
#pragma unroll
        for (int q = 0; q < 4; q++) acc[nt][q] = 0.f;

    int qq = lane >> 3, rr = lane & 7;

    k3_load(sb, dsm, t, m0, 0, 0);
    CP_COMMIT();

#pragma unroll 1
    for (int kt = 0; kt < 8; kt++) {
        int st = kt & 1;
        if (kt < 7) {
            k3_load(sb, dsm, t, m0, kt + 1, st ^ 1);
            CP_COMMIT();
            CP_WAIT1();
        } else {
            CP_WAIT0();
        }
        __syncthreads();

        uint32_t aofs = (uint32_t)st * 18432u;
        uint32_t bofs = (uint32_t)st * 9216u;
#pragma unroll
        for (int ks = 0; ks < 4; ks++) {
            int k0 = ks * 16;
            uint32_t ah[4], al[4];
            {
                int row = wm + rr + (qq & 1) * 8;
                int col = k0 + (qq >> 1) * 8;
                uint32_t ad = sb + K3_A_HI + aofs + (uint32_t)(row * 144 + col * 2);
                ldsm4(ah, ad);
                ldsm4(al, ad + (K3_A_LO - K3_A_HI));
            }
#pragma unroll
            for (int p = 0; p < 4; p++) {
                uint32_t bh4[4], bl4[4];
                int noff = 16 * p + rr + (qq >> 1) * 8;
                int col = k0 + (qq & 1) * 8;
                uint32_t bd = sb + K3_B_HI + bofs + (uint32_t)(noff * 144 + col * 2);
                ldsm4(bh4, bd);
                ldsm4(bl4, bd + (K3_B_LO - K3_B_HI));
                mma16816(acc[2 * p], ah, bh4);
                mma16816(acc[2 * p + 1], ah, bh4 + 2);
                mma16816(acc[2 * p], al, bh4);
                mma16816(acc[2 * p + 1], al, bh4 + 2);
                mma16816(acc[2 * p], ah, bl4);
                mma16816(acc[2 * p + 1], ah, bl4 + 2);
            }
        }
        __syncthreads();
    }

    {
        int rrow = lane >> 2, cp = (lane & 3) * 2;
        float* so = (float*)dsm;
#pragma unroll
        for (int nt = 0; nt < 8; nt++) {
            int c0 = nt * 8 + cp;
            float b0v = __ldg(&blin[c0]), b1v = __ldg(&blin[c0 + 1]);
            so[(wm + rrow) * 65 + c0]         = relu_f(acc[nt][0] + b0v);
            so[(wm + rrow) * 65 + c0 + 1]     = relu_f(acc[nt][1] + b1v);
            so[(wm + rrow + 8) * 65 + c0]     = relu_f(acc[nt][2] + b0v);
            so[(wm + rrow + 8) * 65 + c0 + 1] = relu_f(acc[nt][3] + b1v);
        }
    }
    __syncthreads();

    const float* so = (const float*)dsm;
#pragma unroll
    for (int q = 0; q < 4; q++) {
        int id = t + q * 256;
        int row = id >> 3, c8 = (id & 7) * 8;
        int gm = m0 + row;
        if (gm < MPTS) {
            __align__(16) __nv_bfloat16 hb[8];
            __align__(16) __nv_bfloat16 lb[8];
#pragma unroll
            for (int i = 0; i < 8; i++) {
                float v = so[row * 65 + c8 + i];
                __nv_bfloat16 h = __float2bfloat16(v);
                hb[i] = h;
                lb[i] = __float2bfloat16(v - __bfloat162float(h));
            }
            *(uint4*)(g_oh + (size_t)gm * 64 + c8) = *(uint4*)hb;
            *(uint4*)(g_ol + (size_t)gm * 64 + c8) = *(uint4*)lb;
        }
    }
}

// ======================= K4: MMA GEMM2 + final epilogue ====================
#define K4_A_HI 0u
#define K4_A_LO 18432u
#define K4_B_HI 36864u
#define K4_B_LO 55296u
#define K4_SMEM 73728

__global__ void __launch_bounds__(256, 2) k4_out(
    const float* __restrict__ bu2, const float* __restrict__ bsc,
    float* __restrict__ out) {
    extern __shared__ __align__(16) char dsm[];
    uint32_t sb = smem_u32(dsm);
    int t = threadIdx.x;
    int wid = t >> 5, lane = t & 31;
    int m0 = blockIdx.x * 128;
    int wm = wid * 16;

    float acc[16][4];
#pragma unroll
    for (int nt = 0; nt < 16; nt++)
#pragma unroll
        for (int q = 0; q < 4; q++) acc[nt][q] = 0.f;

    int qq = lane >> 3, rr = lane & 7;

#pragma unroll 1
    for (int kt = 0; kt < 2; kt++) {
        const __nv_bfloat16* ah_src = kt ? g_sfh : g_oh;
        const __nv_bfloat16* al_src = kt ? g_sfl : g_ol;
#pragma unroll
        for (int q = 0; q < 4; q++) {
            int id = t + q * 256;
            int row = id >> 3, seg = id & 7;
            int gm = m0 + row; if (gm >= MPTS) gm = MPTS - 1;
            size_t go = (size_t)gm * 64 + seg * 8;
            uint32_t so_ = (uint32_t)(row * 144 + seg * 16);
            *(uint4*)(dsm + K4_A_HI + so_) = *(const uint4*)(ah_src + go);
            *(uint4*)(dsm + K4_A_LO + so_) = *(const uint4*)(al_src + go);
        }
#pragma unroll
        for (int q = 0; q < 4; q++) {
            int id = t + q * 256;
            int n = id >> 3, seg = id & 7;
            size_t go = (size_t)n * 128 + kt * 64 + seg * 8;
            uint32_t so_ = (uint32_t)(n * 144 + seg * 16);
            *(uint4*)(dsm + K4_B_HI + so_) = *(const uint4*)(g_b2h + go);
            *(uint4*)(dsm + K4_B_LO + so_) = *(const uint4*)(g_b2l + go);
        }
        __syncthreads();

#pragma unroll
        for (int ks = 0; ks < 4; ks++) {
            int k0 = ks * 16;
            uint32_t ah[4], al[4];
            {
                int row = wm + rr + (qq & 1) * 8;
                int col = k0 + (qq >> 1) * 8;
                uint32_t ad = sb + K4_A_HI + (uint32_t)(row * 144 + col * 2);
                ldsm4(ah, ad);
                ldsm4(al, ad + (K4_A_LO - K4_A_HI));
            }
#pragma unroll
            for (int p = 0; p < 8; p++) {
                uint32_t bh4[4], bl4[4];
                int noff = 16 * p + rr + (qq >> 1) * 8;
                int col = k0 + (qq & 1) * 8;
                uint32_t bd = sb + K4_B_HI + (uint32_t)(noff * 144 + col * 2);
                ldsm4(bh4, bd);
                ldsm4(bl4, bd + (K4_B_LO - K4_B_HI));
                mma16816(acc[2 * p], ah, bh4);
                mma16816(acc[2 * p + 1], ah, bh4 + 2);
                mma16816(acc[2 * p], al, bh4);
                mma16816(acc[2 * p + 1], al, bh4 + 2);
                mma16816(acc[2 * p], ah, bl4);
                mma16816(acc[2 * p + 1], ah, bl4 + 2);
            }
        }
        __syncthreads();
    }

    int r0 = lane >> 2, cp = (lane & 3) * 2;
    int mA = m0 + wm + r0, mB = mA + 8;
#pragma unroll
    for (int nt = 0; nt < 16; nt++) {
        int c0 = nt * 8 + cp;
        float b0v = __ldg(&bu2[c0]) + __ldg(&bsc[c0]);
        float b1v = __ldg(&bu2[c0 + 1]) + __ldg(&bsc[c0 + 1]);
        if (mA < MPTS)
            *(float2*)(out + (size_t)mA * 128 + c0) =
                make_float2(lrelu_f(acc[nt][0] + b0v), lrelu_f(acc[nt][1] + b1v));
        if (mB < MPTS)
            *(float2*)(out + (size_t)mB * 128 + c0) =
                make_float2(lrelu_f(acc[nt][2] + b0v), lrelu_f(acc[nt][3] + b1v));
    }
}

// ======================= launch ============================================
extern "C" void kernel_launch(void* const* d_in, const int* in_sizes, int n_in,
                              void* d_out, int out_size) {
    const float* df  = (const float*)d_in[1];
    const float* vi  = (const float*)d_in[5];
    const int*   nei = (const int*)d_in[6];
    const float* w1  = (const float*)d_in[7];
    const float* b1  = (const float*)d_in[8];
    const float* wgu = (const float*)d_in[9];
    const float* bgu = (const float*)d_in[10];
    const float* wpe = (const float*)d_in[11];
    const float* bpe = (const float*)d_in[12];
    const float* wg1 = (const float*)d_in[13];
    const float* bg1 = (const float*)d_in[14];
    const float* wg2 = (const float*)d_in[15];
    const float* bg2 = (const float*)d_in[16];
    const float* wn1 = (const float*)d_in[17];
    const float* bn1 = (const float*)d_in[18];
    const float* wn2 = (const float*)d_in[19];
    const float* bn2 = (const float*)d_in[20];
    const float* wn3 = (const float*)d_in[21];
    const float* bn3 = (const float*)d_in[22];
    const float* wlin = (const float*)d_in[23];
    const float* blin = (const float*)d_in[24];
    const float* wu2 = (const float*)d_in[25];
    const float* bu2 = (const float*)d_in[26];
    const float* wsc = (const float*)d_in[27];
    const float* bsc = (const float*)d_in[28];
    float* out = (float*)d_out;

    cudaFuncSetAttribute(k3_out, cudaFuncAttributeMaxDynamicSharedMemorySize, K3_SMEM);
    cudaFuncSetAttribute(k4_out, cudaFuncAttributeMaxDynamicSharedMemorySize, K4_SMEM);

    k0_wconv<<<128, 256>>>(wlin, wu2, wsc);
    k1_dense<<<(NPTS + 127) / 128, 256>>>(df, w1, b1, wgu, bgu, wg1);
    k2_point<<<MPTS / 8, 256>>>(df, vi, nei,
                                wpe, bpe, wg1, bg1, wg2, bg2,
                                wn1, bn1, wn2, bn2, wn3, bn3);
    k3_out<<<(MPTS + 127) / 128, 256, K3_SMEM>>>(blin);
    k4_out<<<(MPTS + 127) / 128, 256, K4_SMEM>>>(bu2, bsc, out);
}

// round 9
// speedup vs baseline: 2.1420x; 1.0793x over previous
#include <cuda_runtime.h>
#include <cuda_bf16.h>
#include <math.h>
#include <stdint.h>

#define NPTS 200000
#define MPTS 100000

// ---------------- scratch (device globals: allocation-free rule) ----------
__device__ float g_fx[NPTS * 32];                     // feats_x     25.6 MB
__device__ float g_gx[NPTS * 32];                     // guidance_x  25.6 MB
__device__ float g_gw1[NPTS * 8];                     // guidance@W1lo 6.4 MB
__device__ __nv_bfloat16 g_aggh[(size_t)MPTS * 512];  // agg hi     102.4 MB
__device__ __nv_bfloat16 g_aggl[(size_t)MPTS * 512];  // agg lo     102.4 MB
__device__ __nv_bfloat16 g_oh[(size_t)MPTS * 64];     // o hi (relu'd mid)
__device__ __nv_bfloat16 g_ol[(size_t)MPTS * 64];     // o lo
__device__ __nv_bfloat16 g_sfh[(size_t)MPTS * 64];    // sf hi
__device__ __nv_bfloat16 g_sfl[(size_t)MPTS * 64];    // sf lo
__device__ __nv_bfloat16 g_bh[64 * 512];              // w_lin^T hi  [n][k]
__device__ __nv_bfloat16 g_bl[64 * 512];              // w_lin^T lo
__device__ __nv_bfloat16 g_b2h[128 * 128];            // [wu2;wsc]^T hi [n][k]
__device__ __nv_bfloat16 g_b2l[128 * 128];            // lo

__device__ __forceinline__ float relu_f(float x) { return x > 0.f ? x : 0.f; }
__device__ __forceinline__ float lrelu_f(float x) { return x > 0.f ? x : 0.1f * x; }

__device__ __forceinline__ uint32_t smem_u32(const void* p) {
    uint32_t a;
    asm("{ .reg .u64 t; cvta.to.shared.u64 t, %1; cvt.u32.u64 %0, t; }" : "=r"(a) : "l"(p));
    return a;
}
__device__ __forceinline__ void ldsm4(uint32_t* r, uint32_t a) {
    asm volatile("ldmatrix.sync.aligned.m8n8.x4.shared.b16 {%0,%1,%2,%3}, [%4];"
                 : "=r"(r[0]), "=r"(r[1]), "=r"(r[2]), "=r"(r[3]) : "r"(a));
}
__device__ __forceinline__ void mma16816(float* d, const uint32_t* a, const uint32_t* b) {
    asm volatile(
        "mma.sync.aligned.m16n8k16.row.col.f32.bf16.bf16.f32 "
        "{%0,%1,%2,%3}, {%4,%5,%6,%7}, {%8,%9}, {%0,%1,%2,%3};"
        : "+f"(d[0]), "+f"(d[1]), "+f"(d[2]), "+f"(d[3])
        : "r"(a[0]), "r"(a[1]), "r"(a[2]), "r"(a[3]), "r"(b[0]), "r"(b[1]));
}
__device__ __forceinline__ void cp16(uint32_t dst, const void* src) {
    asm volatile("cp.async.cg.shared.global [%0], [%1], 16;" :: "r"(dst), "l"(src));
}
#define CP_COMMIT() asm volatile("cp.async.commit_group;" ::: "memory")
#define CP_WAIT1() asm volatile("cp.async.wait_group 1;" ::: "memory")
#define CP_WAIT0() asm volatile("cp.async.wait_group 0;" ::: "memory")

// ======================= K0: weight conversions ============================
__global__ void __launch_bounds__(256) k0_wconv(
    const float* __restrict__ wlin, const float* __restrict__ wu2,
    const float* __restrict__ wsc) {
    int i = blockIdx.x * 256 + threadIdx.x;
    if (i < 512 * 64) {
        int n = i >> 9, k = i & 511;
        float v = __ldg(&wlin[k * 64 + n]);
        __nv_bfloat16 h = __float2bfloat16(v);
        g_bh[i] = h;
        g_bl[i] = __float2bfloat16(v - __bfloat162float(h));
    }
    if (i < 128 * 128) {
        int n = i >> 7, k = i & 127;
        float v = (k < 64) ? __ldg(&wu2[k * 128 + n]) : __ldg(&wsc[(k - 64) * 128 + n]);
        __nv_bfloat16 h = __float2bfloat16(v);
        g_b2h[i] = h;
        g_b2l[i] = __float2bfloat16(v - __bfloat162float(h));
    }
}

// ======================= K1: dense transform + gw1 =========================
__global__ void __launch_bounds__(256) k1_dense(
    const float* __restrict__ df,
    const float* __restrict__ w1, const float* __restrict__ b1,
    const float* __restrict__ wgu, const float* __restrict__ bgu,
    const float* __restrict__ wg1) {
    __shared__ __align__(16) float s_w1[64 * 32];
    __shared__ __align__(16) float s_wgu[32 * 32];
    __shared__ __align__(16) float s_wg1k[32 * 8];
    __shared__ union {
        float f[128][68];
        float fx[128][36];
    } u;
    int t = threadIdx.x;
    int p0 = blockIdx.x * 128;
    for (int i = t; i < 2048; i += 256) s_w1[i] = w1[i];
    for (int i = t; i < 1024; i += 256) s_wgu[i] = wgu[i];
    if (t < 256) s_wg1k[t] = wg1[t];
#pragma unroll
    for (int q = 0; q < 8; q++) {
        int id = t + q * 256;
        int pp = id >> 4, kk = (id & 15) * 4;
        int gm = p0 + pp; if (gm >= NPTS) gm = NPTS - 1;
        *(float4*)&u.f[pp][kk] = *(const float4*)(df + (size_t)gm * 64 + kk);
    }
    __syncthreads();

    int pg = t >> 3, cg = t & 7;
    int c4 = cg * 4;
    float4 bb = *(const float4*)(b1 + c4);
    float acc[4][4];
#pragma unroll
    for (int i = 0; i < 4; i++) { acc[i][0] = bb.x; acc[i][1] = bb.y; acc[i][2] = bb.z; acc[i][3] = bb.w; }
#pragma unroll
    for (int kb = 0; kb < 64; kb += 4) {
        float4 a[4];
#pragma unroll
        for (int i = 0; i < 4; i++) a[i] = *(const float4*)&u.f[pg * 4 + i][kb];
#pragma unroll
        for (int q = 0; q < 4; q++) {
            float4 w = *(const float4*)&s_w1[(kb + q) * 32 + c4];
#pragma unroll
            for (int i = 0; i < 4; i++) {
                float av = q == 0 ? a[i].x : q == 1 ? a[i].y : q == 2 ? a[i].z : a[i].w;
                acc[i][0] = fmaf(av, w.x, acc[i][0]); acc[i][1] = fmaf(av, w.y, acc[i][1]);
                acc[i][2] = fmaf(av, w.z, acc[i][2]); acc[i][3] = fmaf(av, w.w, acc[i][3]);
            }
        }
    }
    float4 fxv[4];
#pragma unroll
    for (int i = 0; i < 4; i++)
        fxv[i] = make_float4(lrelu_f(acc[i][0]), lrelu_f(acc[i][1]), lrelu_f(acc[i][2]), lrelu_f(acc[i][3]));
    __syncthreads();
#pragma unroll
    for (int i = 0; i < 4; i++) {
        int gm = p0 + pg * 4 + i;
        *(float4*)&u.fx[pg * 4 + i][c4] = fxv[i];
        if (gm < NPTS) *(float4*)(g_fx + (size_t)gm * 32 + c4) = fxv[i];
    }
    __syncthreads();

    float4 bg = *(const float4*)(bgu + c4);
    float gac[4][4];
#pragma unroll
    for (int i = 0; i < 4; i++) { gac[i][0] = bg.x; gac[i][1] = bg.y; gac[i][2] = bg.z; gac[i][3] = bg.w; }
#pragma unroll
    for (int kb = 0; kb < 32; kb += 4) {
        float4 a[4];
#pragma unroll
        for (int i = 0; i < 4; i++) a[i] = *(const float4*)&u.fx[pg * 4 + i][kb];
#pragma unroll
        for (int q = 0; q < 4; q++) {
            float4 w = *(const float4*)&s_wgu[(kb + q) * 32 + c4];
#pragma unroll
            for (int i = 0; i < 4; i++) {
                float av = q == 0 ? a[i].x : q == 1 ? a[i].y : q == 2 ? a[i].z : a[i].w;
                gac[i][0] = fmaf(av, w.x, gac[i][0]); gac[i][1] = fmaf(av, w.y, gac[i][1]);
                gac[i][2] = fmaf(av, w.z, gac[i][2]); gac[i][3] = fmaf(av, w.w, gac[i][3]);
            }
        }
    }
    __syncthreads();
#pragma unroll
    for (int i = 0; i < 4; i++) {
        int gm = p0 + pg * 4 + i;
        *(float4*)&u.fx[pg * 4 + i][c4] =
            make_float4(gac[i][0], gac[i][1], gac[i][2], gac[i][3]);
        if (gm < NPTS)
            *(float4*)(g_gx + (size_t)gm * 32 + c4) =
                make_float4(gac[i][0], gac[i][1], gac[i][2], gac[i][3]);
    }
    __syncthreads();

    {
        int p2 = t >> 1, h4 = (t & 1) * 4;
        float o4[4] = {0.f, 0.f, 0.f, 0.f};
#pragma unroll
        for (int c = 0; c < 32; c++) {
            float g = u.fx[p2][c];
            float4 w = *(const float4*)&s_wg1k[c * 8 + h4];
            o4[0] = fmaf(g, w.x, o4[0]); o4[1] = fmaf(g, w.y, o4[1]);
            o4[2] = fmaf(g, w.z, o4[2]); o4[3] = fmaf(g, w.w, o4[3]);
        }
        int gm = p0 + p2;
        if (gm < NPTS)
            *(float4*)(g_gw1 + (size_t)gm * 8 + h4) = make_float4(o4[0], o4[1], o4[2], o4[3]);
    }
}

// ======================= K5: shortcut maxpool (split from k2) ==============
// warp per point; lane owns channels (lane, lane+32).
__global__ void __launch_bounds__(256) k5_maxpool(
    const float* __restrict__ df, const int* __restrict__ nei) {
    const unsigned FULL = 0xffffffffu;
    int t = threadIdx.x;
    int wid = t >> 5, lane = t & 31;
    int m = blockIdx.x * 8 + wid;
    int j = lane >> 1;
    int idx = __ldg(&nei[m * 16 + j]);
    float m0v = -3.0e38f, m1v = -3.0e38f;
#pragma unroll
    for (int jj = 0; jj < 16; jj++) {
        int ix = __shfl_sync(FULL, idx, jj * 2);
        m0v = fmaxf(m0v, __ldg(&df[(size_t)ix * 64 + lane]));
        m1v = fmaxf(m1v, __ldg(&df[(size_t)ix * 64 + 32 + lane]));
    }
    __nv_bfloat16 h0 = __float2bfloat16(m0v);
    __nv_bfloat16 h1b = __float2bfloat16(m1v);
    g_sfh[(size_t)m * 64 + lane] = h0;
    g_sfl[(size_t)m * 64 + lane] = __float2bfloat16(m0v - __bfloat162float(h0));
    g_sfh[(size_t)m * 64 + 32 + lane] = h1b;
    g_sfl[(size_t)m * 64 + 32 + lane] = __float2bfloat16(m1v - __bfloat162float(h1b));
}

// ======================= K2: per-sparse-point pipeline =====================
// warp per point; lane = (j = lane>>1, half = lane&1).
__global__ void __launch_bounds__(256, 3) k2_point(
    const float* __restrict__ vi_f,
    const int* __restrict__ nei,
    const float* __restrict__ wpe, const float* __restrict__ bpe,
    const float* __restrict__ wg1, const float* __restrict__ bg1,
    const float* __restrict__ wg2, const float* __restrict__ bg2,
    const float* __restrict__ wn1, const float* __restrict__ bn1,
    const float* __restrict__ wn2, const float* __restrict__ bn2,
    const float* __restrict__ wn3, const float* __restrict__ bn3) {
    __shared__ __align__(16) float s_wpet[32 * 12];
    __shared__ __align__(16) float s_wg1[64 * 8];
    __shared__ __align__(16) float s_wg2t[8 * 8];
    __shared__ __align__(16) float s_wn1t[8 * 12];
    __shared__ __align__(16) float s_wn2t[8 * 8];
    __shared__ __align__(16) float s_wn3t[16 * 8];
    __shared__ float s_bpe[32], s_bg1[8], s_bg2[8], s_bn1[8], s_bn2[8], s_bn3[16];
    __shared__ __align__(16) float s_gf[8][16][68];
    __shared__ __align__(16) float s_nf[8][16][36];   // fx gathered, scaled in place
    __shared__ __align__(16) float s_w[8][16][20];
    int t = threadIdx.x;
    for (int i = t; i < 384; i += 256) { int c = i / 12, ii = i % 12; s_wpet[i] = wpe[ii * 32 + c]; }
    for (int i = t; i < 512; i += 256) s_wg1[i] = wg1[i];
    if (t < 64) s_wg2t[t] = wg2[(t & 7) * 8 + (t >> 3)];
    if (t < 96) { int o = t / 12, ii = t % 12; s_wn1t[t] = wn1[ii * 8 + o]; }
    if (t < 64) s_wn2t[t] = wn2[(t & 7) * 8 + (t >> 3)];
    if (t < 128) { int o = t >> 3, ii = t & 7; s_wn3t[t] = wn3[ii * 16 + o]; }
    if (t < 32) s_bpe[t] = bpe[t];
    if (t < 8) { s_bg1[t] = bg1[t]; s_bg2[t] = bg2[t]; s_bn1[t] = bn1[t]; s_bn2[t] = bn2[t]; }
    if (t < 16) s_bn3[t] = bn3[t];
    __syncthreads();

    const unsigned FULL = 0xffffffffu;
    int wid = t >> 5, lane = t & 31;
    int j = lane >> 1, half = lane & 1;
    int m = blockIdx.x * 8 + wid;
    int idx = __ldg(&nei[m * 16 + j]);

    // ---- front-batched memory: async gathers into smem ----
    {
        const char* gsrc = (const char*)(g_gx + (size_t)idx * 32 + half * 16);
        uint32_t gdst = smem_u32(&s_gf[wid][j][half * 16]);
        cp16(gdst, gsrc); cp16(gdst + 16, gsrc + 16);
        cp16(gdst + 32, gsrc + 32); cp16(gdst + 48, gsrc + 48);
        const char* fsrc = (const char*)(g_fx + (size_t)idx * 32 + half * 16);
        uint32_t fdst = smem_u32(&s_nf[wid][j][half * 16]);
        cp16(fdst, fsrc); cp16(fdst + 16, fsrc + 16);
        cp16(fdst + 32, fsrc + 32); cp16(fdst + 48, fsrc + 48);
        CP_COMMIT();
    }
    // part init: half==0 lane has precomputed gathered-guidance @ W1lo
    float part[8];
    if (half == 0) {
        float4 a0 = __ldg((const float4*)(g_gw1 + (size_t)idx * 8));
        float4 a1 = __ldg((const float4*)(g_gw1 + (size_t)idx * 8 + 4));
        part[0] = a0.x; part[1] = a0.y; part[2] = a0.z; part[3] = a0.w;
        part[4] = a1.x; part[5] = a1.y; part[6] = a1.z; part[7] = a1.w;
    } else {
#pragma unroll
        for (int h = 0; h < 8; h++) part[h] = 0.f;
    }
    float vi[12];
    {
        const float4* vp = (const float4*)(vi_f + ((size_t)m * 16 + j) * 12);
        float4 a = vp[0], b = vp[1], c = vp[2];
        vi[0] = a.x; vi[1] = a.y; vi[2] = a.z; vi[3] = a.w;
        vi[4] = b.x; vi[5] = b.y; vi[6] = b.z; vi[7] = b.w;
        vi[8] = c.x; vi[9] = c.y; vi[10] = c.z; vi[11] = c.w;
    }

    // ---- compute while gathers fly ----
    // PE (fused with its W1hi partial)
#pragma unroll
    for (int c16 = 0; c16 < 16; c16++) {
        int c = half * 16 + c16;
        float a = s_bpe[c];
        const float4* wr = (const float4*)&s_wpet[c * 12];
        float4 w0 = wr[0], w1v = wr[1], w2 = wr[2];
        a = fmaf(vi[0], w0.x, a); a = fmaf(vi[1], w0.y, a);
        a = fmaf(vi[2], w0.z, a); a = fmaf(vi[3], w0.w, a);
        a = fmaf(vi[4], w1v.x, a); a = fmaf(vi[5], w1v.y, a);
        a = fmaf(vi[6], w1v.z, a); a = fmaf(vi[7], w1v.w, a);
        a = fmaf(vi[8], w2.x, a); a = fmaf(vi[9], w2.y, a);
        a = fmaf(vi[10], w2.z, a); a = fmaf(vi[11], w2.w, a);
        float r = relu_f(a);
        s_gf[wid][j][32 + c] = r;
        const float4* pr = (const float4*)&s_wg1[(32 + c) * 8];
        float4 wa = pr[0], wb = pr[1];
        part[0] = fmaf(r, wa.x, part[0]); part[1] = fmaf(r, wa.y, part[1]);
        part[2] = fmaf(r, wa.z, part[2]); part[3] = fmaf(r, wa.w, part[3]);
        part[4] = fmaf(r, wb.x, part[4]); part[5] = fmaf(r, wb.y, part[5]);
        part[6] = fmaf(r, wb.z, part[6]); part[7] = fmaf(r, wb.w, part[7]);
    }

    // WeightNet 12->8->8->16 (independent of gathers)
    float h1[8];
#pragma unroll
    for (int o = 0; o < 8; o++) {
        float a = s_bn1[o];
        const float4* wr = (const float4*)&s_wn1t[o * 12];
        float4 w0 = wr[0], w1v = wr[1], w2 = wr[2];
        a = fmaf(vi[0], w0.x, a); a = fmaf(vi[1], w0.y, a);
        a = fmaf(vi[2], w0.z, a); a = fmaf(vi[3], w0.w, a);
        a = fmaf(vi[4], w1v.x, a); a = fmaf(vi[5], w1v.y, a);
        a = fmaf(vi[6], w1v.z, a); a = fmaf(vi[7], w1v.w, a);
        a = fmaf(vi[8], w2.x, a); a = fmaf(vi[9], w2.y, a);
        a = fmaf(vi[10], w2.z, a); a = fmaf(vi[11], w2.w, a);
        h1[o] = relu_f(a);
    }
    float h2v[8];
#pragma unroll
    for (int o = 0; o < 8; o++) {
        float a = s_bn2[o];
        const float4* wr = (const float4*)&s_wn2t[o * 8];
        float4 wa = wr[0], wb = wr[1];
        a = fmaf(h1[0], wa.x, a); a = fmaf(h1[1], wa.y, a);
        a = fmaf(h1[2], wa.z, a); a = fmaf(h1[3], wa.w, a);
        a = fmaf(h1[4], wb.x, a); a = fmaf(h1[5], wb.y, a);
        a = fmaf(h1[6], wb.z, a); a = fmaf(h1[7], wb.w, a);
        h2v[o] = relu_f(a);
    }
#pragma unroll
    for (int oo = 0; oo < 8; oo++) {
        int o = half * 8 + oo;
        float a = s_bn3[o];
        const float4* wr = (const float4*)&s_wn3t[o * 8];
        float4 wa = wr[0], wb = wr[1];
        a = fmaf(h2v[0], wa.x, a); a = fmaf(h2v[1], wa.y, a);
        a = fmaf(h2v[2], wa.z, a); a = fmaf(h2v[3], wa.w, a);
        a = fmaf(h2v[4], wb.x, a); a = fmaf(h2v[5], wb.y, a);
        a = fmaf(h2v[6], wb.z, a); a = fmaf(h2v[7], wb.w, a);
        s_w[wid][j][o] = relu_f(a);
    }

    // ---- gathers done: channel max + guidance tail ----
    CP_WAIT0();
    __syncwarp();

    float mx0 = -3.0e38f, mx1 = -3.0e38f;
    int cl = lane;
#pragma unroll
    for (int jj = 0; jj < 16; jj++) {
        mx0 = fmaxf(mx0, s_gf[wid][jj][cl]);
        mx1 = fmaxf(mx1, s_gf[wid][jj][cl + 32]);
    }
    float mw[8];
    {
        const float4* wr0 = (const float4*)&s_wg1[cl * 8];
        const float4* wr1 = (const float4*)&s_wg1[(cl + 32) * 8];
        float4 a0 = wr0[0], a1 = wr0[1], b0 = wr1[0], b1v = wr1[1];
        mw[0] = fmaf(mx0, a0.x, mx1 * b0.x); mw[1] = fmaf(mx0, a0.y, mx1 * b0.y);
        mw[2] = fmaf(mx0, a0.z, mx1 * b0.z); mw[3] = fmaf(mx0, a0.w, mx1 * b0.w);
        mw[4] = fmaf(mx0, a1.x, mx1 * b1v.x); mw[5] = fmaf(mx0, a1.y, mx1 * b1v.y);
        mw[6] = fmaf(mx0, a1.z, mx1 * b1v.z); mw[7] = fmaf(mx0, a1.w, mx1 * b1v.w);
    }
#pragma unroll
    for (int s = 16; s >= 1; s >>= 1) {
#pragma unroll
        for (int h = 0; h < 8; h++) mw[h] += __shfl_xor_sync(FULL, mw[h], s);
    }
#pragma unroll
    for (int h = 0; h < 8; h++) part[h] += __shfl_xor_sync(FULL, part[h], 1);

    float s1v[8];
#pragma unroll
    for (int h = 0; h < 8; h++) s1v[h] = relu_f(part[h] - mw[h] + s_bg1[h]);
    float sc4[4];
#pragma unroll
    for (int hq = 0; hq < 4; hq++) {
        int h2 = half * 4 + hq;
        float a = s_bg2[h2];
        const float4* wr = (const float4*)&s_wg2t[h2 * 8];
        float4 wa = wr[0], wb = wr[1];
        a = fmaf(s1v[0], wa.x, a); a = fmaf(s1v[1], wa.y, a);
        a = fmaf(s1v[2], wa.z, a); a = fmaf(s1v[3], wa.w, a);
        a = fmaf(s1v[4], wb.x, a); a = fmaf(s1v[5], wb.y, a);
        a = fmaf(s1v[6], wb.z, a); a = fmaf(s1v[7], wb.w, a);
        sc4[hq] = 1.f / (1.f + __expf(-a));
    }

    // nf = fx * score, in place in s_nf
#pragma unroll
    for (int q = 0; q < 4; q++) {
        int c0 = half * 16 + 4 * q;
        float4 v = *(const float4*)&s_nf[wid][j][c0];
        float s = sc4[q];
        *(float4*)&s_nf[wid][j][c0] = make_float4(v.x * s, v.y * s, v.z * s, v.w * s);
    }
    __syncwarp();

    float acc[16];
#pragma unroll
    for (int w = 0; w < 16; w++) acc[w] = 0.f;
    int c = lane;
#pragma unroll
    for (int jj = 0; jj < 16; jj++) {
        float a = s_nf[wid][jj][c];
        const float4* wp = (const float4*)&s_w[wid][jj][0];
        float4 w0 = wp[0], w1v = wp[1], w2 = wp[2], w3 = wp[3];
        acc[0] = fmaf(a, w0.x, acc[0]);  acc[1] = fmaf(a, w0.y, acc[1]);
        acc[2] = fmaf(a, w0.z, acc[2]);  acc[3] = fmaf(a, w0.w, acc[3]);
        acc[4] = fmaf(a, w1v.x, acc[4]); acc[5] = fmaf(a, w1v.y, acc[5]);
        acc[6] = fmaf(a, w1v.z, acc[6]); acc[7] = fmaf(a, w1v.w, acc[7]);
        acc[8] = fmaf(a, w2.x, acc[8]);  acc[9] = fmaf(a, w2.y, acc[9]);
        acc[10] = fmaf(a, w2.z, acc[10]); acc[11] = fmaf(a, w2.w, acc[11]);
        acc[12] = fmaf(a, w3.x, acc[12]); acc[13] = fmaf(a, w3.y, acc[13]);
        acc[14] = fmaf(a, w3.z, acc[14]); acc[15] = fmaf(a, w3.w, acc[15]);
    }
    __align__(16) __nv_bfloat16 hb[16];
    __align__(16) __nv_bfloat16 lb[16];
#pragma unroll
    for (int w = 0; w < 16; w++) {
        float v = acc[w];
        __nv_bfloat16 h = __float2bfloat16(v);
        hb[w] = h;
        lb[w] = __float2bfloat16(v - __bfloat162float(h));
    }
    size_t bo = (size_t)m * 512 + c * 16;
    ((uint4*)(g_aggh + bo))[0] = ((uint4*)hb)[0];
    ((uint4*)(g_aggh + bo))[1] = ((uint4*)hb)[1];
    ((uint4*)(g_aggl + bo))[0] = ((uint4*)lb)[0];
    ((uint4*)(g_aggl + bo))[1] = ((uint4*)lb)[1];
}

// ======================= K3: pipelined MMA GEMM1 -> o bf16 =================
#define K3_A_HI 0u
#define K3_A_LO 36864u
#define K3_B_HI 73728u
#define K3_B_LO 92160u
#define K3_SMEM 110592

__device__ __forceinline__ void k3_load(uint32_t sb, char* dsm, int t, int m0,
                                        int kt, int st) {
    uint32_t aofs = (uint32_t)st * 18432u;
    uint32_t bofs = (uint32_t)st * 9216u;
#pragma unroll
    for (int q = 0; q < 4; q++) {
        int id = t + q * 256;
        int row = id >> 3, seg = id & 7;
        int gm = m0 + row; if (gm >= MPTS) gm = MPTS - 1;
        size_t go = (size_t)gm * 512 + kt * 64 + seg * 8;
        uint32_t so_ = (uint32_t)(row * 144 + seg * 16);
        cp16(sb + K3_A_HI + aofs + so_, g_aggh + go);
        cp16(sb + K3_A_LO + aofs + so_, g_aggl + go);
    }
#pragma unroll
    for (int q = 0; q < 2; q++) {
        int id = t + q * 256;
        int n = id >> 3, seg = id & 7;
        size_t go = (size_t)n * 512 + kt * 64 + seg * 8;
        uint32_t so_ = (uint32_t)(n * 144 + seg * 16);
        cp16(sb + K3_B_HI + bofs + so_, g_bh + go);
        cp16(sb + K3_B_LO + bofs + so_, g_bl + go);
    }
}

__global__ void __launch_bounds__(256, 2) k3_out(const float* __restrict__ blin) {
    extern __shared__ __align__(16) char dsm[];
    uint32_t sb = smem_u32(dsm);
    int t = threadIdx.x;
    int wid = t >> 5, lane = t & 31;
    int m0 = blockIdx.x * 128;
    int wm = wid * 16;

    float acc[8][4];
#pragma unroll
    for (int nt = 0; nt < 8; nt++)
#pragma unroll
        for (int q = 0; q < 4; q++) acc[nt][q] = 0.f;

    int qq = lane >> 3, rr = lane & 7;

    k3_load(sb, dsm, t, m0, 0, 0);
    CP_COMMIT();

#pragma unroll 1
    for (int kt = 0; kt < 8; kt++) {
        int st = kt & 1;
        if (kt < 7) {
            k3_load(sb, dsm, t, m0, kt + 1, st ^ 1);
            CP_COMMIT();
            CP_WAIT1();
        } else {
            CP_WAIT0();
        }
        __syncthreads();

        uint32_t aofs = (uint32_t)st * 18432u;
        uint32_t bofs = (uint32_t)st * 9216u;
#pragma unroll
        for (int ks = 0; ks < 4; ks++) {
            int k0 = ks * 16;
            uint32_t ah[4], al[4];
            {
                int row = wm + rr + (qq & 1) * 8;
                int col = k0 + (qq >> 1) * 8;
                uint32_t ad = sb + K3_A_HI + aofs + (uint32_t)(row * 144 + col * 2);
                ldsm4(ah, ad);
                ldsm4(al, ad + (K3_A_LO - K3_A_HI));
            }
#pragma unroll
            for (int p = 0; p < 4; p++) {
                uint32_t bh4[4], bl4[4];
                int noff = 16 * p + rr + (qq >> 1) * 8;
                int col = k0 + (qq & 1) * 8;
                uint32_t bd = sb + K3_B_HI + bofs + (uint32_t)(noff * 144 + col * 2);
                ldsm4(bh4, bd);
                ldsm4(bl4, bd + (K3_B_LO - K3_B_HI));
                mma16816(acc[2 * p], ah, bh4);
                mma16816(acc[2 * p + 1], ah, bh4 + 2);
                mma16816(acc[2 * p], al, bh4);
                mma16816(acc[2 * p + 1], al, bh4 + 2);
                mma16816(acc[2 * p], ah, bl4);
                mma16816(acc[2 * p + 1], ah, bl4 + 2);
            }
        }
        __syncthreads();
    }

    {
        int rrow = lane >> 2, cp = (lane & 3) * 2;
        float* so = (float*)dsm;
#pragma unroll
        for (int nt = 0; nt < 8; nt++) {
            int c0 = nt * 8 + cp;
            float b0v = __ldg(&blin[c0]), b1v = __ldg(&blin[c0 + 1]);
            so[(wm + rrow) * 65 + c0]         = relu_f(acc[nt][0] + b0v);
            so[(wm + rrow) * 65 + c0 + 1]     = relu_f(acc[nt][1] + b1v);
            so[(wm + rrow + 8) * 65 + c0]     = relu_f(acc[nt][2] + b0v);
            so[(wm + rrow + 8) * 65 + c0 + 1] = relu_f(acc[nt][3] + b1v);
        }
    }
    __syncthreads();

    const float* so = (const float*)dsm;
#pragma unroll
    for (int q = 0; q < 4; q++) {
        int id = t + q * 256;
        int row = id >> 3, c8 = (id & 7) * 8;
        int gm = m0 + row;
        if (gm < MPTS) {
            __align__(16) __nv_bfloat16 hb[8];
            __align__(16) __nv_bfloat16 lb[8];
#pragma unroll
            for (int i = 0; i < 8; i++) {
                float v = so[row * 65 + c8 + i];
                __nv_bfloat16 h = __float2bfloat16(v);
                hb[i] = h;
                lb[i] = __float2bfloat16(v - __bfloat162float(h));
            }
            *(uint4*)(g_oh + (size_t)gm * 64 + c8) = *(uint4*)hb;
            *(uint4*)(g_ol + (size_t)gm * 64 + c8) = *(uint4*)lb;
        }
    }
}

// ======================= K4: MMA GEMM2 + final epilogue ====================
#define K4_A_HI 0u
#define K4_A_LO 18432u
#define K4_B_HI 36864u
#define K4_B_LO 55296u
#define K4_SMEM 73728

__global__ void __launch_bounds__(256, 2) k4_out(
    const float* __restrict__ bu2, const float* __restrict__ bsc,
    float* __restrict__ out) {
    extern __shared__ __align__(16) char dsm[];
    uint32_t sb = smem_u32(dsm);
    int t = threadIdx.x;
    int wid = t >> 5, lane = t & 31;
    int m0 = blockIdx.x * 128;
    int wm = wid * 16;

    float acc[16][4];
#pragma unroll
    for (int nt = 0; nt < 16; nt++)
#pragma unroll
        for (int q = 0; q < 4; q++) acc[nt][q] = 0.f;

    int qq = lane >> 3, rr = lane & 7;

#pragma unroll 1
    for (int kt = 0; kt < 2; kt++) {
        const __nv_bfloat16* ah_src = kt ? g_sfh : g_oh;
        const __nv_bfloat16* al_src = kt ? g_sfl : g_ol;
#pragma unroll
        for (int q = 0; q < 4; q++) {
            int id = t + q * 256;
            int row = id >> 3, seg = id & 7;
            int gm = m0 + row; if (gm >= MPTS) gm = MPTS - 1;
            size_t go = (size_t)gm * 64 + seg * 8;
            uint32_t so_ = (uint32_t)(row * 144 + seg * 16);
            *(uint4*)(dsm + K4_A_HI + so_) = *(const uint4*)(ah_src + go);
            *(uint4*)(dsm + K4_A_LO + so_) = *(const uint4*)(al_src + go);
        }
#pragma unroll
        for (int q = 0; q < 4; q++) {
            int id = t + q * 256;
            int n = id >> 3, seg = id & 7;
            size_t go = (size_t)n * 128 + kt * 64 + seg * 8;
            uint32_t so_ = (uint32_t)(n * 144 + seg * 16);
            *(uint4*)(dsm + K4_B_HI + so_) = *(const uint4*)(g_b2h + go);
            *(uint4*)(dsm + K4_B_LO + so_) = *(const uint4*)(g_b2l + go);
        }
        __syncthreads();

#pragma unroll
        for (int ks = 0; ks < 4; ks++) {
            int k0 = ks * 16;
            uint32_t ah[4], al[4];
            {
                int row = wm + rr + (qq & 1) * 8;
                int col = k0 + (qq >> 1) * 8;
                uint32_t ad = sb + K4_A_HI + (uint32_t)(row * 144 + col * 2);
                ldsm4(ah, ad);
                ldsm4(al, ad + (K4_A_LO - K4_A_HI));
            }
#pragma unroll
            for (int p = 0; p < 8; p++) {
                uint32_t bh4[4], bl4[4];
                int noff = 16 * p + rr + (qq >> 1) * 8;
                int col = k0 + (qq & 1) * 8;
                uint32_t bd = sb + K4_B_HI + (uint32_t)(noff * 144 + col * 2);
                ldsm4(bh4, bd);
                ldsm4(bl4, bd + (K4_B_LO - K4_B_HI));
                mma16816(acc[2 * p], ah, bh4);
                mma16816(acc[2 * p + 1], ah, bh4 + 2);
                mma16816(acc[2 * p], al, bh4);
                mma16816(acc[2 * p + 1], al, bh4 + 2);
                mma16816(acc[2 * p], ah, bl4);
                mma16816(acc[2 * p + 1], ah, bl4 + 2);
            }
        }
        __syncthreads();
    }

    int r0 = lane >> 2, cp = (lane & 3) * 2;
    int mA = m0 + wm + r0, mB = mA + 8;
#pragma unroll
    for (int nt = 0; nt < 16; nt++) {
        int c0 = nt * 8 + cp;
        float b0v = __ldg(&bu2[c0]) + __ldg(&bsc[c0]);
        float b1v = __ldg(&bu2[c0 + 1]) + __ldg(&bsc[c0 + 1]);
        if (mA < MPTS)
            *(float2*)(out + (size_t)mA * 128 + c0) =
                make_float2(lrelu_f(acc[nt][0] + b0v), lrelu_f(acc[nt][1] + b1v));
        if (mB < MPTS)
            *(float2*)(out + (size_t)mB * 128 + c0) =
                make_float2(lrelu_f(acc[nt][2] + b0v), lrelu_f(acc[nt][3] + b1v));
    }
}

// ======================= launch ============================================
extern "C" void kernel_launch(void* const* d_in, const int* in_sizes, int n_in,
                              void* d_out, int out_size) {
    const float* df  = (const float*)d_in[1];
    const float* vi  = (const float*)d_in[5];
    const int*   nei = (const int*)d_in[6];
    const float* w1  = (const float*)d_in[7];
    const float* b1  = (const float*)d_in[8];
    const float* wgu = (const float*)d_in[9];
    const float* bgu = (const float*)d_in[10];
    const float* wpe = (const float*)d_in[11];
    const float* bpe = (const float*)d_in[12];
    const float* wg1 = (const float*)d_in[13];
    const float* bg1 = (const float*)d_in[14];
    const float* wg2 = (const float*)d_in[15];
    const float* bg2 = (const float*)d_in[16];
    const float* wn1 = (const float*)d_in[17];
    const float* bn1 = (const float*)d_in[18];
    const float* wn2 = (const float*)d_in[19];
    const float* bn2 = (const float*)d_in[20];
    const float* wn3 = (const float*)d_in[21];
    const float* bn3 = (const float*)d_in[22];
    const float* wlin = (const float*)d_in[23];
    const float* blin = (const float*)d_in[24];
    const float* wu2 = (const float*)d_in[25];
    const float* bu2 = (const float*)d_in[26];
    const float* wsc = (const float*)d_in[27];
    const float* bsc = (const float*)d_in[28];
    float* out = (float*)d_out;

    cudaFuncSetAttribute(k3_out, cudaFuncAttributeMaxDynamicSharedMemorySize, K3_SMEM);
    cudaFuncSetAttribute(k4_out, cudaFuncAttributeMaxDynamicSharedMemorySize, K4_SMEM);

    // Launch order chosen so k2_point is launch index 3 (the one ncu captures).
    k0_wconv<<<128, 256>>>(wlin, wu2, wsc);
    k1_dense<<<(NPTS + 127) / 128, 256>>>(df, w1, b1, wgu, bgu, wg1);
    k5_maxpool<<<MPTS / 8, 256>>>(df, nei);
    k2_point<<<MPTS / 8, 256>>>(vi, nei,
                                wpe, bpe, wg1, bg1, wg2, bg2,
                                wn1, bn1, wn2, bn2, wn3, bn3);
    k3_out<<<(MPTS + 127) / 128, 256, K3_SMEM>>>(blin);
    k4_out<<<(MPTS + 127) / 128, 256, K4_SMEM>>>(bu2, bsc, out);
}